// round 13
// baseline (speedup 1.0000x reference)
#include <cuda_runtime.h>
#include <cstdint>
#include <cstddef>
#include <math.h>

typedef unsigned short u16;

constexpr int B_ = 2, T_ = 1024, H_ = 2048, NH_ = 8, NKV_ = 2, HD_ = 256;
constexpr int FF_ = 8192, LR_ = 64;
constexpr int BT_ = B_ * T_;
constexpr size_t BTH_ = (size_t)BT_ * H_;
constexpr size_t SCSZ_ = (size_t)B_ * NH_ * T_ * T_;
constexpr float EPS_ = 1e-6f;

struct Scratch {
    float pred[4 * BTH_];
    float xnorm[BTH_];
    float lrpart[8 * BT_ * LR_];
    float lrbuf[BT_ * LR_];
    float laurel[BTH_];
    float qraw[BTH_];
    float kraw[(size_t)BT_ * NKV_ * HD_];
    float vraw[(size_t)BT_ * NKV_ * HD_];
    float q[BTH_];
    float k[(size_t)BT_ * NKV_ * HD_];
    float vT[(size_t)BT_ * NKV_ * HD_];
    float scores[SCSZ_];
    u16 probs[SCSZ_];
    float attnout[BTH_];
    float attnproj[BTH_];
    float attnlaurel[BTH_];
    float hn[BTH_];
    float gate[(size_t)BT_ * FF_];
    float up[(size_t)BT_ * FF_];
    float ffw[BTH_];
};
__device__ Scratch g_scratch;

// ---------- bf16 / fp16 bit helpers ----------
__device__ __forceinline__ uint32_t f2bf(float x) {
    uint32_t u = __float_as_uint(x);
    return (u + 0x7FFFu + ((u >> 16) & 1u)) >> 16;
}
__device__ __forceinline__ float bf2f(uint32_t b) {
    return __uint_as_float(b << 16);
}
__device__ __forceinline__ u16 f2h(float x) {
    u16 h;
    asm("cvt.rn.f16.f32 %0, %1;" : "=h"(h) : "f"(x));
    return h;
}

// ---------- reductions ----------
__device__ __forceinline__ float warpSum(float v) {
#pragma unroll
    for (int o = 16; o > 0; o >>= 1) v += __shfl_xor_sync(0xffffffffu, v, o);
    return v;
}
__device__ __forceinline__ float warpMax(float v) {
#pragma unroll
    for (int o = 16; o > 0; o >>= 1) v = fmaxf(v, __shfl_xor_sync(0xffffffffu, v, o));
    return v;
}
__device__ __forceinline__ float blockSum(float v, float* red) {
    v = warpSum(v);
    int lane = threadIdx.x & 31, w = threadIdx.x >> 5;
    if (lane == 0) red[w] = v;
    __syncthreads();
    int nw = (blockDim.x + 31) >> 5;
    float r = (lane < nw) ? red[lane] : 0.f;
    if (w == 0) {
        r = warpSum(r);
        if (lane == 0) red[0] = r;
    }
    __syncthreads();
    r = red[0];
    __syncthreads();
    return r;
}
__device__ __forceinline__ float blockMax(float v, float* red) {
    v = warpMax(v);
    int lane = threadIdx.x & 31, w = threadIdx.x >> 5;
    if (lane == 0) red[w] = v;
    __syncthreads();
    int nw = (blockDim.x + 31) >> 5;
    float r = (lane < nw) ? red[lane] : -INFINITY;
    if (w == 0) {
        r = warpMax(r);
        if (lane == 0) red[0] = r;
    }
    __syncthreads();
    r = red[0];
    __syncthreads();
    return r;
}

// ===== fused per-token kernels =====
__global__ void fused_pre(const float* __restrict__ hs, const float* __restrict__ rnw,
                          const float* __restrict__ rw, const float* __restrict__ pcw,
                          const float* __restrict__ inw,
                          float* __restrict__ pred, float* __restrict__ xnorm) {
    __shared__ float sx[H_];
    __shared__ float px[H_];
    __shared__ float red[32];
    __shared__ float cf[16];
    size_t off = (size_t)blockIdx.x * H_;
    int tid = threadIdx.x;

    float ls = 0.f;
    for (int i = tid; i < H_; i += blockDim.x) {
        float v = hs[off + i];
        sx[i] = v;
        ls += v;
    }
    float mean = blockSum(ls, red) * (1.f / H_);
    float lv = 0.f;
    for (int i = tid; i < H_; i += blockDim.x) {
        float d = sx[i] - mean;
        lv += d * d;
    }
    float rs = rsqrtf(blockSum(lv, red) * (1.f / H_) + EPS_);

    float a0 = 0.f, a1 = 0.f, a2 = 0.f, a3 = 0.f;
    for (int i = tid; i < H_; i += blockDim.x) {
        float r = (sx[i] - mean) * rs * rnw[i] * (1.f / H_);
        a0 += r * rw[i];
        a1 += r * rw[H_ + i];
        a2 += r * rw[2 * H_ + i];
        a3 += r * rw[3 * H_ + i];
    }
    float t0 = blockSum(a0, red);
    float t1 = blockSum(a1, red);
    float t2 = blockSum(a2, red);
    float t3 = blockSum(a3, red);
    if (tid < 16) {
        float m0 = tanhf(t0), m1 = tanhf(t1), m2 = tanhf(t2), m3 = tanhf(t3);
        cf[tid] = m0 * pcw[tid * 4] + m1 * pcw[tid * 4 + 1]
                + m2 * pcw[tid * 4 + 2] + m3 * pcw[tid * 4 + 3];
    }
    __syncthreads();

    float ps = 0.f;
    for (int i = tid; i < H_; i += blockDim.x) {
        float h0 = sx[i];
        float h1 = hs[BTH_ + off + i];
        float h2 = hs[2 * BTH_ + off + i];
        float h3 = hs[3 * BTH_ + off + i];
        float p0 = h0 + h0 * cf[0] + h1 * cf[1] + h2 * cf[2] + h3 * cf[3];
        pred[off + i] = p0;
        px[i] = p0;
        ps += p0;
        pred[BTH_ + off + i]     = h1 + h0 * cf[4]  + h1 * cf[5]  + h2 * cf[6]  + h3 * cf[7];
        pred[2 * BTH_ + off + i] = h2 + h0 * cf[8]  + h1 * cf[9]  + h2 * cf[10] + h3 * cf[11];
        pred[3 * BTH_ + off + i] = h3 + h0 * cf[12] + h1 * cf[13] + h2 * cf[14] + h3 * cf[15];
    }
    float mean2 = blockSum(ps, red) * (1.f / H_);
    float lv2 = 0.f;
    for (int i = tid; i < H_; i += blockDim.x) {
        float d = px[i] - mean2;
        lv2 += d * d;
    }
    float rs2 = rsqrtf(blockSum(lv2, red) * (1.f / H_) + EPS_);
    for (int i = tid; i < H_; i += blockDim.x) {
        xnorm[off + i] = (px[i] - mean2) * rs2 * inw[i];
    }
}

__global__ void fused_mid(const float* __restrict__ ap, const float* __restrict__ paw,
                          const float* __restrict__ pred, const float* __restrict__ laurel,
                          const float* __restrict__ pfw,
                          float* __restrict__ attnlaurel, float* __restrict__ hn) {
    __shared__ float sx[H_];
    __shared__ float ax[H_];
    __shared__ float red[32];
    size_t off = (size_t)blockIdx.x * H_;
    int tid = threadIdx.x;

    float ls = 0.f;
    for (int i = tid; i < H_; i += blockDim.x) {
        float v = ap[off + i];
        sx[i] = v;
        ls += v;
    }
    float mean = blockSum(ls, red) * (1.f / H_);
    float lv = 0.f;
    for (int i = tid; i < H_; i += blockDim.x) {
        float d = sx[i] - mean;
        lv += d * d;
    }
    float rs = rsqrtf(blockSum(lv, red) * (1.f / H_) + EPS_);

    float ls2 = 0.f;
    for (int i = tid; i < H_; i += blockDim.x) {
        float v = (sx[i] - mean) * rs * paw[i] + pred[off + i] + laurel[off + i];
        v *= 0.7071067811865476f;
        ax[i] = v;
        attnlaurel[off + i] = v;
        ls2 += v;
    }
    float mean2 = blockSum(ls2, red) * (1.f / H_);
    float lv2 = 0.f;
    for (int i = tid; i < H_; i += blockDim.x) {
        float d = ax[i] - mean2;
        lv2 += d * d;
    }
    float rs2 = rsqrtf(blockSum(lv2, red) * (1.f / H_) + EPS_);
    for (int i = tid; i < H_; i += blockDim.x) {
        hn[off + i] = (ax[i] - mean2) * rs2 * pfw[i];
    }
}

__global__ void fused_post(const float* __restrict__ ffw, const float* __restrict__ pww,
                           const float* __restrict__ attnlaurel,
                           const float* __restrict__ rnw, const float* __restrict__ rw,
                           const float* __restrict__ ccw, const float* __restrict__ cscale,
                           const float* __restrict__ pred, float* __restrict__ out) {
    __shared__ float sx[H_];
    __shared__ float ax[H_];
    __shared__ float red[32];
    size_t off = (size_t)blockIdx.x * H_;
    int tid = threadIdx.x;

    float ls = 0.f;
    for (int i = tid; i < H_; i += blockDim.x) {
        float v = ffw[off + i];
        sx[i] = v;
        ls += v;
    }
    float mean = blockSum(ls, red) * (1.f / H_);
    float lv = 0.f;
    for (int i = tid; i < H_; i += blockDim.x) {
        float d = sx[i] - mean;
        lv += d * d;
    }
    float rs = rsqrtf(blockSum(lv, red) * (1.f / H_) + EPS_);

    float as = 0.f;
    for (int i = tid; i < H_; i += blockDim.x) {
        float v = (sx[i] - mean) * rs * pww[i] + attnlaurel[off + i];
        ax[i] = v;
        as += v;
    }
    float mean2 = blockSum(as, red) * (1.f / H_);
    float lv2 = 0.f;
    for (int i = tid; i < H_; i += blockDim.x) {
        float d = ax[i] - mean2;
        lv2 += d * d;
    }
    float rs2 = rsqrtf(blockSum(lv2, red) * (1.f / H_) + EPS_);
    float a0 = 0.f, a1 = 0.f, a2 = 0.f, a3 = 0.f;
    for (int i = tid; i < H_; i += blockDim.x) {
        float r = (ax[i] - mean2) * rs2 * rnw[i] * (1.f / H_);
        a0 += r * rw[i];
        a1 += r * rw[H_ + i];
        a2 += r * rw[2 * H_ + i];
        a3 += r * rw[3 * H_ + i];
    }
    float m0 = tanhf(blockSum(a0, red));
    float m1 = tanhf(blockSum(a1, red));
    float m2 = tanhf(blockSum(a2, red));
    float m3 = tanhf(blockSum(a3, red));
    float cc0 = 1.f + m0 * ccw[0]  + m1 * ccw[1]  + m2 * ccw[2]  + m3 * ccw[3];
    float cc1 = 1.f + m0 * ccw[4]  + m1 * ccw[5]  + m2 * ccw[6]  + m3 * ccw[7];
    float cc2 = 1.f + m0 * ccw[8]  + m1 * ccw[9]  + m2 * ccw[10] + m3 * ccw[11];
    float cc3 = 1.f + m0 * ccw[12] + m1 * ccw[13] + m2 * ccw[14] + m3 * ccw[15];

    for (int f = tid; f < H_; f += blockDim.x) {
        float p0 = pred[off + f];
        float inno = ax[f] - p0;
        out[off + f]            = (inno * cc0 + p0) * cscale[f];
        out[BTH_ + off + f]     = inno * cc1 + pred[BTH_ + off + f];
        out[2 * BTH_ + off + f] = inno * cc2 + pred[2 * BTH_ + off + f];
        out[3 * BTH_ + off + f] = inno * cc3 + pred[3 * BTH_ + off + f];
    }
}

// ---------- remaining elementwise ----------
__global__ void ln_kernel(const float* __restrict__ a, const float* __restrict__ w,
                          const float* __restrict__ add1, const float* __restrict__ add2,
                          float scale, float* __restrict__ dst) {
    __shared__ float sx[H_];
    __shared__ float red[32];
    size_t off = (size_t)blockIdx.x * H_;
    int tid = threadIdx.x;
    float ls = 0.f;
    for (int i = tid; i < H_; i += blockDim.x) {
        float v = a[off + i];
        sx[i] = v;
        ls += v;
    }
    float mean = blockSum(ls, red) * (1.f / H_);
    float lv = 0.f;
    for (int i = tid; i < H_; i += blockDim.x) {
        float d = sx[i] - mean;
        lv += d * d;
    }
    float var = blockSum(lv, red) * (1.f / H_);
    float rs = rsqrtf(var + EPS_);
    for (int i = tid; i < H_; i += blockDim.x) {
        float v = (sx[i] - mean) * rs * w[i];
        if (add1) v += add1[off + i];
        if (add2) v += add2[off + i];
        dst[off + i] = v * scale;
    }
}

__device__ __forceinline__ void qkvpost_body(
    const float* __restrict__ raw, const float* __restrict__ nw,
    const float* __restrict__ cosb, const float* __restrict__ sinb,
    float* __restrict__ out, int nheads, int do_rope, int trans, int idx) {
    __shared__ float sx[HD_];
    __shared__ float red[32];
    int h = idx % nheads;
    int bt = idx / nheads;
    int t = bt % T_, b = bt / T_;
    int d = threadIdx.x;
    float v = raw[(size_t)bt * nheads * HD_ + h * HD_ + d];
    float mean = blockSum(v, red) * (1.f / HD_);
    float c = v - mean;
    float var = blockSum(c * c, red) * (1.f / HD_);
    float ln = c * rsqrtf(var + EPS_) * (nw ? nw[d] : 1.f);
    sx[d] = ln;
    __syncthreads();
    float o = ln;
    if (do_rope) {
        float cs = cosb[(size_t)bt * HD_ + d];
        float sn = sinb[(size_t)bt * HD_ + d];
        float rot = (d < 128) ? -sx[d + 128] : sx[d - 128];
        o = ln * cs + rot * sn;
    }
    if (trans) {
        out[((size_t)(b * nheads + h) * HD_ + d) * T_ + t] = o;
    } else {
        out[((size_t)(b * nheads + h) * T_ + t) * HD_ + d] = o;
    }
}

__global__ void qkvpost_kernel(const float* __restrict__ raw, const float* __restrict__ nw,
                               const float* __restrict__ cosb, const float* __restrict__ sinb,
                               float* __restrict__ out, int nheads, int do_rope, int trans) {
    qkvpost_body(raw, nw, cosb, sinb, out, nheads, do_rope, trans, blockIdx.x);
}

__global__ void qkvpost_qk(const float* __restrict__ qraw, const float* __restrict__ kraw,
                           const float* __restrict__ qnw, const float* __restrict__ knw,
                           const float* __restrict__ cosb, const float* __restrict__ sinb,
                           float* __restrict__ q, float* __restrict__ k) {
    int idx = blockIdx.x;
    if (idx < BT_ * NH_) {
        qkvpost_body(qraw, qnw, cosb, sinb, q, NH_, 1, 0, idx);
    } else {
        qkvpost_body(kraw, knw, cosb, sinb, k, NKV_, 1, 0, idx - BT_ * NH_);
    }
}

// causal softmax; emits fp16 probs (same bits attnv previously produced via f2h)
__global__ void softmax_kernel(const float* __restrict__ scores, u16* __restrict__ probs) {
    __shared__ float sx[T_];
    __shared__ float red[32];
    int q = blockIdx.x % T_;
    size_t off = (size_t)blockIdx.x * T_;
    int tid = threadIdx.x;
    int n = q + 1;
    float lm = -INFINITY;
    for (int i = tid; i < n; i += blockDim.x) {
        float v = scores[off + i];
        sx[i] = v;
        lm = fmaxf(lm, v);
    }
    float gm = blockMax(lm, red);
    float lsum = 0.f;
    for (int i = tid; i < n; i += blockDim.x) {
        float e = __expf(sx[i] - gm);
        sx[i] = e;
        lsum += e;
    }
    float inv = 1.f / blockSum(lsum, red);
    for (int i = tid; i < T_; i += blockDim.x) {
        probs[off + i] = (i < n) ? f2h(sx[i] * inv) : (u16)0;
    }
}

__device__ __forceinline__ float gelu_tanh(float x) {
    return 0.5f * x * (1.f + tanhf(0.7978845608028654f * (x + 0.044715f * x * x * x)));
}

// ===== shared MMA plumbing =====
__device__ __forceinline__ void ldsm4(uint32_t* r, uint32_t addr) {
    asm volatile("ldmatrix.sync.aligned.m8n8.x4.shared.b16 {%0,%1,%2,%3}, [%4];"
                 : "=r"(r[0]), "=r"(r[1]), "=r"(r[2]), "=r"(r[3]) : "r"(addr));
}
__device__ __forceinline__ void mma_bf(float* d, const uint32_t* a, uint32_t b0, uint32_t b1) {
    asm volatile("mma.sync.aligned.m16n8k16.row.col.f32.bf16.bf16.f32 "
                 "{%0,%1,%2,%3}, {%4,%5,%6,%7}, {%8,%9}, {%0,%1,%2,%3};"
                 : "+f"(d[0]), "+f"(d[1]), "+f"(d[2]), "+f"(d[3])
                 : "r"(a[0]), "r"(a[1]), "r"(a[2]), "r"(a[3]), "r"(b0), "r"(b1));
}
__device__ __forceinline__ void mma_fp(float* d, const uint32_t* a, uint32_t b0, uint32_t b1) {
    asm volatile("mma.sync.aligned.m16n8k16.row.col.f32.f16.f16.f32 "
                 "{%0,%1,%2,%3}, {%4,%5,%6,%7}, {%8,%9}, {%0,%1,%2,%3};"
                 : "+f"(d[0]), "+f"(d[1]), "+f"(d[2]), "+f"(d[3])
                 : "r"(a[0]), "r"(a[1]), "r"(a[2]), "r"(a[3]), "r"(b0), "r"(b1));
}
__device__ __forceinline__ void splitStoreBF(float4 v, uint32_t* hi, uint32_t* lo) {
    uint32_t hx = f2bf(v.x), hy = f2bf(v.y), hz = f2bf(v.z), hw = f2bf(v.w);
    uint32_t lx = f2bf(v.x - bf2f(hx));
    uint32_t ly = f2bf(v.y - bf2f(hy));
    uint32_t lz = f2bf(v.z - bf2f(hz));
    uint32_t lw = f2bf(v.w - bf2f(hw));
    hi[0] = hx | (hy << 16);
    hi[1] = hz | (hw << 16);
    lo[0] = lx | (ly << 16);
    lo[1] = lz | (lw << 16);
}
__device__ __forceinline__ void convStoreH(float4 v, uint32_t* hi) {
    u16 hx = f2h(v.x), hy = f2h(v.y), hz = f2h(v.z), hw = f2h(v.w);
    hi[0] = (uint32_t)hx | ((uint32_t)hy << 16);
    hi[1] = (uint32_t)hz | ((uint32_t)hw << 16);
}

constexpr int MBM = 128, MBN = 128, MBK = 32;
constexpr int MLDW = 20;

// ===== 3-pass bf16 core — q/k projections + scores =====
struct MSmem3 {
    uint32_t Ah[MBM][MLDW];
    uint32_t Al[MBM][MLDW];
    uint32_t Bh[MBN][MLDW];
    uint32_t Bl[MBN][MLDW];
};

__device__ __forceinline__ void mma_core3(
    const float* __restrict__ A, const float* __restrict__ B, float* __restrict__ C,
    int K, int lda, int ldb, int ldc, int bm, int bn, MSmem3& s)
{
    const int tid = threadIdx.x;
    const int lane = tid & 31, wid = tid >> 5;
    const int wm = wid & 3, wn = wid >> 2;

    float acc[2][8][4];
#pragma unroll
    for (int i = 0; i < 2; i++)
#pragma unroll
        for (int j = 0; j < 8; j++)
#pragma unroll
            for (int e = 0; e < 4; e++) acc[i][j][e] = 0.f;

    const int lr = tid >> 3;
    const int lc = (tid & 7) * 4;
    const int wc = (tid & 7) * 2;

    const uint32_t sb = (uint32_t)__cvta_generic_to_shared(&s);
    const uint32_t offAl = MBM * MLDW * 4;
    const uint32_t offBh = 2 * MBM * MLDW * 4;
    const uint32_t offBl = 3 * MBM * MLDW * 4;
    const int arow = wm * 32 + (lane & 15);
    const int acol = (lane >> 4) * 8;
    const int brow = wn * 64 + (lane & 7) + ((lane >> 4) << 3);
    const int bcol = ((lane >> 3) & 1) << 3;

    for (int k0 = 0; k0 < K; k0 += MBK) {
#pragma unroll
        for (int p = 0; p < 4; p++) {
            int r = lr + p * 32;
            float4 av = *reinterpret_cast<const float4*>(&A[(size_t)(bm + r) * lda + k0 + lc]);
            splitStoreBF(av, &s.Ah[r][wc], &s.Al[r][wc]);
            float4 bv = *reinterpret_cast<const float4*>(&B[(size_t)(bn + r) * ldb + k0 + lc]);
            splitStoreBF(bv, &s.Bh[r][wc], &s.Bl[r][wc]);
        }
        __syncthreads();

#pragma unroll
        for (int kk = 0; kk < 2; kk++) {
            uint32_t ah[2][4], al[2][4], bh[4][4], bl[4][4];
#pragma unroll
            for (int mf = 0; mf < 2; mf++) {
                uint32_t ao = (uint32_t)(((arow + mf * 16) * MLDW * 4) + (kk * 16 + acol) * 2);
                ldsm4(ah[mf], sb + ao);
                ldsm4(al[mf], sb + offAl + ao);
            }
#pragma unroll
            for (int np = 0; np < 4; np++) {
                uint32_t bo = (uint32_t)(((brow + np * 16) * MLDW * 4) + (kk * 16 + bcol) * 2);
                ldsm4(bh[np], sb + offBh + bo);
                ldsm4(bl[np], sb + offBl + bo);
            }
#pragma unroll
            for (int mf = 0; mf < 2; mf++) {
#pragma unroll
                for (int nf = 0; nf < 8; nf++) {
                    int np = nf >> 1;
                    int hf = (nf & 1) * 2;
                    mma_bf(acc[mf][nf], ah[mf], bh[np][hf], bh[np][hf + 1]);
                    mma_bf(acc[mf][nf], al[mf], bh[np][hf], bh[np][hf + 1]);
                    mma_bf(acc[mf][nf], ah[mf], bl[np][hf], bl[np][hf + 1]);
                }
            }
        }
        __syncthreads();
    }

#pragma unroll
    for (int mf = 0; mf < 2; mf++) {
        int row = bm + wm * 32 + mf * 16 + (lane >> 2);
#pragma unroll
        for (int nf = 0; nf < 8; nf++) {
            int col = bn + wn * 64 + nf * 8 + (lane & 3) * 2;
            *reinterpret_cast<float2*>(&C[(size_t)row * ldc + col]) =
                make_float2(acc[mf][nf][0], acc[mf][nf][1]);
            *reinterpret_cast<float2*>(&C[(size_t)(row + 8) * ldc + col]) =
                make_float2(acc[mf][nf][2], acc[mf][nf][3]);
        }
    }
}

__global__ void __launch_bounds__(256, 2)
mma_qk(const float* __restrict__ A, const float* __restrict__ wq, const float* __restrict__ wk,
       float* __restrict__ qraw, float* __restrict__ kraw) {
    __shared__ MSmem3 s;
    if (blockIdx.y < 16) {
        mma_core3(A, wq, qraw, H_, H_, H_, NH_ * HD_, blockIdx.x * MBM, blockIdx.y * MBN, s);
    } else {
        mma_core3(A, wk, kraw, H_, H_, H_, NKV_ * HD_, blockIdx.x * MBM,
                  (blockIdx.y - 16) * MBN, s);
    }
}

__global__ void __launch_bounds__(256, 2)
mma_scores(const float* __restrict__ q, const float* __restrict__ k, float* __restrict__ sc) {
    if (blockIdx.y > blockIdx.x) return;
    int z = blockIdx.z;
    int b = z >> 3, h = z & 7;
    const float* A = q + (size_t)z * T_ * HD_;
    const float* B = k + (size_t)(b * NKV_ + (h >> 2)) * T_ * HD_;
    float* C = sc + (size_t)z * T_ * T_;
    __shared__ MSmem3 s;
    mma_core3(A, B, C, HD_, HD_, HD_, T_, blockIdx.x * MBM, blockIdx.y * MBN, s);
}

// ===== 1-pass fp16 cores =====
struct MSmem1 {
    uint32_t Ah[MBM][MLDW];
    uint32_t Bh[MBN][MLDW];
};

// pipelined fp32-operand core (gate/up/wo/v/laurel2)
__device__ __forceinline__ void mma_core1(
    const float* __restrict__ A, const float* __restrict__ B, float* __restrict__ C,
    int K, int lda, int ldb, int ldc, int bm, int bn, MSmem1 (&s)[2])
{
    const int tid = threadIdx.x;
    const int lane = tid & 31, wid = tid >> 5;
    const int wm = wid & 3, wn = wid >> 2;

    float acc[2][8][4];
#pragma unroll
    for (int i = 0; i < 2; i++)
#pragma unroll
        for (int j = 0; j < 8; j++)
#pragma unroll
            for (int e = 0; e < 4; e++) acc[i][j][e] = 0.f;

    const int lr = tid >> 3;
    const int lc = (tid & 7) * 4;
    const int wc = (tid & 7) * 2;

    const uint32_t sb0 = (uint32_t)__cvta_generic_to_shared(&s[0]);
    const uint32_t stageBytes = (uint32_t)sizeof(MSmem1);
    const uint32_t offBh = MBM * MLDW * 4;
    const int arow = wm * 32 + (lane & 15);
    const int acol = (lane >> 4) * 8;
    const int brow = wn * 64 + (lane & 7) + ((lane >> 4) << 3);
    const int bcol = ((lane >> 3) & 1) << 3;

    float4 av[4], bv[4];
#pragma unroll
    for (int p = 0; p < 4; p++) {
        int r = lr + p * 32;
        av[p] = *reinterpret_cast<const float4*>(&A[(size_t)(bm + r) * lda + lc]);
        bv[p] = *reinterpret_cast<const float4*>(&B[(size_t)(bn + r) * ldb + lc]);
    }
#pragma unroll
    for (int p = 0; p < 4; p++) {
        int r = lr + p * 32;
        convStoreH(av[p], &s[0].Ah[r][wc]);
        convStoreH(bv[p], &s[0].Bh[r][wc]);
    }
    __syncthreads();

    const int KT = K / MBK;
    for (int kt = 0; kt < KT; kt++) {
        const int cur = kt & 1;
        const uint32_t sb = sb0 + (uint32_t)cur * stageBytes;
        if (kt + 1 < KT) {
            int k0 = (kt + 1) * MBK;
#pragma unroll
            for (int p = 0; p < 4; p++) {
                int r = lr + p * 32;
                av[p] = *reinterpret_cast<const float4*>(&A[(size_t)(bm + r) * lda + k0 + lc]);
                bv[p] = *reinterpret_cast<const float4*>(&B[(size_t)(bn + r) * ldb + k0 + lc]);
            }
        }
#pragma unroll
        for (int kk = 0; kk < 2; kk++) {
            uint32_t ah[2][4], bh[4][4];
#pragma unroll
            for (int mf = 0; mf < 2; mf++) {
                uint32_t ao = (uint32_t)(((arow + mf * 16) * MLDW * 4) + (kk * 16 + acol) * 2);
                ldsm4(ah[mf], sb + ao);
            }
#pragma unroll
            for (int np = 0; np < 4; np++) {
                uint32_t bo = (uint32_t)(((brow + np * 16) * MLDW * 4) + (kk * 16 + bcol) * 2);
                ldsm4(bh[np], sb + offBh + bo);
            }
#pragma unroll
            for (int mf = 0; mf < 2; mf++) {
#pragma unroll
                for (int nf = 0; nf < 8; nf++) {
                    int np = nf >> 1;
                    int hf = (nf & 1) * 2;
                    mma_fp(acc[mf][nf], ah[mf], bh[np][hf], bh[np][hf + 1]);
                }
            }
        }
        if (kt + 1 < KT) {
            MSmem1& sn = s[cur ^ 1];
#pragma unroll
            for (int p = 0; p < 4; p++) {
                int r = lr + p * 32;
                convStoreH(av[p], &sn.Ah[r][wc]);
                convStoreH(bv[p], &sn.Bh[r][wc]);
            }
        }
        __syncthreads();
    }

#pragma unroll
    for (int mf = 0; mf < 2; mf++) {
        int row = bm + wm * 32 + mf * 16 + (lane >> 2);
#pragma unroll
        for (int nf = 0; nf < 8; nf++) {
            int col = bn + wn * 64 + nf * 8 + (lane & 3) * 2;
            *reinterpret_cast<float2*>(&C[(size_t)row * ldc + col]) =
                make_float2(acc[mf][nf][0], acc[mf][nf][1]);
            *reinterpret_cast<float2*>(&C[(size_t)(row + 8) * ldc + col]) =
                make_float2(acc[mf][nf][2], acc[mf][nf][3]);
        }
    }
}

// pipelined core with u16 A operand (attnv: probs already fp16)
__device__ __forceinline__ void mma_core1h(
    const u16* __restrict__ A, const float* __restrict__ B, float* __restrict__ C,
    int K, int lda, int ldb, int ldc, int bm, int bn, MSmem1 (&s)[2])
{
    const int tid = threadIdx.x;
    const int lane = tid & 31, wid = tid >> 5;
    const int wm = wid & 3, wn = wid >> 2;

    float acc[2][8][4];
#pragma unroll
    for (int i = 0; i < 2; i++)
#pragma unroll
        for (int j = 0; j < 8; j++)
#pragma unroll
            for (int e = 0; e < 4; e++) acc[i][j][e] = 0.f;

    const int lr = tid >> 3;
    const int lc = (tid & 7) * 4;
    const int wc = (tid & 7) * 2;

    const uint32_t sb0 = (uint32_t)__cvta_generic_to_shared(&s[0]);
    const uint32_t stageBytes = (uint32_t)sizeof(MSmem1);
    const uint32_t offBh = MBM * MLDW * 4;
    const int arow = wm * 32 + (lane & 15);
    const int acol = (lane >> 4) * 8;
    const int brow = wn * 64 + (lane & 7) + ((lane >> 4) << 3);
    const int bcol = ((lane >> 3) & 1) << 3;

    uint2 av[4];
    float4 bv[4];
#pragma unroll
    for (int p = 0; p < 4; p++) {
        int r = lr + p * 32;
        av[p] = *reinterpret_cast<const uint2*>(&A[(size_t)(bm + r) * lda + lc]);
        bv[p] = *reinterpret_cast<const float4*>(&B[(size_t)(bn + r) * ldb + lc]);
    }
#pragma unroll
    for (int p = 0; p < 4; p++) {
        int r = lr + p * 32;
        s[0].Ah[r][wc] = av[p].x;
        s[0].Ah[r][wc + 1] = av[p].y;
        convStoreH(bv[p], &s[0].Bh[r][wc]);
    }
    __syncthreads();

    const int KT = K / MBK;
    for (int kt = 0; kt < KT; kt++) {
        const int cur = kt & 1;
        const uint32_t sb = sb0 + (uint32_t)cur * stageBytes;
        if (kt + 1 < KT) {
            int k0 = (kt + 1) * MBK;
#pragma unroll
            for (int p = 0; p < 4; p++) {
                int r = lr + p * 32;
                av[p] = *reinterpret_cast<const uint2*>(&A[(size_t)(bm + r) * lda + k0 + lc]);
                bv[p] = *reinterpret_cast<const float4*>(&B[(size_t)(bn + r) * ldb + k0 + lc]);
            }
        }
#pragma unroll
        for (int kk = 0; kk < 2; kk++) {
            uint32_t ah[2][4], bh[4][4];
#pragma unroll
            for (int mf = 0; mf < 2; mf++) {
                uint32_t ao = (uint32_t)(((arow + mf * 16) * MLDW * 4) + (kk * 16 + acol) * 2);
                ldsm4(ah[mf], sb + ao);
            }
#pragma unroll
            for (int np = 0; np < 4; np++) {
                uint32_t bo = (uint32_t)(((brow + np * 16) * MLDW * 4) + (kk * 16 + bcol) * 2);
                ldsm4(bh[np], sb + offBh + bo);
            }
#pragma unroll
            for (int mf = 0; mf < 2; mf++) {
#pragma unroll
                for (int nf = 0; nf < 8; nf++) {
                    int np = nf >> 1;
                    int hf = (nf & 1) * 2;
                    mma_fp(acc[mf][nf], ah[mf], bh[np][hf], bh[np][hf + 1]);
                }
            }
        }
        if (kt + 1 < KT) {
            MSmem1& sn = s[cur ^ 1];
#pragma unroll
            for (int p = 0; p < 4; p++) {
                int r = lr + p * 32;
                sn.Ah[r][wc] = av[p].x;
                sn.Ah[r][wc + 1] = av[p].y;
                convStoreH(bv[p], &sn.Bh[r][wc]);
            }
        }
        __syncthreads();
    }

#pragma unroll
    for (int mf = 0; mf < 2; mf++) {
        int row = bm + wm * 32 + mf * 16 + (lane >> 2);
#pragma unroll
        for (int nf = 0; nf < 8; nf++) {
            int col = bn + wn * 64 + nf * 8 + (lane & 3) * 2;
            *reinterpret_cast<float2*>(&C[(size_t)row * ldc + col]) =
                make_float2(acc[mf][nf][0], acc[mf][nf][1]);
            *reinterpret_cast<float2*>(&C[(size_t)(row + 8) * ldc + col]) =
                make_float2(acc[mf][nf][2], acc[mf][nf][3]);
        }
    }
}

__global__ void __launch_bounds__(256, 2)
mma_nt1(const float* __restrict__ A, const float* __restrict__ B, float* __restrict__ C,
        int K, int lda, int ldb, int ldc) {
    __shared__ MSmem1 s[2];
    mma_core1(A, B, C, K, lda, ldb, ldc, blockIdx.x * MBM, blockIdx.y * MBN, s);
}

__global__ void __launch_bounds__(256, 2)
mma_gateup(const float* __restrict__ A, const float* __restrict__ gw,
           const float* __restrict__ uw, float* __restrict__ gate, float* __restrict__ up) {
    __shared__ MSmem1 s[2];
    if (blockIdx.y < 64) {
        mma_core1(A, gw, gate, H_, H_, H_, FF_, blockIdx.x * MBM, blockIdx.y * MBN, s);
    } else {
        mma_core1(A, uw, up, H_, H_, H_, FF_, blockIdx.x * MBM, (blockIdx.y - 64) * MBN, s);
    }
}

__global__ void __launch_bounds__(256, 2)
mma_attnv(const u16* __restrict__ p, const float* __restrict__ vT, float* __restrict__ o) {
    int z = blockIdx.z;
    int b = z >> 3, h = z & 7;
    const u16* A = p + (size_t)z * T_ * T_;
    const float* B = vT + (size_t)(b * NKV_ + (h >> 2)) * HD_ * T_;
    float* C = o + (size_t)b * T_ * H_ + (size_t)h * HD_;
    int bm = blockIdx.x * MBM;
    __shared__ MSmem1 s[2];
    mma_core1h(A, B, C, bm + MBM, T_, T_, H_, bm, blockIdx.y * MBN, s);
}

// down GEMM with gelu(gate)*up fused into A-load (non-pipelined, single stage)
__global__ void __launch_bounds__(256, 2)
mma_down(const float* __restrict__ G, const float* __restrict__ U,
         const float* __restrict__ B, float* __restrict__ C,
         int K, int lda, int ldb, int ldc) {
    __shared__ MSmem1 s;
    const int tid = threadIdx.x;
    const int lane = tid & 31, wid = tid >> 5;
    const int wm = wid & 3, wn = wid >> 2;
    const int bm = blockIdx.x * MBM, bn = blockIdx.y * MBN;

    float acc[2][8][4];
#pragma unroll
    for (int i = 0; i < 2; i++)
#pragma unroll
        for (int j = 0; j < 8; j++)
#pragma unroll
            for (int e = 0; e < 4; e++) acc[i][j][e] = 0.f;

    const int lr = tid >> 3;
    const int lc = (tid & 7) * 4;
    const int wc = (tid & 7) * 2;

    const uint32_t sb = (uint32_t)__cvta_generic_to_shared(&s);
    const uint32_t offBh = MBM * MLDW * 4;
    const int arow = wm * 32 + (lane & 15);
    const int acol = (lane >> 4) * 8;
    const int brow = wn * 64 + (lane & 7) + ((lane >> 4) << 3);
    const int bcol = ((lane >> 3) & 1) << 3;

    for (int k0 = 0; k0 < K; k0 += MBK) {
#pragma unroll
        for (int p = 0; p < 4; p++) {
            int r = lr + p * 32;
            size_t aoff = (size_t)(bm + r) * lda + k0 + lc;
            float4 g4 = *reinterpret_cast<const float4*>(&G[aoff]);
            float4 u4 = *reinterpret_cast<const float4*>(&U[aoff]);
            float4 hv;
            hv.x = gelu_tanh(g4.x) * u4.x;
            hv.y = gelu_tanh(g4.y) * u4.y;
            hv.z = gelu_tanh(g4.z) * u4.z;
            hv.w = gelu_tanh(g4.w) * u4.w;
            convStoreH(hv, &s.Ah[r][wc]);
            float4 bv = *reinterpret_cast<const float4*>(&B[(size_t)(bn + r) * ldb + k0 + lc]);
            convStoreH(bv, &s.Bh[r][wc]);
        }
        __syncthreads();

#pragma unroll
        for (int kk = 0; kk < 2; kk++) {
            uint32_t ah[2][4], bh[4][4];
#pragma unroll
            for (int mf = 0; mf < 2; mf++) {
                uint32_t ao = (uint32_t)(((arow + mf * 16) * MLDW * 4) + (kk * 16 + acol) * 2);
                ldsm4(ah[mf], sb + ao);
            }
#pragma unroll
            for (int np = 0; np < 4; np++) {
                uint32_t bo = (uint32_t)(((brow + np * 16) * MLDW * 4) + (kk * 16 + bcol) * 2);
                ldsm4(bh[np], sb + offBh + bo);
            }
#pragma unroll
            for (int mf = 0; mf < 2; mf++) {
#pragma unroll
                for (int nf = 0; nf < 8; nf++) {
                    int np = nf >> 1;
                    int hf = (nf & 1) * 2;
                    mma_fp(acc[mf][nf], ah[mf], bh[np][hf], bh[np][hf + 1]);
                }
            }
        }
        __syncthreads();
    }

#pragma unroll
    for (int mf = 0; mf < 2; mf++) {
        int row = bm + wm * 32 + mf * 16 + (lane >> 2);
#pragma unroll
        for (int nf = 0; nf < 8; nf++) {
            int col = bn + wn * 64 + nf * 8 + (lane & 3) * 2;
            *reinterpret_cast<float2*>(&C[(size_t)row * ldc + col]) =
                make_float2(acc[mf][nf][0], acc[mf][nf][1]);
            *reinterpret_cast<float2*>(&C[(size_t)(row + 8) * ldc + col]) =
                make_float2(acc[mf][nf][2], acc[mf][nf][3]);
        }
    }
}

// laurel1: split-K x8
__global__ void __launch_bounds__(256)
laurel1_kernel(const float* __restrict__ A, const float* __restrict__ B, float* __restrict__ P) {
    __shared__ float Bs[64][65];
    __shared__ float As[32][65];
    int tid = threadIdx.x;
    int bm = blockIdx.x * 32;
    int ks = blockIdx.y;
    int kbeg = ks * (H_ / 8), kend = kbeg + H_ / 8;
    float acc0[4] = {0.f, 0.f, 0.f, 0.f};
    float acc1[4] = {0.f, 0.f, 0.f, 0.f};
    int tn = tid & 15;
    int tr = tid >> 4;
    for (int k0 = kbeg; k0 < kend; k0 += 64) {
        for (int i = tid; i < 64 * 64; i += 256) {
            int n = i >> 6, kk = i & 63;
            Bs[n][kk] = B[(size_t)n * H_ + k0 + kk];
        }
        for (int i = tid; i < 32 * 64; i += 256) {
            int r = i >> 6, kk = i & 63;
            As[r][kk] = A[(size_t)(bm + r) * H_ + k0 + kk];
        }
        __syncthreads();
#pragma unroll 8
        for (int kk = 0; kk < 64; kk++) {
            float a0 = As[tr][kk], a1 = As[tr + 16][kk];
#pragma unroll
            for (int j = 0; j < 4; j++) {
                float bv = Bs[tn * 4 + j][kk];
                acc0[j] = fmaf(a0, bv, acc0[j]);
                acc1[j] = fmaf(a1, bv, acc1[j]);
            }
        }
        __syncthreads();
    }
#pragma unroll
    for (int j = 0; j < 4; j++) {
        P[((size_t)ks * BT_ + bm + tr) * LR_ + tn * 4 + j] = acc0[j];
        P[((size_t)ks * BT_ + bm + tr + 16) * LR_ + tn * 4 + j] = acc1[j];
    }
}

__global__ void laurel1_reduce(const float* __restrict__ P, float* __restrict__ out) {
    int i = blockIdx.x * blockDim.x + threadIdx.x;
    if (i >= BT_ * LR_) return;
    float s = 0.f;
#pragma unroll
    for (int k = 0; k < 8; k++) s += P[(size_t)k * BT_ * LR_ + i];
    out[i] = s;
}

// ---------- lazy side stream + events ----------
static cudaStream_t g_s1 = 0;
static cudaEvent_t g_ev0 = 0, g_evL = 0;

extern "C" void kernel_launch(void* const* d_in, const int* in_sizes, int n_in,
                              void* d_out, int out_size) {
    const float* hs    = (const float*)d_in[0];
    const float* cosb  = (const float*)d_in[1];
    const float* sinb  = (const float*)d_in[2];
    const float* wq    = (const float*)d_in[3];
    const float* wk    = (const float*)d_in[4];
    const float* wv    = (const float*)d_in[5];
    const float* wo    = (const float*)d_in[6];
    const float* qnw   = (const float*)d_in[7];
    const float* knw   = (const float*)d_in[8];
    const float* in_ln = (const float*)d_in[9];
    const float* pa_ln = (const float*)d_in[10];
    const float* pf_ln = (const float*)d_in[11];
    const float* pw_ln = (const float*)d_in[12];
    const float* gatew = (const float*)d_in[13];
    const float* upw   = (const float*)d_in[14];
    const float* downw = (const float*)d_in[15];
    const float* llw   = (const float*)d_in[16];
    const float* lrw   = (const float*)d_in[17];
    const float* lnw   = (const float*)d_in[18];
    const float* rnw   = (const float*)d_in[19];
    const float* rw    = (const float*)d_in[20];
    const float* pcw   = (const float*)d_in[21];
    const float* ccw   = (const float*)d_in[22];
    const float* cscal = (const float*)d_in[23];
    float* out = (float*)d_out;

    Scratch* S = 0;
    cudaGetSymbolAddress((void**)&S, g_scratch);

    if (!g_s1) {
        cudaStreamCreateWithFlags(&g_s1, cudaStreamNonBlocking);
        cudaEventCreateWithFlags(&g_ev0, cudaEventDisableTiming);
        cudaEventCreateWithFlags(&g_evL, cudaEventDisableTiming);
    }

    fused_pre<<<BT_, 256>>>(hs, rnw, rw, pcw, in_ln, S->pred, S->xnorm);

    // fork: laurel chain + v chain on side stream
    cudaEventRecord(g_ev0, 0);
    cudaStreamWaitEvent(g_s1, g_ev0, 0);
    laurel1_kernel<<<dim3(BT_ / 32, 8), 256, 0, g_s1>>>(S->xnorm, llw, S->lrpart);
    laurel1_reduce<<<(BT_ * LR_ + 255) / 256, 256, 0, g_s1>>>(S->lrpart, S->lrbuf);
    mma_nt1<<<dim3(16, 16), 256, 0, g_s1>>>(S->lrbuf, lrw, S->laurel, LR_, LR_, LR_, H_);
    ln_kernel<<<BT_, 256, 0, g_s1>>>(S->laurel, lnw, S->xnorm, (const float*)0, 1.f, S->laurel);
    mma_nt1<<<dim3(16, 4), 256, 0, g_s1>>>(S->xnorm, wv, S->vraw, H_, H_, H_, NKV_ * HD_);
    qkvpost_kernel<<<BT_ * NKV_, 256, 0, g_s1>>>(S->vraw, (const float*)0, cosb, sinb,
                                                 S->vT, NKV_, 0, 1);
    cudaEventRecord(g_evL, g_s1);

    // main: q+k projections (combined), post, scores, softmax
    mma_qk<<<dim3(16, 20), 256>>>(S->xnorm, wq, wk, S->qraw, S->kraw);
    qkvpost_qk<<<BT_ * (NH_ + NKV_), 256>>>(S->qraw, S->kraw, qnw, knw, cosb, sinb, S->q, S->k);
    mma_scores<<<dim3(8, 8, B_ * NH_), 256>>>(S->q, S->k, S->scores);
    softmax_kernel<<<B_ * NH_ * T_, 256>>>(S->scores, S->probs);

    cudaStreamWaitEvent(0, g_evL, 0);
    mma_attnv<<<dim3(8, 2, B_ * NH_), 256>>>(S->probs, S->vT, S->attnout);
    mma_nt1<<<dim3(16, 16), 256>>>(S->attnout, wo, S->attnproj,
                                   NH_ * HD_, NH_ * HD_, NH_ * HD_, H_);

    fused_mid<<<BT_, 256>>>(S->attnproj, pa_ln, S->pred, S->laurel, pf_ln,
                            S->attnlaurel, S->hn);

    mma_gateup<<<dim3(16, 128), 256>>>(S->hn, gatew, upw, S->gate, S->up);

    // down GEMM with fused gelu(gate)*up A-operand
    mma_down<<<dim3(16, 16), 256>>>(S->gate, S->up, downw, S->ffw, FF_, FF_, FF_, H_);

    fused_post<<<BT_, 256>>>(S->ffw, pw_ln, S->attnlaurel, rnw, rw, ccw, cscal,
                             S->pred, out);

    (void)in_sizes; (void)n_in; (void)out_size;
}

// round 14
// speedup vs baseline: 1.2166x; 1.2166x over previous
#include <cuda_runtime.h>
#include <cstdint>
#include <cstddef>
#include <math.h>

typedef unsigned short u16;

constexpr int B_ = 2, T_ = 1024, H_ = 2048, NH_ = 8, NKV_ = 2, HD_ = 256;
constexpr int FF_ = 8192, LR_ = 64;
constexpr int BT_ = B_ * T_;
constexpr size_t BTH_ = (size_t)BT_ * H_;
constexpr size_t SCSZ_ = (size_t)B_ * NH_ * T_ * T_;
constexpr size_t FFSZ_ = (size_t)BT_ * FF_;
constexpr float EPS_ = 1e-6f;

struct Scratch {
    float pred[4 * BTH_];
    float xnorm[BTH_];
    float lrpart[8 * BT_ * LR_];
    float lrbuf[BT_ * LR_];
    float laurel[BTH_];
    float qraw[BTH_];
    float kraw[(size_t)BT_ * NKV_ * HD_];
    float vraw[(size_t)BT_ * NKV_ * HD_];
    float q[BTH_];
    float k[(size_t)BT_ * NKV_ * HD_];
    float vT[(size_t)BT_ * NKV_ * HD_];
    float scores[SCSZ_];
    u16 probs[SCSZ_];
    float attnout[BTH_];
    float attnproj[BTH_];
    float attnlaurel[BTH_];
    float hn[BTH_];
    float gate[FFSZ_];
    float up[FFSZ_];
    u16 gp[FFSZ_];
    float ffw[BTH_];
};
__device__ Scratch g_scratch;

// ---------- bf16 / fp16 bit helpers ----------
__device__ __forceinline__ uint32_t f2bf(float x) {
    uint32_t u = __float_as_uint(x);
    return (u + 0x7FFFu + ((u >> 16) & 1u)) >> 16;
}
__device__ __forceinline__ float bf2f(uint32_t b) {
    return __uint_as_float(b << 16);
}
__device__ __forceinline__ u16 f2h(float x) {
    u16 h;
    asm("cvt.rn.f16.f32 %0, %1;" : "=h"(h) : "f"(x));
    return h;
}

// ---------- reductions ----------
__device__ __forceinline__ float warpSum(float v) {
#pragma unroll
    for (int o = 16; o > 0; o >>= 1) v += __shfl_xor_sync(0xffffffffu, v, o);
    return v;
}
__device__ __forceinline__ float warpMax(float v) {
#pragma unroll
    for (int o = 16; o > 0; o >>= 1) v = fmaxf(v, __shfl_xor_sync(0xffffffffu, v, o));
    return v;
}
__device__ __forceinline__ float blockSum(float v, float* red) {
    v = warpSum(v);
    int lane = threadIdx.x & 31, w = threadIdx.x >> 5;
    if (lane == 0) red[w] = v;
    __syncthreads();
    int nw = (blockDim.x + 31) >> 5;
    float r = (lane < nw) ? red[lane] : 0.f;
    if (w == 0) {
        r = warpSum(r);
        if (lane == 0) red[0] = r;
    }
    __syncthreads();
    r = red[0];
    __syncthreads();
    return r;
}
__device__ __forceinline__ float blockMax(float v, float* red) {
    v = warpMax(v);
    int lane = threadIdx.x & 31, w = threadIdx.x >> 5;
    if (lane == 0) red[w] = v;
    __syncthreads();
    int nw = (blockDim.x + 31) >> 5;
    float r = (lane < nw) ? red[lane] : -INFINITY;
    if (w == 0) {
        r = warpMax(r);
        if (lane == 0) red[0] = r;
    }
    __syncthreads();
    r = red[0];
    __syncthreads();
    return r;
}

// ===== fused per-token kernels =====
__global__ void fused_pre(const float* __restrict__ hs, const float* __restrict__ rnw,
                          const float* __restrict__ rw, const float* __restrict__ pcw,
                          const float* __restrict__ inw,
                          float* __restrict__ pred, float* __restrict__ xnorm) {
    __shared__ float sx[H_];
    __shared__ float px[H_];
    __shared__ float red[32];
    __shared__ float cf[16];
    size_t off = (size_t)blockIdx.x * H_;
    int tid = threadIdx.x;

    float ls = 0.f;
    for (int i = tid; i < H_; i += blockDim.x) {
        float v = hs[off + i];
        sx[i] = v;
        ls += v;
    }
    float mean = blockSum(ls, red) * (1.f / H_);
    float lv = 0.f;
    for (int i = tid; i < H_; i += blockDim.x) {
        float d = sx[i] - mean;
        lv += d * d;
    }
    float rs = rsqrtf(blockSum(lv, red) * (1.f / H_) + EPS_);

    float a0 = 0.f, a1 = 0.f, a2 = 0.f, a3 = 0.f;
    for (int i = tid; i < H_; i += blockDim.x) {
        float r = (sx[i] - mean) * rs * rnw[i] * (1.f / H_);
        a0 += r * rw[i];
        a1 += r * rw[H_ + i];
        a2 += r * rw[2 * H_ + i];
        a3 += r * rw[3 * H_ + i];
    }
    float t0 = blockSum(a0, red);
    float t1 = blockSum(a1, red);
    float t2 = blockSum(a2, red);
    float t3 = blockSum(a3, red);
    if (tid < 16) {
        float m0 = tanhf(t0), m1 = tanhf(t1), m2 = tanhf(t2), m3 = tanhf(t3);
        cf[tid] = m0 * pcw[tid * 4] + m1 * pcw[tid * 4 + 1]
                + m2 * pcw[tid * 4 + 2] + m3 * pcw[tid * 4 + 3];
    }
    __syncthreads();

    float ps = 0.f;
    for (int i = tid; i < H_; i += blockDim.x) {
        float h0 = sx[i];
        float h1 = hs[BTH_ + off + i];
        float h2 = hs[2 * BTH_ + off + i];
        float h3 = hs[3 * BTH_ + off + i];
        float p0 = h0 + h0 * cf[0] + h1 * cf[1] + h2 * cf[2] + h3 * cf[3];
        pred[off + i] = p0;
        px[i] = p0;
        ps += p0;
        pred[BTH_ + off + i]     = h1 + h0 * cf[4]  + h1 * cf[5]  + h2 * cf[6]  + h3 * cf[7];
        pred[2 * BTH_ + off + i] = h2 + h0 * cf[8]  + h1 * cf[9]  + h2 * cf[10] + h3 * cf[11];
        pred[3 * BTH_ + off + i] = h3 + h0 * cf[12] + h1 * cf[13] + h2 * cf[14] + h3 * cf[15];
    }
    float mean2 = blockSum(ps, red) * (1.f / H_);
    float lv2 = 0.f;
    for (int i = tid; i < H_; i += blockDim.x) {
        float d = px[i] - mean2;
        lv2 += d * d;
    }
    float rs2 = rsqrtf(blockSum(lv2, red) * (1.f / H_) + EPS_);
    for (int i = tid; i < H_; i += blockDim.x) {
        xnorm[off + i] = (px[i] - mean2) * rs2 * inw[i];
    }
}

__global__ void fused_mid(const float* __restrict__ ap, const float* __restrict__ paw,
                          const float* __restrict__ pred, const float* __restrict__ laurel,
                          const float* __restrict__ pfw,
                          float* __restrict__ attnlaurel, float* __restrict__ hn) {
    __shared__ float sx[H_];
    __shared__ float ax[H_];
    __shared__ float red[32];
    size_t off = (size_t)blockIdx.x * H_;
    int tid = threadIdx.x;

    float ls = 0.f;
    for (int i = tid; i < H_; i += blockDim.x) {
        float v = ap[off + i];
        sx[i] = v;
        ls += v;
    }
    float mean = blockSum(ls, red) * (1.f / H_);
    float lv = 0.f;
    for (int i = tid; i < H_; i += blockDim.x) {
        float d = sx[i] - mean;
        lv += d * d;
    }
    float rs = rsqrtf(blockSum(lv, red) * (1.f / H_) + EPS_);

    float ls2 = 0.f;
    for (int i = tid; i < H_; i += blockDim.x) {
        float v = (sx[i] - mean) * rs * paw[i] + pred[off + i] + laurel[off + i];
        v *= 0.7071067811865476f;
        ax[i] = v;
        attnlaurel[off + i] = v;
        ls2 += v;
    }
    float mean2 = blockSum(ls2, red) * (1.f / H_);
    float lv2 = 0.f;
    for (int i = tid; i < H_; i += blockDim.x) {
        float d = ax[i] - mean2;
        lv2 += d * d;
    }
    float rs2 = rsqrtf(blockSum(lv2, red) * (1.f / H_) + EPS_);
    for (int i = tid; i < H_; i += blockDim.x) {
        hn[off + i] = (ax[i] - mean2) * rs2 * pfw[i];
    }
}

__global__ void fused_post(const float* __restrict__ ffw, const float* __restrict__ pww,
                           const float* __restrict__ attnlaurel,
                           const float* __restrict__ rnw, const float* __restrict__ rw,
                           const float* __restrict__ ccw, const float* __restrict__ cscale,
                           const float* __restrict__ pred, float* __restrict__ out) {
    __shared__ float sx[H_];
    __shared__ float ax[H_];
    __shared__ float red[32];
    size_t off = (size_t)blockIdx.x * H_;
    int tid = threadIdx.x;

    float ls = 0.f;
    for (int i = tid; i < H_; i += blockDim.x) {
        float v = ffw[off + i];
        sx[i] = v;
        ls += v;
    }
    float mean = blockSum(ls, red) * (1.f / H_);
    float lv = 0.f;
    for (int i = tid; i < H_; i += blockDim.x) {
        float d = sx[i] - mean;
        lv += d * d;
    }
    float rs = rsqrtf(blockSum(lv, red) * (1.f / H_) + EPS_);

    float as = 0.f;
    for (int i = tid; i < H_; i += blockDim.x) {
        float v = (sx[i] - mean) * rs * pww[i] + attnlaurel[off + i];
        ax[i] = v;
        as += v;
    }
    float mean2 = blockSum(as, red) * (1.f / H_);
    float lv2 = 0.f;
    for (int i = tid; i < H_; i += blockDim.x) {
        float d = ax[i] - mean2;
        lv2 += d * d;
    }
    float rs2 = rsqrtf(blockSum(lv2, red) * (1.f / H_) + EPS_);
    float a0 = 0.f, a1 = 0.f, a2 = 0.f, a3 = 0.f;
    for (int i = tid; i < H_; i += blockDim.x) {
        float r = (ax[i] - mean2) * rs2 * rnw[i] * (1.f / H_);
        a0 += r * rw[i];
        a1 += r * rw[H_ + i];
        a2 += r * rw[2 * H_ + i];
        a3 += r * rw[3 * H_ + i];
    }
    float m0 = tanhf(blockSum(a0, red));
    float m1 = tanhf(blockSum(a1, red));
    float m2 = tanhf(blockSum(a2, red));
    float m3 = tanhf(blockSum(a3, red));
    float cc0 = 1.f + m0 * ccw[0]  + m1 * ccw[1]  + m2 * ccw[2]  + m3 * ccw[3];
    float cc1 = 1.f + m0 * ccw[4]  + m1 * ccw[5]  + m2 * ccw[6]  + m3 * ccw[7];
    float cc2 = 1.f + m0 * ccw[8]  + m1 * ccw[9]  + m2 * ccw[10] + m3 * ccw[11];
    float cc3 = 1.f + m0 * ccw[12] + m1 * ccw[13] + m2 * ccw[14] + m3 * ccw[15];

    for (int f = tid; f < H_; f += blockDim.x) {
        float p0 = pred[off + f];
        float inno = ax[f] - p0;
        out[off + f]            = (inno * cc0 + p0) * cscale[f];
        out[BTH_ + off + f]     = inno * cc1 + pred[BTH_ + off + f];
        out[2 * BTH_ + off + f] = inno * cc2 + pred[2 * BTH_ + off + f];
        out[3 * BTH_ + off + f] = inno * cc3 + pred[3 * BTH_ + off + f];
    }
}

// ---------- remaining elementwise ----------
__global__ void ln_kernel(const float* __restrict__ a, const float* __restrict__ w,
                          const float* __restrict__ add1, const float* __restrict__ add2,
                          float scale, float* __restrict__ dst) {
    __shared__ float sx[H_];
    __shared__ float red[32];
    size_t off = (size_t)blockIdx.x * H_;
    int tid = threadIdx.x;
    float ls = 0.f;
    for (int i = tid; i < H_; i += blockDim.x) {
        float v = a[off + i];
        sx[i] = v;
        ls += v;
    }
    float mean = blockSum(ls, red) * (1.f / H_);
    float lv = 0.f;
    for (int i = tid; i < H_; i += blockDim.x) {
        float d = sx[i] - mean;
        lv += d * d;
    }
    float var = blockSum(lv, red) * (1.f / H_);
    float rs = rsqrtf(var + EPS_);
    for (int i = tid; i < H_; i += blockDim.x) {
        float v = (sx[i] - mean) * rs * w[i];
        if (add1) v += add1[off + i];
        if (add2) v += add2[off + i];
        dst[off + i] = v * scale;
    }
}

__device__ __forceinline__ void qkvpost_body(
    const float* __restrict__ raw, const float* __restrict__ nw,
    const float* __restrict__ cosb, const float* __restrict__ sinb,
    float* __restrict__ out, int nheads, int do_rope, int trans, int idx) {
    __shared__ float sx[HD_];
    __shared__ float red[32];
    int h = idx % nheads;
    int bt = idx / nheads;
    int t = bt % T_, b = bt / T_;
    int d = threadIdx.x;
    float v = raw[(size_t)bt * nheads * HD_ + h * HD_ + d];
    float mean = blockSum(v, red) * (1.f / HD_);
    float c = v - mean;
    float var = blockSum(c * c, red) * (1.f / HD_);
    float ln = c * rsqrtf(var + EPS_) * (nw ? nw[d] : 1.f);
    sx[d] = ln;
    __syncthreads();
    float o = ln;
    if (do_rope) {
        float cs = cosb[(size_t)bt * HD_ + d];
        float sn = sinb[(size_t)bt * HD_ + d];
        float rot = (d < 128) ? -sx[d + 128] : sx[d - 128];
        o = ln * cs + rot * sn;
    }
    if (trans) {
        out[((size_t)(b * nheads + h) * HD_ + d) * T_ + t] = o;
    } else {
        out[((size_t)(b * nheads + h) * T_ + t) * HD_ + d] = o;
    }
}

__global__ void qkvpost_kernel(const float* __restrict__ raw, const float* __restrict__ nw,
                               const float* __restrict__ cosb, const float* __restrict__ sinb,
                               float* __restrict__ out, int nheads, int do_rope, int trans) {
    qkvpost_body(raw, nw, cosb, sinb, out, nheads, do_rope, trans, blockIdx.x);
}

__global__ void qkvpost_qk(const float* __restrict__ qraw, const float* __restrict__ kraw,
                           const float* __restrict__ qnw, const float* __restrict__ knw,
                           const float* __restrict__ cosb, const float* __restrict__ sinb,
                           float* __restrict__ q, float* __restrict__ k) {
    int idx = blockIdx.x;
    if (idx < BT_ * NH_) {
        qkvpost_body(qraw, qnw, cosb, sinb, q, NH_, 1, 0, idx);
    } else {
        qkvpost_body(kraw, knw, cosb, sinb, k, NKV_, 1, 0, idx - BT_ * NH_);
    }
}

// causal softmax -> fp16 probs
__global__ void softmax_kernel(const float* __restrict__ scores, u16* __restrict__ probs) {
    __shared__ float sx[T_];
    __shared__ float red[32];
    int q = blockIdx.x % T_;
    size_t off = (size_t)blockIdx.x * T_;
    int tid = threadIdx.x;
    int n = q + 1;
    float lm = -INFINITY;
    for (int i = tid; i < n; i += blockDim.x) {
        float v = scores[off + i];
        sx[i] = v;
        lm = fmaxf(lm, v);
    }
    float gm = blockMax(lm, red);
    float lsum = 0.f;
    for (int i = tid; i < n; i += blockDim.x) {
        float e = __expf(sx[i] - gm);
        sx[i] = e;
        lsum += e;
    }
    float inv = 1.f / blockSum(lsum, red);
    for (int i = tid; i < T_; i += blockDim.x) {
        probs[off + i] = (i < n) ? f2h(sx[i] * inv) : (u16)0;
    }
}

__device__ __forceinline__ float gelu_tanh(float x) {
    return 0.5f * x * (1.f + tanhf(0.7978845608028654f * (x + 0.044715f * x * x * x)));
}

// gelu(g)*u -> fp16 plane (evaluated exactly once per element)
__global__ void gelumul_kernel(const float* __restrict__ g, const float* __restrict__ u,
                               u16* __restrict__ o, int n4) {
    int i = blockIdx.x * blockDim.x + threadIdx.x;
    if (i >= n4) return;
    float4 a = reinterpret_cast<const float4*>(g)[i];
    float4 b = reinterpret_cast<const float4*>(u)[i];
    u16 h0 = f2h(gelu_tanh(a.x) * b.x);
    u16 h1 = f2h(gelu_tanh(a.y) * b.y);
    u16 h2 = f2h(gelu_tanh(a.z) * b.z);
    u16 h3 = f2h(gelu_tanh(a.w) * b.w);
    uint2 pk;
    pk.x = (uint32_t)h0 | ((uint32_t)h1 << 16);
    pk.y = (uint32_t)h2 | ((uint32_t)h3 << 16);
    reinterpret_cast<uint2*>(o)[i] = pk;
}

// ===== shared MMA plumbing =====
__device__ __forceinline__ void ldsm4(uint32_t* r, uint32_t addr) {
    asm volatile("ldmatrix.sync.aligned.m8n8.x4.shared.b16 {%0,%1,%2,%3}, [%4];"
                 : "=r"(r[0]), "=r"(r[1]), "=r"(r[2]), "=r"(r[3]) : "r"(addr));
}
__device__ __forceinline__ void mma_bf(float* d, const uint32_t* a, uint32_t b0, uint32_t b1) {
    asm volatile("mma.sync.aligned.m16n8k16.row.col.f32.bf16.bf16.f32 "
                 "{%0,%1,%2,%3}, {%4,%5,%6,%7}, {%8,%9}, {%0,%1,%2,%3};"
                 : "+f"(d[0]), "+f"(d[1]), "+f"(d[2]), "+f"(d[3])
                 : "r"(a[0]), "r"(a[1]), "r"(a[2]), "r"(a[3]), "r"(b0), "r"(b1));
}
__device__ __forceinline__ void mma_fp(float* d, const uint32_t* a, uint32_t b0, uint32_t b1) {
    asm volatile("mma.sync.aligned.m16n8k16.row.col.f32.f16.f16.f32 "
                 "{%0,%1,%2,%3}, {%4,%5,%6,%7}, {%8,%9}, {%0,%1,%2,%3};"
                 : "+f"(d[0]), "+f"(d[1]), "+f"(d[2]), "+f"(d[3])
                 : "r"(a[0]), "r"(a[1]), "r"(a[2]), "r"(a[3]), "r"(b0), "r"(b1));
}
__device__ __forceinline__ void splitStoreBF(float4 v, uint32_t* hi, uint32_t* lo) {
    uint32_t hx = f2bf(v.x), hy = f2bf(v.y), hz = f2bf(v.z), hw = f2bf(v.w);
    uint32_t lx = f2bf(v.x - bf2f(hx));
    uint32_t ly = f2bf(v.y - bf2f(hy));
    uint32_t lz = f2bf(v.z - bf2f(hz));
    uint32_t lw = f2bf(v.w - bf2f(hw));
    hi[0] = hx | (hy << 16);
    hi[1] = hz | (hw << 16);
    lo[0] = lx | (ly << 16);
    lo[1] = lz | (lw << 16);
}
__device__ __forceinline__ void convStoreH(float4 v, uint32_t* hi) {
    u16 hx = f2h(v.x), hy = f2h(v.y), hz = f2h(v.z), hw = f2h(v.w);
    hi[0] = (uint32_t)hx | ((uint32_t)hy << 16);
    hi[1] = (uint32_t)hz | ((uint32_t)hw << 16);
}

constexpr int MBM = 128, MBN = 128, MBK = 32;
constexpr int MLDW = 20;

// ===== 3-pass bf16 core — q/k projections + scores =====
struct MSmem3 {
    uint32_t Ah[MBM][MLDW];
    uint32_t Al[MBM][MLDW];
    uint32_t Bh[MBN][MLDW];
    uint32_t Bl[MBN][MLDW];
};

__device__ __forceinline__ void mma_core3(
    const float* __restrict__ A, const float* __restrict__ B, float* __restrict__ C,
    int K, int lda, int ldb, int ldc, int bm, int bn, MSmem3& s)
{
    const int tid = threadIdx.x;
    const int lane = tid & 31, wid = tid >> 5;
    const int wm = wid & 3, wn = wid >> 2;

    float acc[2][8][4];
#pragma unroll
    for (int i = 0; i < 2; i++)
#pragma unroll
        for (int j = 0; j < 8; j++)
#pragma unroll
            for (int e = 0; e < 4; e++) acc[i][j][e] = 0.f;

    const int lr = tid >> 3;
    const int lc = (tid & 7) * 4;
    const int wc = (tid & 7) * 2;

    const uint32_t sb = (uint32_t)__cvta_generic_to_shared(&s);
    const uint32_t offAl = MBM * MLDW * 4;
    const uint32_t offBh = 2 * MBM * MLDW * 4;
    const uint32_t offBl = 3 * MBM * MLDW * 4;
    const int arow = wm * 32 + (lane & 15);
    const int acol = (lane >> 4) * 8;
    const int brow = wn * 64 + (lane & 7) + ((lane >> 4) << 3);
    const int bcol = ((lane >> 3) & 1) << 3;

    for (int k0 = 0; k0 < K; k0 += MBK) {
#pragma unroll
        for (int p = 0; p < 4; p++) {
            int r = lr + p * 32;
            float4 av = *reinterpret_cast<const float4*>(&A[(size_t)(bm + r) * lda + k0 + lc]);
            splitStoreBF(av, &s.Ah[r][wc], &s.Al[r][wc]);
            float4 bv = *reinterpret_cast<const float4*>(&B[(size_t)(bn + r) * ldb + k0 + lc]);
            splitStoreBF(bv, &s.Bh[r][wc], &s.Bl[r][wc]);
        }
        __syncthreads();

#pragma unroll
        for (int kk = 0; kk < 2; kk++) {
            uint32_t ah[2][4], al[2][4], bh[4][4], bl[4][4];
#pragma unroll
            for (int mf = 0; mf < 2; mf++) {
                uint32_t ao = (uint32_t)(((arow + mf * 16) * MLDW * 4) + (kk * 16 + acol) * 2);
                ldsm4(ah[mf], sb + ao);
                ldsm4(al[mf], sb + offAl + ao);
            }
#pragma unroll
            for (int np = 0; np < 4; np++) {
                uint32_t bo = (uint32_t)(((brow + np * 16) * MLDW * 4) + (kk * 16 + bcol) * 2);
                ldsm4(bh[np], sb + offBh + bo);
                ldsm4(bl[np], sb + offBl + bo);
            }
#pragma unroll
            for (int mf = 0; mf < 2; mf++) {
#pragma unroll
                for (int nf = 0; nf < 8; nf++) {
                    int np = nf >> 1;
                    int hf = (nf & 1) * 2;
                    mma_bf(acc[mf][nf], ah[mf], bh[np][hf], bh[np][hf + 1]);
                    mma_bf(acc[mf][nf], al[mf], bh[np][hf], bh[np][hf + 1]);
                    mma_bf(acc[mf][nf], ah[mf], bl[np][hf], bl[np][hf + 1]);
                }
            }
        }
        __syncthreads();
    }

#pragma unroll
    for (int mf = 0; mf < 2; mf++) {
        int row = bm + wm * 32 + mf * 16 + (lane >> 2);
#pragma unroll
        for (int nf = 0; nf < 8; nf++) {
            int col = bn + wn * 64 + nf * 8 + (lane & 3) * 2;
            *reinterpret_cast<float2*>(&C[(size_t)row * ldc + col]) =
                make_float2(acc[mf][nf][0], acc[mf][nf][1]);
            *reinterpret_cast<float2*>(&C[(size_t)(row + 8) * ldc + col]) =
                make_float2(acc[mf][nf][2], acc[mf][nf][3]);
        }
    }
}

__global__ void __launch_bounds__(256, 2)
mma_qk(const float* __restrict__ A, const float* __restrict__ wq, const float* __restrict__ wk,
       float* __restrict__ qraw, float* __restrict__ kraw) {
    __shared__ MSmem3 s;
    if (blockIdx.y < 16) {
        mma_core3(A, wq, qraw, H_, H_, H_, NH_ * HD_, blockIdx.x * MBM, blockIdx.y * MBN, s);
    } else {
        mma_core3(A, wk, kraw, H_, H_, H_, NKV_ * HD_, blockIdx.x * MBM,
                  (blockIdx.y - 16) * MBN, s);
    }
}

__global__ void __launch_bounds__(256, 2)
mma_scores(const float* __restrict__ q, const float* __restrict__ k, float* __restrict__ sc) {
    if (blockIdx.y > blockIdx.x) return;
    int z = blockIdx.z;
    int b = z >> 3, h = z & 7;
    const float* A = q + (size_t)z * T_ * HD_;
    const float* B = k + (size_t)(b * NKV_ + (h >> 2)) * T_ * HD_;
    float* C = sc + (size_t)z * T_ * T_;
    __shared__ MSmem3 s;
    mma_core3(A, B, C, HD_, HD_, HD_, T_, blockIdx.x * MBM, blockIdx.y * MBN, s);
}

// ===== 1-pass fp16 cores =====
struct MSmem1 {
    uint32_t Ah[MBM][MLDW];
    uint32_t Bh[MBN][MLDW];
};

// pipelined fp32-operand core
__device__ __forceinline__ void mma_core1(
    const float* __restrict__ A, const float* __restrict__ B, float* __restrict__ C,
    int K, int lda, int ldb, int ldc, int bm, int bn, MSmem1 (&s)[2])
{
    const int tid = threadIdx.x;
    const int lane = tid & 31, wid = tid >> 5;
    const int wm = wid & 3, wn = wid >> 2;

    float acc[2][8][4];
#pragma unroll
    for (int i = 0; i < 2; i++)
#pragma unroll
        for (int j = 0; j < 8; j++)
#pragma unroll
            for (int e = 0; e < 4; e++) acc[i][j][e] = 0.f;

    const int lr = tid >> 3;
    const int lc = (tid & 7) * 4;
    const int wc = (tid & 7) * 2;

    const uint32_t sb0 = (uint32_t)__cvta_generic_to_shared(&s[0]);
    const uint32_t stageBytes = (uint32_t)sizeof(MSmem1);
    const uint32_t offBh = MBM * MLDW * 4;
    const int arow = wm * 32 + (lane & 15);
    const int acol = (lane >> 4) * 8;
    const int brow = wn * 64 + (lane & 7) + ((lane >> 4) << 3);
    const int bcol = ((lane >> 3) & 1) << 3;

    float4 av[4], bv[4];
#pragma unroll
    for (int p = 0; p < 4; p++) {
        int r = lr + p * 32;
        av[p] = *reinterpret_cast<const float4*>(&A[(size_t)(bm + r) * lda + lc]);
        bv[p] = *reinterpret_cast<const float4*>(&B[(size_t)(bn + r) * ldb + lc]);
    }
#pragma unroll
    for (int p = 0; p < 4; p++) {
        int r = lr + p * 32;
        convStoreH(av[p], &s[0].Ah[r][wc]);
        convStoreH(bv[p], &s[0].Bh[r][wc]);
    }
    __syncthreads();

    const int KT = K / MBK;
    for (int kt = 0; kt < KT; kt++) {
        const int cur = kt & 1;
        const uint32_t sb = sb0 + (uint32_t)cur * stageBytes;
        if (kt + 1 < KT) {
            int k0 = (kt + 1) * MBK;
#pragma unroll
            for (int p = 0; p < 4; p++) {
                int r = lr + p * 32;
                av[p] = *reinterpret_cast<const float4*>(&A[(size_t)(bm + r) * lda + k0 + lc]);
                bv[p] = *reinterpret_cast<const float4*>(&B[(size_t)(bn + r) * ldb + k0 + lc]);
            }
        }
#pragma unroll
        for (int kk = 0; kk < 2; kk++) {
            uint32_t ah[2][4], bh[4][4];
#pragma unroll
            for (int mf = 0; mf < 2; mf++) {
                uint32_t ao = (uint32_t)(((arow + mf * 16) * MLDW * 4) + (kk * 16 + acol) * 2);
                ldsm4(ah[mf], sb + ao);
            }
#pragma unroll
            for (int np = 0; np < 4; np++) {
                uint32_t bo = (uint32_t)(((brow + np * 16) * MLDW * 4) + (kk * 16 + bcol) * 2);
                ldsm4(bh[np], sb + offBh + bo);
            }
#pragma unroll
            for (int mf = 0; mf < 2; mf++) {
#pragma unroll
                for (int nf = 0; nf < 8; nf++) {
                    int np = nf >> 1;
                    int hf = (nf & 1) * 2;
                    mma_fp(acc[mf][nf], ah[mf], bh[np][hf], bh[np][hf + 1]);
                }
            }
        }
        if (kt + 1 < KT) {
            MSmem1& sn = s[cur ^ 1];
#pragma unroll
            for (int p = 0; p < 4; p++) {
                int r = lr + p * 32;
                convStoreH(av[p], &sn.Ah[r][wc]);
                convStoreH(bv[p], &sn.Bh[r][wc]);
            }
        }
        __syncthreads();
    }

#pragma unroll
    for (int mf = 0; mf < 2; mf++) {
        int row = bm + wm * 32 + mf * 16 + (lane >> 2);
#pragma unroll
        for (int nf = 0; nf < 8; nf++) {
            int col = bn + wn * 64 + nf * 8 + (lane & 3) * 2;
            *reinterpret_cast<float2*>(&C[(size_t)row * ldc + col]) =
                make_float2(acc[mf][nf][0], acc[mf][nf][1]);
            *reinterpret_cast<float2*>(&C[(size_t)(row + 8) * ldc + col]) =
                make_float2(acc[mf][nf][2], acc[mf][nf][3]);
        }
    }
}

// pipelined core with u16 (fp16) A operand
__device__ __forceinline__ void mma_core1h(
    const u16* __restrict__ A, const float* __restrict__ B, float* __restrict__ C,
    int K, int lda, int ldb, int ldc, int bm, int bn, MSmem1 (&s)[2])
{
    const int tid = threadIdx.x;
    const int lane = tid & 31, wid = tid >> 5;
    const int wm = wid & 3, wn = wid >> 2;

    float acc[2][8][4];
#pragma unroll
    for (int i = 0; i < 2; i++)
#pragma unroll
        for (int j = 0; j < 8; j++)
#pragma unroll
            for (int e = 0; e < 4; e++) acc[i][j][e] = 0.f;

    const int lr = tid >> 3;
    const int lc = (tid & 7) * 4;
    const int wc = (tid & 7) * 2;

    const uint32_t sb0 = (uint32_t)__cvta_generic_to_shared(&s[0]);
    const uint32_t stageBytes = (uint32_t)sizeof(MSmem1);
    const uint32_t offBh = MBM * MLDW * 4;
    const int arow = wm * 32 + (lane & 15);
    const int acol = (lane >> 4) * 8;
    const int brow = wn * 64 + (lane & 7) + ((lane >> 4) << 3);
    const int bcol = ((lane >> 3) & 1) << 3;

    uint2 av[4];
    float4 bv[4];
#pragma unroll
    for (int p = 0; p < 4; p++) {
        int r = lr + p * 32;
        av[p] = *reinterpret_cast<const uint2*>(&A[(size_t)(bm + r) * lda + lc]);
        bv[p] = *reinterpret_cast<const float4*>(&B[(size_t)(bn + r) * ldb + lc]);
    }
#pragma unroll
    for (int p = 0; p < 4; p++) {
        int r = lr + p * 32;
        s[0].Ah[r][wc] = av[p].x;
        s[0].Ah[r][wc + 1] = av[p].y;
        convStoreH(bv[p], &s[0].Bh[r][wc]);
    }
    __syncthreads();

    const int KT = K / MBK;
    for (int kt = 0; kt < KT; kt++) {
        const int cur = kt & 1;
        const uint32_t sb = sb0 + (uint32_t)cur * stageBytes;
        if (kt + 1 < KT) {
            int k0 = (kt + 1) * MBK;
#pragma unroll
            for (int p = 0; p < 4; p++) {
                int r = lr + p * 32;
                av[p] = *reinterpret_cast<const uint2*>(&A[(size_t)(bm + r) * lda + k0 + lc]);
                bv[p] = *reinterpret_cast<const float4*>(&B[(size_t)(bn + r) * ldb + k0 + lc]);
            }
        }
#pragma unroll
        for (int kk = 0; kk < 2; kk++) {
            uint32_t ah[2][4], bh[4][4];
#pragma unroll
            for (int mf = 0; mf < 2; mf++) {
                uint32_t ao = (uint32_t)(((arow + mf * 16) * MLDW * 4) + (kk * 16 + acol) * 2);
                ldsm4(ah[mf], sb + ao);
            }
#pragma unroll
            for (int np = 0; np < 4; np++) {
                uint32_t bo = (uint32_t)(((brow + np * 16) * MLDW * 4) + (kk * 16 + bcol) * 2);
                ldsm4(bh[np], sb + offBh + bo);
            }
#pragma unroll
            for (int mf = 0; mf < 2; mf++) {
#pragma unroll
                for (int nf = 0; nf < 8; nf++) {
                    int np = nf >> 1;
                    int hf = (nf & 1) * 2;
                    mma_fp(acc[mf][nf], ah[mf], bh[np][hf], bh[np][hf + 1]);
                }
            }
        }
        if (kt + 1 < KT) {
            MSmem1& sn = s[cur ^ 1];
#pragma unroll
            for (int p = 0; p < 4; p++) {
                int r = lr + p * 32;
                sn.Ah[r][wc] = av[p].x;
                sn.Ah[r][wc + 1] = av[p].y;
                convStoreH(bv[p], &sn.Bh[r][wc]);
            }
        }
        __syncthreads();
    }

#pragma unroll
    for (int mf = 0; mf < 2; mf++) {
        int row = bm + wm * 32 + mf * 16 + (lane >> 2);
#pragma unroll
        for (int nf = 0; nf < 8; nf++) {
            int col = bn + wn * 64 + nf * 8 + (lane & 3) * 2;
            *reinterpret_cast<float2*>(&C[(size_t)row * ldc + col]) =
                make_float2(acc[mf][nf][0], acc[mf][nf][1]);
            *reinterpret_cast<float2*>(&C[(size_t)(row + 8) * ldc + col]) =
                make_float2(acc[mf][nf][2], acc[mf][nf][3]);
        }
    }
}

__global__ void __launch_bounds__(256, 2)
mma_nt1(const float* __restrict__ A, const float* __restrict__ B, float* __restrict__ C,
        int K, int lda, int ldb, int ldc) {
    __shared__ MSmem1 s[2];
    mma_core1(A, B, C, K, lda, ldb, ldc, blockIdx.x * MBM, blockIdx.y * MBN, s);
}

// general u16-A GEMM (down)
__global__ void __launch_bounds__(256, 2)
mma_nt1h(const u16* __restrict__ A, const float* __restrict__ B, float* __restrict__ C,
         int K, int lda, int ldb, int ldc) {
    __shared__ MSmem1 s[2];
    mma_core1h(A, B, C, K, lda, ldb, ldc, blockIdx.x * MBM, blockIdx.y * MBN, s);
}

__global__ void __launch_bounds__(256, 2)
mma_gateup(const float* __restrict__ A, const float* __restrict__ gw,
           const float* __restrict__ uw, float* __restrict__ gate, float* __restrict__ up) {
    __shared__ MSmem1 s[2];
    if (blockIdx.y < 64) {
        mma_core1(A, gw, gate, H_, H_, H_, FF_, blockIdx.x * MBM, blockIdx.y * MBN, s);
    } else {
        mma_core1(A, uw, up, H_, H_, H_, FF_, blockIdx.x * MBM, (blockIdx.y - 64) * MBN, s);
    }
}

__global__ void __launch_bounds__(256, 2)
mma_attnv(const u16* __restrict__ p, const float* __restrict__ vT, float* __restrict__ o) {
    int z = blockIdx.z;
    int b = z >> 3, h = z & 7;
    const u16* A = p + (size_t)z * T_ * T_;
    const float* B = vT + (size_t)(b * NKV_ + (h >> 2)) * HD_ * T_;
    float* C = o + (size_t)b * T_ * H_ + (size_t)h * HD_;
    int bm = blockIdx.x * MBM;
    __shared__ MSmem1 s[2];
    mma_core1h(A, B, C, bm + MBM, T_, T_, H_, bm, blockIdx.y * MBN, s);
}

// laurel1: split-K x8
__global__ void __launch_bounds__(256)
laurel1_kernel(const float* __restrict__ A, const float* __restrict__ B, float* __restrict__ P) {
    __shared__ float Bs[64][65];
    __shared__ float As[32][65];
    int tid = threadIdx.x;
    int bm = blockIdx.x * 32;
    int ks = blockIdx.y;
    int kbeg = ks * (H_ / 8), kend = kbeg + H_ / 8;
    float acc0[4] = {0.f, 0.f, 0.f, 0.f};
    float acc1[4] = {0.f, 0.f, 0.f, 0.f};
    int tn = tid & 15;
    int tr = tid >> 4;
    for (int k0 = kbeg; k0 < kend; k0 += 64) {
        for (int i = tid; i < 64 * 64; i += 256) {
            int n = i >> 6, kk = i & 63;
            Bs[n][kk] = B[(size_t)n * H_ + k0 + kk];
        }
        for (int i = tid; i < 32 * 64; i += 256) {
            int r = i >> 6, kk = i & 63;
            As[r][kk] = A[(size_t)(bm + r) * H_ + k0 + kk];
        }
        __syncthreads();
#pragma unroll 8
        for (int kk = 0; kk < 64; kk++) {
            float a0 = As[tr][kk], a1 = As[tr + 16][kk];
#pragma unroll
            for (int j = 0; j < 4; j++) {
                float bv = Bs[tn * 4 + j][kk];
                acc0[j] = fmaf(a0, bv, acc0[j]);
                acc1[j] = fmaf(a1, bv, acc1[j]);
            }
        }
        __syncthreads();
    }
#pragma unroll
    for (int j = 0; j < 4; j++) {
        P[((size_t)ks * BT_ + bm + tr) * LR_ + tn * 4 + j] = acc0[j];
        P[((size_t)ks * BT_ + bm + tr + 16) * LR_ + tn * 4 + j] = acc1[j];
    }
}

__global__ void laurel1_reduce(const float* __restrict__ P, float* __restrict__ out) {
    int i = blockIdx.x * blockDim.x + threadIdx.x;
    if (i >= BT_ * LR_) return;
    float s = 0.f;
#pragma unroll
    for (int k = 0; k < 8; k++) s += P[(size_t)k * BT_ * LR_ + i];
    out[i] = s;
}

// ---------- lazy side stream + events ----------
static cudaStream_t g_s1 = 0;
static cudaEvent_t g_ev0 = 0, g_evL = 0;

extern "C" void kernel_launch(void* const* d_in, const int* in_sizes, int n_in,
                              void* d_out, int out_size) {
    const float* hs    = (const float*)d_in[0];
    const float* cosb  = (const float*)d_in[1];
    const float* sinb  = (const float*)d_in[2];
    const float* wq    = (const float*)d_in[3];
    const float* wk    = (const float*)d_in[4];
    const float* wv    = (const float*)d_in[5];
    const float* wo    = (const float*)d_in[6];
    const float* qnw   = (const float*)d_in[7];
    const float* knw   = (const float*)d_in[8];
    const float* in_ln = (const float*)d_in[9];
    const float* pa_ln = (const float*)d_in[10];
    const float* pf_ln = (const float*)d_in[11];
    const float* pw_ln = (const float*)d_in[12];
    const float* gatew = (const float*)d_in[13];
    const float* upw   = (const float*)d_in[14];
    const float* downw = (const float*)d_in[15];
    const float* llw   = (const float*)d_in[16];
    const float* lrw   = (const float*)d_in[17];
    const float* lnw   = (const float*)d_in[18];
    const float* rnw   = (const float*)d_in[19];
    const float* rw    = (const float*)d_in[20];
    const float* pcw   = (const float*)d_in[21];
    const float* ccw   = (const float*)d_in[22];
    const float* cscal = (const float*)d_in[23];
    float* out = (float*)d_out;

    Scratch* S = 0;
    cudaGetSymbolAddress((void**)&S, g_scratch);

    if (!g_s1) {
        cudaStreamCreateWithFlags(&g_s1, cudaStreamNonBlocking);
        cudaEventCreateWithFlags(&g_ev0, cudaEventDisableTiming);
        cudaEventCreateWithFlags(&g_evL, cudaEventDisableTiming);
    }

    fused_pre<<<BT_, 256>>>(hs, rnw, rw, pcw, in_ln, S->pred, S->xnorm);

    // fork: laurel chain + v chain on side stream
    cudaEventRecord(g_ev0, 0);
    cudaStreamWaitEvent(g_s1, g_ev0, 0);
    laurel1_kernel<<<dim3(BT_ / 32, 8), 256, 0, g_s1>>>(S->xnorm, llw, S->lrpart);
    laurel1_reduce<<<(BT_ * LR_ + 255) / 256, 256, 0, g_s1>>>(S->lrpart, S->lrbuf);
    mma_nt1<<<dim3(16, 16), 256, 0, g_s1>>>(S->lrbuf, lrw, S->laurel, LR_, LR_, LR_, H_);
    ln_kernel<<<BT_, 256, 0, g_s1>>>(S->laurel, lnw, S->xnorm, (const float*)0, 1.f, S->laurel);
    mma_nt1<<<dim3(16, 4), 256, 0, g_s1>>>(S->xnorm, wv, S->vraw, H_, H_, H_, NKV_ * HD_);
    qkvpost_kernel<<<BT_ * NKV_, 256, 0, g_s1>>>(S->vraw, (const float*)0, cosb, sinb,
                                                 S->vT, NKV_, 0, 1);
    cudaEventRecord(g_evL, g_s1);

    // main: q+k projections (combined), post, scores, softmax
    mma_qk<<<dim3(16, 20), 256>>>(S->xnorm, wq, wk, S->qraw, S->kraw);
    qkvpost_qk<<<BT_ * (NH_ + NKV_), 256>>>(S->qraw, S->kraw, qnw, knw, cosb, sinb, S->q, S->k);
    mma_scores<<<dim3(8, 8, B_ * NH_), 256>>>(S->q, S->k, S->scores);
    softmax_kernel<<<B_ * NH_ * T_, 256>>>(S->scores, S->probs);

    cudaStreamWaitEvent(0, g_evL, 0);
    mma_attnv<<<dim3(8, 2, B_ * NH_), 256>>>(S->probs, S->vT, S->attnout);
    mma_nt1<<<dim3(16, 16), 256>>>(S->attnout, wo, S->attnproj,
                                   NH_ * HD_, NH_ * HD_, NH_ * HD_, H_);

    fused_mid<<<BT_, 256>>>(S->attnproj, pa_ln, S->pred, S->laurel, pf_ln,
                            S->attnlaurel, S->hn);

    mma_gateup<<<dim3(16, 128), 256>>>(S->hn, gatew, upw, S->gate, S->up);

    // gelu(gate)*up -> fp16 plane (once per element), then u16-A down GEMM
    int n4 = (int)(FFSZ_ / 4);
    gelumul_kernel<<<(n4 + 255) / 256, 256>>>(S->gate, S->up, S->gp, n4);
    mma_nt1h<<<dim3(16, 16), 256>>>(S->gp, downw, S->ffw, FF_, FF_, FF_, H_);

    fused_post<<<BT_, 256>>>(S->ffw, pw_ln, S->attnlaurel, rnw, rw, ccw, cscal,
                             S->pred, out);

    (void)in_sizes; (void)n_in; (void)out_size;
}

// round 15
// speedup vs baseline: 1.2787x; 1.0511x over previous
#include <cuda_runtime.h>
#include <cstdint>
#include <cstddef>
#include <math.h>

typedef unsigned short u16;

constexpr int B_ = 2, T_ = 1024, H_ = 2048, NH_ = 8, NKV_ = 2, HD_ = 256;
constexpr int FF_ = 8192, LR_ = 64;
constexpr int BT_ = B_ * T_;
constexpr size_t BTH_ = (size_t)BT_ * H_;
constexpr size_t SCSZ_ = (size_t)B_ * NH_ * T_ * T_;
constexpr size_t FFSZ_ = (size_t)BT_ * FF_;
constexpr float EPS_ = 1e-6f;

struct Scratch {
    float pred0[BTH_];
    float cfg[BT_ * 16];
    float xnorm[BTH_];
    float lrpart[8 * BT_ * LR_];
    float lrbuf[BT_ * LR_];
    float laurel[BTH_];
    float qraw[BTH_];
    float kraw[(size_t)BT_ * NKV_ * HD_];
    float vraw[(size_t)BT_ * NKV_ * HD_];
    float q[BTH_];
    float k[(size_t)BT_ * NKV_ * HD_];
    float vT[(size_t)BT_ * NKV_ * HD_];
    float scores[SCSZ_];
    u16 probs[SCSZ_];
    u16 aoH[BTH_];
    float attnproj[BTH_];
    float attnlaurel[BTH_];
    u16 hnH[BTH_];
    u16 gateH[FFSZ_];
    u16 upH[FFSZ_];
    u16 gp[FFSZ_];
    float ffw[BTH_];
};
__device__ Scratch g_scratch;

// ---------- bf16 / fp16 bit helpers ----------
__device__ __forceinline__ uint32_t f2bf(float x) {
    uint32_t u = __float_as_uint(x);
    return (u + 0x7FFFu + ((u >> 16) & 1u)) >> 16;
}
__device__ __forceinline__ float bf2f(uint32_t b) {
    return __uint_as_float(b << 16);
}
__device__ __forceinline__ u16 f2h(float x) {
    u16 h;
    asm("cvt.rn.f16.f32 %0, %1;" : "=h"(h) : "f"(x));
    return h;
}
__device__ __forceinline__ float h2f(u16 h) {
    float f;
    asm("cvt.f32.f16 %0, %1;" : "=f"(f) : "h"(h));
    return f;
}

// ---------- reductions ----------
__device__ __forceinline__ float warpSum(float v) {
#pragma unroll
    for (int o = 16; o > 0; o >>= 1) v += __shfl_xor_sync(0xffffffffu, v, o);
    return v;
}
__device__ __forceinline__ float warpMax(float v) {
#pragma unroll
    for (int o = 16; o > 0; o >>= 1) v = fmaxf(v, __shfl_xor_sync(0xffffffffu, v, o));
    return v;
}
__device__ __forceinline__ float blockSum(float v, float* red) {
    v = warpSum(v);
    int lane = threadIdx.x & 31, w = threadIdx.x >> 5;
    if (lane == 0) red[w] = v;
    __syncthreads();
    int nw = (blockDim.x + 31) >> 5;
    float r = (lane < nw) ? red[lane] : 0.f;
    if (w == 0) {
        r = warpSum(r);
        if (lane == 0) red[0] = r;
    }
    __syncthreads();
    r = red[0];
    __syncthreads();
    return r;
}
__device__ __forceinline__ float blockMax(float v, float* red) {
    v = warpMax(v);
    int lane = threadIdx.x & 31, w = threadIdx.x >> 5;
    if (lane == 0) red[w] = v;
    __syncthreads();
    int nw = (blockDim.x + 31) >> 5;
    float r = (lane < nw) ? red[lane] : -INFINITY;
    if (w == 0) {
        r = warpMax(r);
        if (lane == 0) red[0] = r;
    }
    __syncthreads();
    r = red[0];
    __syncthreads();
    return r;
}

// ===== fused per-token kernels =====
// router(hs0) + AltUp predict-coeffs + pred0 + input LN -> pred0, cfg, xnorm
__global__ void fused_pre(const float* __restrict__ hs, const float* __restrict__ rnw,
                          const float* __restrict__ rw, const float* __restrict__ pcw,
                          const float* __restrict__ inw,
                          float* __restrict__ pred0, float* __restrict__ cfg,
                          float* __restrict__ xnorm) {
    __shared__ float sx[H_];
    __shared__ float px[H_];
    __shared__ float red[32];
    __shared__ float cf[16];
    size_t off = (size_t)blockIdx.x * H_;
    int tid = threadIdx.x;

    float ls = 0.f;
    for (int i = tid; i < H_; i += blockDim.x) {
        float v = hs[off + i];
        sx[i] = v;
        ls += v;
    }
    float mean = blockSum(ls, red) * (1.f / H_);
    float lv = 0.f;
    for (int i = tid; i < H_; i += blockDim.x) {
        float d = sx[i] - mean;
        lv += d * d;
    }
    float rs = rsqrtf(blockSum(lv, red) * (1.f / H_) + EPS_);

    float a0 = 0.f, a1 = 0.f, a2 = 0.f, a3 = 0.f;
    for (int i = tid; i < H_; i += blockDim.x) {
        float r = (sx[i] - mean) * rs * rnw[i] * (1.f / H_);
        a0 += r * rw[i];
        a1 += r * rw[H_ + i];
        a2 += r * rw[2 * H_ + i];
        a3 += r * rw[3 * H_ + i];
    }
    float t0 = blockSum(a0, red);
    float t1 = blockSum(a1, red);
    float t2 = blockSum(a2, red);
    float t3 = blockSum(a3, red);
    if (tid < 16) {
        float m0 = tanhf(t0), m1 = tanhf(t1), m2 = tanhf(t2), m3 = tanhf(t3);
        float c = m0 * pcw[tid * 4] + m1 * pcw[tid * 4 + 1]
                + m2 * pcw[tid * 4 + 2] + m3 * pcw[tid * 4 + 3];
        cf[tid] = c;
        cfg[(size_t)blockIdx.x * 16 + tid] = c;
    }
    __syncthreads();

    float ps = 0.f;
    for (int i = tid; i < H_; i += blockDim.x) {
        float h0 = sx[i];
        float h1 = hs[BTH_ + off + i];
        float h2 = hs[2 * BTH_ + off + i];
        float h3 = hs[3 * BTH_ + off + i];
        float p0 = h0 + h0 * cf[0] + h1 * cf[1] + h2 * cf[2] + h3 * cf[3];
        pred0[off + i] = p0;
        px[i] = p0;
        ps += p0;
    }
    float mean2 = blockSum(ps, red) * (1.f / H_);
    float lv2 = 0.f;
    for (int i = tid; i < H_; i += blockDim.x) {
        float d = px[i] - mean2;
        lv2 += d * d;
    }
    float rs2 = rsqrtf(blockSum(lv2, red) * (1.f / H_) + EPS_);
    for (int i = tid; i < H_; i += blockDim.x) {
        xnorm[off + i] = (px[i] - mean2) * rs2 * inw[i];
    }
}

// post-attn LN (+pred0+laurel, /sqrt2) + pre-ffw LN -> attnlaurel, hnH (fp16)
__global__ void fused_mid(const float* __restrict__ ap, const float* __restrict__ paw,
                          const float* __restrict__ pred0, const float* __restrict__ laurel,
                          const float* __restrict__ pfw,
                          float* __restrict__ attnlaurel, u16* __restrict__ hnH) {
    __shared__ float sx[H_];
    __shared__ float ax[H_];
    __shared__ float red[32];
    size_t off = (size_t)blockIdx.x * H_;
    int tid = threadIdx.x;

    float ls = 0.f;
    for (int i = tid; i < H_; i += blockDim.x) {
        float v = ap[off + i];
        sx[i] = v;
        ls += v;
    }
    float mean = blockSum(ls, red) * (1.f / H_);
    float lv = 0.f;
    for (int i = tid; i < H_; i += blockDim.x) {
        float d = sx[i] - mean;
        lv += d * d;
    }
    float rs = rsqrtf(blockSum(lv, red) * (1.f / H_) + EPS_);

    float ls2 = 0.f;
    for (int i = tid; i < H_; i += blockDim.x) {
        float v = (sx[i] - mean) * rs * paw[i] + pred0[off + i] + laurel[off + i];
        v *= 0.7071067811865476f;
        ax[i] = v;
        attnlaurel[off + i] = v;
        ls2 += v;
    }
    float mean2 = blockSum(ls2, red) * (1.f / H_);
    float lv2 = 0.f;
    for (int i = tid; i < H_; i += blockDim.x) {
        float d = ax[i] - mean2;
        lv2 += d * d;
    }
    float rs2 = rsqrtf(blockSum(lv2, red) * (1.f / H_) + EPS_);
    for (int i = tid; i < H_; i += blockDim.x) {
        hnH[off + i] = f2h((ax[i] - mean2) * rs2 * pfw[i]);
    }
}

// post-ffw LN (+attnlaurel) + router + AltUp correct (pred recomputed from hs+cf)
__global__ void fused_post(const float* __restrict__ ffw, const float* __restrict__ pww,
                           const float* __restrict__ attnlaurel,
                           const float* __restrict__ rnw, const float* __restrict__ rw,
                           const float* __restrict__ ccw, const float* __restrict__ cscale,
                           const float* __restrict__ hs, const float* __restrict__ cfg,
                           float* __restrict__ out) {
    __shared__ float sx[H_];
    __shared__ float ax[H_];
    __shared__ float red[32];
    __shared__ float cf[16];
    size_t off = (size_t)blockIdx.x * H_;
    int tid = threadIdx.x;

    if (tid < 16) cf[tid] = cfg[(size_t)blockIdx.x * 16 + tid];

    float ls = 0.f;
    for (int i = tid; i < H_; i += blockDim.x) {
        float v = ffw[off + i];
        sx[i] = v;
        ls += v;
    }
    float mean = blockSum(ls, red) * (1.f / H_);
    float lv = 0.f;
    for (int i = tid; i < H_; i += blockDim.x) {
        float d = sx[i] - mean;
        lv += d * d;
    }
    float rs = rsqrtf(blockSum(lv, red) * (1.f / H_) + EPS_);

    float as = 0.f;
    for (int i = tid; i < H_; i += blockDim.x) {
        float v = (sx[i] - mean) * rs * pww[i] + attnlaurel[off + i];
        ax[i] = v;
        as += v;
    }
    float mean2 = blockSum(as, red) * (1.f / H_);
    float lv2 = 0.f;
    for (int i = tid; i < H_; i += blockDim.x) {
        float d = ax[i] - mean2;
        lv2 += d * d;
    }
    float rs2 = rsqrtf(blockSum(lv2, red) * (1.f / H_) + EPS_);
    float a0 = 0.f, a1 = 0.f, a2 = 0.f, a3 = 0.f;
    for (int i = tid; i < H_; i += blockDim.x) {
        float r = (ax[i] - mean2) * rs2 * rnw[i] * (1.f / H_);
        a0 += r * rw[i];
        a1 += r * rw[H_ + i];
        a2 += r * rw[2 * H_ + i];
        a3 += r * rw[3 * H_ + i];
    }
    float m0 = tanhf(blockSum(a0, red));
    float m1 = tanhf(blockSum(a1, red));
    float m2 = tanhf(blockSum(a2, red));
    float m3 = tanhf(blockSum(a3, red));
    float cc0 = 1.f + m0 * ccw[0]  + m1 * ccw[1]  + m2 * ccw[2]  + m3 * ccw[3];
    float cc1 = 1.f + m0 * ccw[4]  + m1 * ccw[5]  + m2 * ccw[6]  + m3 * ccw[7];
    float cc2 = 1.f + m0 * ccw[8]  + m1 * ccw[9]  + m2 * ccw[10] + m3 * ccw[11];
    float cc3 = 1.f + m0 * ccw[12] + m1 * ccw[13] + m2 * ccw[14] + m3 * ccw[15];

    for (int f = tid; f < H_; f += blockDim.x) {
        float h0 = hs[off + f];
        float h1 = hs[BTH_ + off + f];
        float h2 = hs[2 * BTH_ + off + f];
        float h3 = hs[3 * BTH_ + off + f];
        float p0 = h0 + h0 * cf[0]  + h1 * cf[1]  + h2 * cf[2]  + h3 * cf[3];
        float p1 = h1 + h0 * cf[4]  + h1 * cf[5]  + h2 * cf[6]  + h3 * cf[7];
        float p2 = h2 + h0 * cf[8]  + h1 * cf[9]  + h2 * cf[10] + h3 * cf[11];
        float p3 = h3 + h0 * cf[12] + h1 * cf[13] + h2 * cf[14] + h3 * cf[15];
        float inno = ax[f] - p0;
        out[off + f]            = (inno * cc0 + p0) * cscale[f];
        out[BTH_ + off + f]     = inno * cc1 + p1;
        out[2 * BTH_ + off + f] = inno * cc2 + p2;
        out[3 * BTH_ + off + f] = inno * cc3 + p3;
    }
}

// ---------- remaining elementwise ----------
__global__ void ln_kernel(const float* __restrict__ a, const float* __restrict__ w,
                          const float* __restrict__ add1, const float* __restrict__ add2,
                          float scale, float* __restrict__ dst) {
    __shared__ float sx[H_];
    __shared__ float red[32];
    size_t off = (size_t)blockIdx.x * H_;
    int tid = threadIdx.x;
    float ls = 0.f;
    for (int i = tid; i < H_; i += blockDim.x) {
        float v = a[off + i];
        sx[i] = v;
        ls += v;
    }
    float mean = blockSum(ls, red) * (1.f / H_);
    float lv = 0.f;
    for (int i = tid; i < H_; i += blockDim.x) {
        float d = sx[i] - mean;
        lv += d * d;
    }
    float var = blockSum(lv, red) * (1.f / H_);
    float rs = rsqrtf(var + EPS_);
    for (int i = tid; i < H_; i += blockDim.x) {
        float v = (sx[i] - mean) * rs * w[i];
        if (add1) v += add1[off + i];
        if (add2) v += add2[off + i];
        dst[off + i] = v * scale;
    }
}

__device__ __forceinline__ void qkvpost_body(
    const float* __restrict__ raw, const float* __restrict__ nw,
    const float* __restrict__ cosb, const float* __restrict__ sinb,
    float* __restrict__ out, int nheads, int do_rope, int trans, int idx) {
    __shared__ float sx[HD_];
    __shared__ float red[32];
    int h = idx % nheads;
    int bt = idx / nheads;
    int t = bt % T_, b = bt / T_;
    int d = threadIdx.x;
    float v = raw[(size_t)bt * nheads * HD_ + h * HD_ + d];
    float mean = blockSum(v, red) * (1.f / HD_);
    float c = v - mean;
    float var = blockSum(c * c, red) * (1.f / HD_);
    float ln = c * rsqrtf(var + EPS_) * (nw ? nw[d] : 1.f);
    sx[d] = ln;
    __syncthreads();
    float o = ln;
    if (do_rope) {
        float cs = cosb[(size_t)bt * HD_ + d];
        float sn = sinb[(size_t)bt * HD_ + d];
        float rot = (d < 128) ? -sx[d + 128] : sx[d - 128];
        o = ln * cs + rot * sn;
    }
    if (trans) {
        out[((size_t)(b * nheads + h) * HD_ + d) * T_ + t] = o;
    } else {
        out[((size_t)(b * nheads + h) * T_ + t) * HD_ + d] = o;
    }
}

__global__ void qkvpost_kernel(const float* __restrict__ raw, const float* __restrict__ nw,
                               const float* __restrict__ cosb, const float* __restrict__ sinb,
                               float* __restrict__ out, int nheads, int do_rope, int trans) {
    qkvpost_body(raw, nw, cosb, sinb, out, nheads, do_rope, trans, blockIdx.x);
}

__global__ void qkvpost_qk(const float* __restrict__ qraw, const float* __restrict__ kraw,
                           const float* __restrict__ qnw, const float* __restrict__ knw,
                           const float* __restrict__ cosb, const float* __restrict__ sinb,
                           float* __restrict__ q, float* __restrict__ k) {
    int idx = blockIdx.x;
    if (idx < BT_ * NH_) {
        qkvpost_body(qraw, qnw, cosb, sinb, q, NH_, 1, 0, idx);
    } else {
        qkvpost_body(kraw, knw, cosb, sinb, k, NKV_, 1, 0, idx - BT_ * NH_);
    }
}

// causal softmax -> fp16 probs
__global__ void softmax_kernel(const float* __restrict__ scores, u16* __restrict__ probs) {
    __shared__ float sx[T_];
    __shared__ float red[32];
    int q = blockIdx.x % T_;
    size_t off = (size_t)blockIdx.x * T_;
    int tid = threadIdx.x;
    int n = q + 1;
    float lm = -INFINITY;
    for (int i = tid; i < n; i += blockDim.x) {
        float v = scores[off + i];
        sx[i] = v;
        lm = fmaxf(lm, v);
    }
    float gm = blockMax(lm, red);
    float lsum = 0.f;
    for (int i = tid; i < n; i += blockDim.x) {
        float e = __expf(sx[i] - gm);
        sx[i] = e;
        lsum += e;
    }
    float inv = 1.f / blockSum(lsum, red);
    for (int i = tid; i < T_; i += blockDim.x) {
        probs[off + i] = (i < n) ? f2h(sx[i] * inv) : (u16)0;
    }
}

__device__ __forceinline__ float gelu_tanh(float x) {
    return 0.5f * x * (1.f + tanhf(0.7978845608028654f * (x + 0.044715f * x * x * x)));
}

// gelu(g)*u on fp16 planes -> fp16 plane
__global__ void gelumul_kernel(const u16* __restrict__ g, const u16* __restrict__ u,
                               u16* __restrict__ o, int n4) {
    int i = blockIdx.x * blockDim.x + threadIdx.x;
    if (i >= n4) return;
    uint2 gp = reinterpret_cast<const uint2*>(g)[i];
    uint2 up = reinterpret_cast<const uint2*>(u)[i];
    float g0 = h2f((u16)(gp.x & 0xFFFF)), g1 = h2f((u16)(gp.x >> 16));
    float g2 = h2f((u16)(gp.y & 0xFFFF)), g3 = h2f((u16)(gp.y >> 16));
    float u0 = h2f((u16)(up.x & 0xFFFF)), u1 = h2f((u16)(up.x >> 16));
    float u2 = h2f((u16)(up.y & 0xFFFF)), u3 = h2f((u16)(up.y >> 16));
    u16 h0 = f2h(gelu_tanh(g0) * u0);
    u16 h1 = f2h(gelu_tanh(g1) * u1);
    u16 h2h = f2h(gelu_tanh(g2) * u2);
    u16 h3 = f2h(gelu_tanh(g3) * u3);
    uint2 pk;
    pk.x = (uint32_t)h0 | ((uint32_t)h1 << 16);
    pk.y = (uint32_t)h2h | ((uint32_t)h3 << 16);
    reinterpret_cast<uint2*>(o)[i] = pk;
}

// ===== shared MMA plumbing =====
__device__ __forceinline__ void ldsm4(uint32_t* r, uint32_t addr) {
    asm volatile("ldmatrix.sync.aligned.m8n8.x4.shared.b16 {%0,%1,%2,%3}, [%4];"
                 : "=r"(r[0]), "=r"(r[1]), "=r"(r[2]), "=r"(r[3]) : "r"(addr));
}
__device__ __forceinline__ void mma_bf(float* d, const uint32_t* a, uint32_t b0, uint32_t b1) {
    asm volatile("mma.sync.aligned.m16n8k16.row.col.f32.bf16.bf16.f32 "
                 "{%0,%1,%2,%3}, {%4,%5,%6,%7}, {%8,%9}, {%0,%1,%2,%3};"
                 : "+f"(d[0]), "+f"(d[1]), "+f"(d[2]), "+f"(d[3])
                 : "r"(a[0]), "r"(a[1]), "r"(a[2]), "r"(a[3]), "r"(b0), "r"(b1));
}
__device__ __forceinline__ void mma_fp(float* d, const uint32_t* a, uint32_t b0, uint32_t b1) {
    asm volatile("mma.sync.aligned.m16n8k16.row.col.f32.f16.f16.f32 "
                 "{%0,%1,%2,%3}, {%4,%5,%6,%7}, {%8,%9}, {%0,%1,%2,%3};"
                 : "+f"(d[0]), "+f"(d[1]), "+f"(d[2]), "+f"(d[3])
                 : "r"(a[0]), "r"(a[1]), "r"(a[2]), "r"(a[3]), "r"(b0), "r"(b1));
}
__device__ __forceinline__ void splitStoreBF(float4 v, uint32_t* hi, uint32_t* lo) {
    uint32_t hx = f2bf(v.x), hy = f2bf(v.y), hz = f2bf(v.z), hw = f2bf(v.w);
    uint32_t lx = f2bf(v.x - bf2f(hx));
    uint32_t ly = f2bf(v.y - bf2f(hy));
    uint32_t lz = f2bf(v.z - bf2f(hz));
    uint32_t lw = f2bf(v.w - bf2f(hw));
    hi[0] = hx | (hy << 16);
    hi[1] = hz | (hw << 16);
    lo[0] = lx | (ly << 16);
    lo[1] = lz | (lw << 16);
}
__device__ __forceinline__ void convStoreH(float4 v, uint32_t* hi) {
    u16 hx = f2h(v.x), hy = f2h(v.y), hz = f2h(v.z), hw = f2h(v.w);
    hi[0] = (uint32_t)hx | ((uint32_t)hy << 16);
    hi[1] = (uint32_t)hz | ((uint32_t)hw << 16);
}

constexpr int MBM = 128, MBN = 128, MBK = 32;
constexpr int MLDW = 20;

// ===== 3-pass bf16 core — q/k projections + scores =====
struct MSmem3 {
    uint32_t Ah[MBM][MLDW];
    uint32_t Al[MBM][MLDW];
    uint32_t Bh[MBN][MLDW];
    uint32_t Bl[MBN][MLDW];
};

__device__ __forceinline__ void mma_core3(
    const float* __restrict__ A, const float* __restrict__ B, float* __restrict__ C,
    int K, int lda, int ldb, int ldc, int bm, int bn, MSmem3& s)
{
    const int tid = threadIdx.x;
    const int lane = tid & 31, wid = tid >> 5;
    const int wm = wid & 3, wn = wid >> 2;

    float acc[2][8][4];
#pragma unroll
    for (int i = 0; i < 2; i++)
#pragma unroll
        for (int j = 0; j < 8; j++)
#pragma unroll
            for (int e = 0; e < 4; e++) acc[i][j][e] = 0.f;

    const int lr = tid >> 3;
    const int lc = (tid & 7) * 4;
    const int wc = (tid & 7) * 2;

    const uint32_t sb = (uint32_t)__cvta_generic_to_shared(&s);
    const uint32_t offAl = MBM * MLDW * 4;
    const uint32_t offBh = 2 * MBM * MLDW * 4;
    const uint32_t offBl = 3 * MBM * MLDW * 4;
    const int arow = wm * 32 + (lane & 15);
    const int acol = (lane >> 4) * 8;
    const int brow = wn * 64 + (lane & 7) + ((lane >> 4) << 3);
    const int bcol = ((lane >> 3) & 1) << 3;

    for (int k0 = 0; k0 < K; k0 += MBK) {
#pragma unroll
        for (int p = 0; p < 4; p++) {
            int r = lr + p * 32;
            float4 av = *reinterpret_cast<const float4*>(&A[(size_t)(bm + r) * lda + k0 + lc]);
            splitStoreBF(av, &s.Ah[r][wc], &s.Al[r][wc]);
            float4 bv = *reinterpret_cast<const float4*>(&B[(size_t)(bn + r) * ldb + k0 + lc]);
            splitStoreBF(bv, &s.Bh[r][wc], &s.Bl[r][wc]);
        }
        __syncthreads();

#pragma unroll
        for (int kk = 0; kk < 2; kk++) {
            uint32_t ah[2][4], al[2][4], bh[4][4], bl[4][4];
#pragma unroll
            for (int mf = 0; mf < 2; mf++) {
                uint32_t ao = (uint32_t)(((arow + mf * 16) * MLDW * 4) + (kk * 16 + acol) * 2);
                ldsm4(ah[mf], sb + ao);
                ldsm4(al[mf], sb + offAl + ao);
            }
#pragma unroll
            for (int np = 0; np < 4; np++) {
                uint32_t bo = (uint32_t)(((brow + np * 16) * MLDW * 4) + (kk * 16 + bcol) * 2);
                ldsm4(bh[np], sb + offBh + bo);
                ldsm4(bl[np], sb + offBl + bo);
            }
#pragma unroll
            for (int mf = 0; mf < 2; mf++) {
#pragma unroll
                for (int nf = 0; nf < 8; nf++) {
                    int np = nf >> 1;
                    int hf = (nf & 1) * 2;
                    mma_bf(acc[mf][nf], ah[mf], bh[np][hf], bh[np][hf + 1]);
                    mma_bf(acc[mf][nf], al[mf], bh[np][hf], bh[np][hf + 1]);
                    mma_bf(acc[mf][nf], ah[mf], bl[np][hf], bl[np][hf + 1]);
                }
            }
        }
        __syncthreads();
    }

#pragma unroll
    for (int mf = 0; mf < 2; mf++) {
        int row = bm + wm * 32 + mf * 16 + (lane >> 2);
#pragma unroll
        for (int nf = 0; nf < 8; nf++) {
            int col = bn + wn * 64 + nf * 8 + (lane & 3) * 2;
            *reinterpret_cast<float2*>(&C[(size_t)row * ldc + col]) =
                make_float2(acc[mf][nf][0], acc[mf][nf][1]);
            *reinterpret_cast<float2*>(&C[(size_t)(row + 8) * ldc + col]) =
                make_float2(acc[mf][nf][2], acc[mf][nf][3]);
        }
    }
}

__global__ void __launch_bounds__(256, 2)
mma_qk(const float* __restrict__ A, const float* __restrict__ wq, const float* __restrict__ wk,
       float* __restrict__ qraw, float* __restrict__ kraw) {
    __shared__ MSmem3 s;
    if (blockIdx.y < 16) {
        mma_core3(A, wq, qraw, H_, H_, H_, NH_ * HD_, blockIdx.x * MBM, blockIdx.y * MBN, s);
    } else {
        mma_core3(A, wk, kraw, H_, H_, H_, NKV_ * HD_, blockIdx.x * MBM,
                  (blockIdx.y - 16) * MBN, s);
    }
}

__global__ void __launch_bounds__(256, 2)
mma_scores(const float* __restrict__ q, const float* __restrict__ k, float* __restrict__ sc) {
    if (blockIdx.y > blockIdx.x) return;
    int z = blockIdx.z;
    int b = z >> 3, h = z & 7;
    const float* A = q + (size_t)z * T_ * HD_;
    const float* B = k + (size_t)(b * NKV_ + (h >> 2)) * T_ * HD_;
    float* C = sc + (size_t)z * T_ * T_;
    __shared__ MSmem3 s;
    mma_core3(A, B, C, HD_, HD_, HD_, T_, blockIdx.x * MBM, blockIdx.y * MBN, s);
}

// ===== 1-pass fp16 cores =====
struct MSmem1 {
    uint32_t Ah[MBM][MLDW];
    uint32_t Bh[MBN][MLDW];
};

// epilogue helper: write fp32 or fp16 output
__device__ __forceinline__ void epi_store(
    float* Cf, u16* Ch, size_t idx, float v0, float v1) {
    if (Ch) {
        *reinterpret_cast<uint32_t*>(&Ch[idx]) =
            (uint32_t)f2h(v0) | ((uint32_t)f2h(v1) << 16);
    } else {
        *reinterpret_cast<float2*>(&Cf[idx]) = make_float2(v0, v1);
    }
}

// pipelined fp32-A core (laurel2, v) — fp32 out
__device__ __forceinline__ void mma_core1(
    const float* __restrict__ A, const float* __restrict__ B, float* __restrict__ C,
    int K, int lda, int ldb, int ldc, int bm, int bn, MSmem1 (&s)[2])
{
    const int tid = threadIdx.x;
    const int lane = tid & 31, wid = tid >> 5;
    const int wm = wid & 3, wn = wid >> 2;

    float acc[2][8][4];
#pragma unroll
    for (int i = 0; i < 2; i++)
#pragma unroll
        for (int j = 0; j < 8; j++)
#pragma unroll
            for (int e = 0; e < 4; e++) acc[i][j][e] = 0.f;

    const int lr = tid >> 3;
    const int lc = (tid & 7) * 4;
    const int wc = (tid & 7) * 2;

    const uint32_t sb0 = (uint32_t)__cvta_generic_to_shared(&s[0]);
    const uint32_t stageBytes = (uint32_t)sizeof(MSmem1);
    const uint32_t offBh = MBM * MLDW * 4;
    const int arow = wm * 32 + (lane & 15);
    const int acol = (lane >> 4) * 8;
    const int brow = wn * 64 + (lane & 7) + ((lane >> 4) << 3);
    const int bcol = ((lane >> 3) & 1) << 3;

    float4 av[4], bv[4];
#pragma unroll
    for (int p = 0; p < 4; p++) {
        int r = lr + p * 32;
        av[p] = *reinterpret_cast<const float4*>(&A[(size_t)(bm + r) * lda + lc]);
        bv[p] = *reinterpret_cast<const float4*>(&B[(size_t)(bn + r) * ldb + lc]);
    }
#pragma unroll
    for (int p = 0; p < 4; p++) {
        int r = lr + p * 32;
        convStoreH(av[p], &s[0].Ah[r][wc]);
        convStoreH(bv[p], &s[0].Bh[r][wc]);
    }
    __syncthreads();

    const int KT = K / MBK;
    for (int kt = 0; kt < KT; kt++) {
        const int cur = kt & 1;
        const uint32_t sb = sb0 + (uint32_t)cur * stageBytes;
        if (kt + 1 < KT) {
            int k0 = (kt + 1) * MBK;
#pragma unroll
            for (int p = 0; p < 4; p++) {
                int r = lr + p * 32;
                av[p] = *reinterpret_cast<const float4*>(&A[(size_t)(bm + r) * lda + k0 + lc]);
                bv[p] = *reinterpret_cast<const float4*>(&B[(size_t)(bn + r) * ldb + k0 + lc]);
            }
        }
#pragma unroll
        for (int kk = 0; kk < 2; kk++) {
            uint32_t ah[2][4], bh[4][4];
#pragma unroll
            for (int mf = 0; mf < 2; mf++) {
                uint32_t ao = (uint32_t)(((arow + mf * 16) * MLDW * 4) + (kk * 16 + acol) * 2);
                ldsm4(ah[mf], sb + ao);
            }
#pragma unroll
            for (int np = 0; np < 4; np++) {
                uint32_t bo = (uint32_t)(((brow + np * 16) * MLDW * 4) + (kk * 16 + bcol) * 2);
                ldsm4(bh[np], sb + offBh + bo);
            }
#pragma unroll
            for (int mf = 0; mf < 2; mf++) {
#pragma unroll
                for (int nf = 0; nf < 8; nf++) {
                    int np = nf >> 1;
                    int hf = (nf & 1) * 2;
                    mma_fp(acc[mf][nf], ah[mf], bh[np][hf], bh[np][hf + 1]);
                }
            }
        }
        if (kt + 1 < KT) {
            MSmem1& sn = s[cur ^ 1];
#pragma unroll
            for (int p = 0; p < 4; p++) {
                int r = lr + p * 32;
                convStoreH(av[p], &sn.Ah[r][wc]);
                convStoreH(bv[p], &sn.Bh[r][wc]);
            }
        }
        __syncthreads();
    }

#pragma unroll
    for (int mf = 0; mf < 2; mf++) {
        int row = bm + wm * 32 + mf * 16 + (lane >> 2);
#pragma unroll
        for (int nf = 0; nf < 8; nf++) {
            int col = bn + wn * 64 + nf * 8 + (lane & 3) * 2;
            *reinterpret_cast<float2*>(&C[(size_t)row * ldc + col]) =
                make_float2(acc[mf][nf][0], acc[mf][nf][1]);
            *reinterpret_cast<float2*>(&C[(size_t)(row + 8) * ldc + col]) =
                make_float2(acc[mf][nf][2], acc[mf][nf][3]);
        }
    }
}

// pipelined u16-A core; dual output (Cf fp32 | Ch fp16)
__device__ __forceinline__ void mma_core1h(
    const u16* __restrict__ A, const float* __restrict__ B,
    float* __restrict__ Cf, u16* __restrict__ Ch,
    int K, int lda, int ldb, int ldc, int bm, int bn, MSmem1 (&s)[2])
{
    const int tid = threadIdx.x;
    const int lane = tid & 31, wid = tid >> 5;
    const int wm = wid & 3, wn = wid >> 2;

    float acc[2][8][4];
#pragma unroll
    for (int i = 0; i < 2; i++)
#pragma unroll
        for (int j = 0; j < 8; j++)
#pragma unroll
            for (int e = 0; e < 4; e++) acc[i][j][e] = 0.f;

    const int lr = tid >> 3;
    const int lc = (tid & 7) * 4;
    const int wc = (tid & 7) * 2;

    const uint32_t sb0 = (uint32_t)__cvta_generic_to_shared(&s[0]);
    const uint32_t stageBytes = (uint32_t)sizeof(MSmem1);
    const uint32_t offBh = MBM * MLDW * 4;
    const int arow = wm * 32 + (lane & 15);
    const int acol = (lane >> 4) * 8;
    const int brow = wn * 64 + (lane & 7) + ((lane >> 4) << 3);
    const int bcol = ((lane >> 3) & 1) << 3;

    uint2 av[4];
    float4 bv[4];
#pragma unroll
    for (int p = 0; p < 4; p++) {
        int r = lr + p * 32;
        av[p] = *reinterpret_cast<const uint2*>(&A[(size_t)(bm + r) * lda + lc]);
        bv[p] = *reinterpret_cast<const float4*>(&B[(size_t)(bn + r) * ldb + lc]);
    }
#pragma unroll
    for (int p = 0; p < 4; p++) {
        int r = lr + p * 32;
        s[0].Ah[r][wc] = av[p].x;
        s[0].Ah[r][wc + 1] = av[p].y;
        convStoreH(bv[p], &s[0].Bh[r][wc]);
    }
    __syncthreads();

    const int KT = K / MBK;
    for (int kt = 0; kt < KT; kt++) {
        const int cur = kt & 1;
        const uint32_t sb = sb0 + (uint32_t)cur * stageBytes;
        if (kt + 1 < KT) {
            int k0 = (kt + 1) * MBK;
#pragma unroll
            for (int p = 0; p < 4; p++) {
                int r = lr + p * 32;
                av[p] = *reinterpret_cast<const uint2*>(&A[(size_t)(bm + r) * lda + k0 + lc]);
                bv[p] = *reinterpret_cast<const float4*>(&B[(size_t)(bn + r) * ldb + k0 + lc]);
            }
        }
#pragma unroll
        for (int kk = 0; kk < 2; kk++) {
            uint32_t ah[2][4], bh[4][4];
#pragma unroll
            for (int mf = 0; mf < 2; mf++) {
                uint32_t ao = (uint32_t)(((arow + mf * 16) * MLDW * 4) + (kk * 16 + acol) * 2);
                ldsm4(ah[mf], sb + ao);
            }
#pragma unroll
            for (int np = 0; np < 4; np++) {
                uint32_t bo = (uint32_t)(((brow + np * 16) * MLDW * 4) + (kk * 16 + bcol) * 2);
                ldsm4(bh[np], sb + offBh + bo);
            }
#pragma unroll
            for (int mf = 0; mf < 2; mf++) {
#pragma unroll
                for (int nf = 0; nf < 8; nf++) {
                    int np = nf >> 1;
                    int hf = (nf & 1) * 2;
                    mma_fp(acc[mf][nf], ah[mf], bh[np][hf], bh[np][hf + 1]);
                }
            }
        }
        if (kt + 1 < KT) {
            MSmem1& sn = s[cur ^ 1];
#pragma unroll
            for (int p = 0; p < 4; p++) {
                int r = lr + p * 32;
                sn.Ah[r][wc] = av[p].x;
                sn.Ah[r][wc + 1] = av[p].y;
                convStoreH(bv[p], &sn.Bh[r][wc]);
            }
        }
        __syncthreads();
    }

#pragma unroll
    for (int mf = 0; mf < 2; mf++) {
        int row = bm + wm * 32 + mf * 16 + (lane >> 2);
#pragma unroll
        for (int nf = 0; nf < 8; nf++) {
            int col = bn + wn * 64 + nf * 8 + (lane & 3) * 2;
            epi_store(Cf, Ch, (size_t)row * ldc + col, acc[mf][nf][0], acc[mf][nf][1]);
            epi_store(Cf, Ch, (size_t)(row + 8) * ldc + col, acc[mf][nf][2], acc[mf][nf][3]);
        }
    }
}

__global__ void __launch_bounds__(256, 2)
mma_nt1(const float* __restrict__ A, const float* __restrict__ B, float* __restrict__ C,
        int K, int lda, int ldb, int ldc) {
    __shared__ MSmem1 s[2];
    mma_core1(A, B, C, K, lda, ldb, ldc, blockIdx.x * MBM, blockIdx.y * MBN, s);
}

// u16-A GEMM, fp32 out (wo, down)
__global__ void __launch_bounds__(256, 2)
mma_nt1h(const u16* __restrict__ A, const float* __restrict__ B, float* __restrict__ C,
         int K, int lda, int ldb, int ldc) {
    __shared__ MSmem1 s[2];
    mma_core1h(A, B, C, (u16*)0, K, lda, ldb, ldc, blockIdx.x * MBM, blockIdx.y * MBN, s);
}

// gate+up GEMM: u16 A (hnH), u16 outputs
__global__ void __launch_bounds__(256, 2)
mma_gateup(const u16* __restrict__ A, const float* __restrict__ gw,
           const float* __restrict__ uw, u16* __restrict__ gateH, u16* __restrict__ upH) {
    __shared__ MSmem1 s[2];
    if (blockIdx.y < 64) {
        mma_core1h(A, gw, (float*)0, gateH, H_, H_, H_, FF_,
                   blockIdx.x * MBM, blockIdx.y * MBN, s);
    } else {
        mma_core1h(A, uw, (float*)0, upH, H_, H_, H_, FF_,
                   blockIdx.x * MBM, (blockIdx.y - 64) * MBN, s);
    }
}

// attnv: u16 probs A, u16 fp16 output (attnout plane)
__global__ void __launch_bounds__(256, 2)
mma_attnv(const u16* __restrict__ p, const float* __restrict__ vT, u16* __restrict__ oH) {
    int z = blockIdx.z;
    int b = z >> 3, h = z & 7;
    const u16* A = p + (size_t)z * T_ * T_;
    const float* B = vT + (size_t)(b * NKV_ + (h >> 2)) * HD_ * T_;
    u16* C = oH + (size_t)b * T_ * H_ + (size_t)h * HD_;
    int bm = blockIdx.x * MBM;
    __shared__ MSmem1 s[2];
    mma_core1h(A, B, (float*)0, C, bm + MBM, T_, T_, H_, bm, blockIdx.y * MBN, s);
}

// laurel1: split-K x8
__global__ void __launch_bounds__(256)
laurel1_kernel(const float* __restrict__ A, const float* __restrict__ B, float* __restrict__ P) {
    __shared__ float Bs[64][65];
    __shared__ float As[32][65];
    int tid = threadIdx.x;
    int bm = blockIdx.x * 32;
    int ks = blockIdx.y;
    int kbeg = ks * (H_ / 8), kend = kbeg + H_ / 8;
    float acc0[4] = {0.f, 0.f, 0.f, 0.f};
    float acc1[4] = {0.f, 0.f, 0.f, 0.f};
    int tn = tid & 15;
    int tr = tid >> 4;
    for (int k0 = kbeg; k0 < kend; k0 += 64) {
        for (int i = tid; i < 64 * 64; i += 256) {
            int n = i >> 6, kk = i & 63;
            Bs[n][kk] = B[(size_t)n * H_ + k0 + kk];
        }
        for (int i = tid; i < 32 * 64; i += 256) {
            int r = i >> 6, kk = i & 63;
            As[r][kk] = A[(size_t)(bm + r) * H_ + k0 + kk];
        }
        __syncthreads();
#pragma unroll 8
        for (int kk = 0; kk < 64; kk++) {
            float a0 = As[tr][kk], a1 = As[tr + 16][kk];
#pragma unroll
            for (int j = 0; j < 4; j++) {
                float bv = Bs[tn * 4 + j][kk];
                acc0[j] = fmaf(a0, bv, acc0[j]);
                acc1[j] = fmaf(a1, bv, acc1[j]);
            }
        }
        __syncthreads();
    }
#pragma unroll
    for (int j = 0; j < 4; j++) {
        P[((size_t)ks * BT_ + bm + tr) * LR_ + tn * 4 + j] = acc0[j];
        P[((size_t)ks * BT_ + bm + tr + 16) * LR_ + tn * 4 + j] = acc1[j];
    }
}

__global__ void laurel1_reduce(const float* __restrict__ P, float* __restrict__ out) {
    int i = blockIdx.x * blockDim.x + threadIdx.x;
    if (i >= BT_ * LR_) return;
    float s = 0.f;
#pragma unroll
    for (int k = 0; k < 8; k++) s += P[(size_t)k * BT_ * LR_ + i];
    out[i] = s;
}

// ---------- lazy side stream + events ----------
static cudaStream_t g_s1 = 0;
static cudaEvent_t g_ev0 = 0, g_evL = 0;

extern "C" void kernel_launch(void* const* d_in, const int* in_sizes, int n_in,
                              void* d_out, int out_size) {
    const float* hs    = (const float*)d_in[0];
    const float* cosb  = (const float*)d_in[1];
    const float* sinb  = (const float*)d_in[2];
    const float* wq    = (const float*)d_in[3];
    const float* wk    = (const float*)d_in[4];
    const float* wv    = (const float*)d_in[5];
    const float* wo    = (const float*)d_in[6];
    const float* qnw   = (const float*)d_in[7];
    const float* knw   = (const float*)d_in[8];
    const float* in_ln = (const float*)d_in[9];
    const float* pa_ln = (const float*)d_in[10];
    const float* pf_ln = (const float*)d_in[11];
    const float* pw_ln = (const float*)d_in[12];
    const float* gatew = (const float*)d_in[13];
    const float* upw   = (const float*)d_in[14];
    const float* downw = (const float*)d_in[15];
    const float* llw   = (const float*)d_in[16];
    const float* lrw   = (const float*)d_in[17];
    const float* lnw   = (const float*)d_in[18];
    const float* rnw   = (const float*)d_in[19];
    const float* rw    = (const float*)d_in[20];
    const float* pcw   = (const float*)d_in[21];
    const float* ccw   = (const float*)d_in[22];
    const float* cscal = (const float*)d_in[23];
    float* out = (float*)d_out;

    Scratch* S = 0;
    cudaGetSymbolAddress((void**)&S, g_scratch);

    if (!g_s1) {
        cudaStreamCreateWithFlags(&g_s1, cudaStreamNonBlocking);
        cudaEventCreateWithFlags(&g_ev0, cudaEventDisableTiming);
        cudaEventCreateWithFlags(&g_evL, cudaEventDisableTiming);
    }

    fused_pre<<<BT_, 256>>>(hs, rnw, rw, pcw, in_ln, S->pred0, S->cfg, S->xnorm);

    // fork: laurel chain + v chain on side stream
    cudaEventRecord(g_ev0, 0);
    cudaStreamWaitEvent(g_s1, g_ev0, 0);
    laurel1_kernel<<<dim3(BT_ / 32, 8), 256, 0, g_s1>>>(S->xnorm, llw, S->lrpart);
    laurel1_reduce<<<(BT_ * LR_ + 255) / 256, 256, 0, g_s1>>>(S->lrpart, S->lrbuf);
    mma_nt1<<<dim3(16, 16), 256, 0, g_s1>>>(S->lrbuf, lrw, S->laurel, LR_, LR_, LR_, H_);
    ln_kernel<<<BT_, 256, 0, g_s1>>>(S->laurel, lnw, S->xnorm, (const float*)0, 1.f, S->laurel);
    mma_nt1<<<dim3(16, 4), 256, 0, g_s1>>>(S->xnorm, wv, S->vraw, H_, H_, H_, NKV_ * HD_);
    qkvpost_kernel<<<BT_ * NKV_, 256, 0, g_s1>>>(S->vraw, (const float*)0, cosb, sinb,
                                                 S->vT, NKV_, 0, 1);
    cudaEventRecord(g_evL, g_s1);

    // main: q+k projections (combined), post, scores, softmax
    mma_qk<<<dim3(16, 20), 256>>>(S->xnorm, wq, wk, S->qraw, S->kraw);
    qkvpost_qk<<<BT_ * (NH_ + NKV_), 256>>>(S->qraw, S->kraw, qnw, knw, cosb, sinb, S->q, S->k);
    mma_scores<<<dim3(8, 8, B_ * NH_), 256>>>(S->q, S->k, S->scores);
    softmax_kernel<<<B_ * NH_ * T_, 256>>>(S->scores, S->probs);

    cudaStreamWaitEvent(0, g_evL, 0);
    mma_attnv<<<dim3(8, 2, B_ * NH_), 256>>>(S->probs, S->vT, S->aoH);
    mma_nt1h<<<dim3(16, 16), 256>>>(S->aoH, wo, S->attnproj,
                                    NH_ * HD_, NH_ * HD_, NH_ * HD_, H_);

    fused_mid<<<BT_, 256>>>(S->attnproj, pa_ln, S->pred0, S->laurel, pf_ln,
                            S->attnlaurel, S->hnH);

    mma_gateup<<<dim3(16, 128), 256>>>(S->hnH, gatew, upw, S->gateH, S->upH);

    int n4 = (int)(FFSZ_ / 4);
    gelumul_kernel<<<(n4 + 255) / 256, 256>>>(S->gateH, S->upH, S->gp, n4);
    mma_nt1h<<<dim3(16, 16), 256>>>(S->gp, downw, S->ffw, FF_, FF_, FF_, H_);

    fused_post<<<BT_, 256>>>(S->ffw, pw_ln, S->attnlaurel, rnw, rw, ccw, cscal,
                             hs, S->cfg, out);

    (void)in_sizes; (void)n_in; (void)out_size;
}

// round 16
// speedup vs baseline: 1.2961x; 1.0135x over previous
#include <cuda_runtime.h>
#include <cstdint>
#include <cstddef>
#include <math.h>

typedef unsigned short u16;

constexpr int B_ = 2, T_ = 1024, H_ = 2048, NH_ = 8, NKV_ = 2, HD_ = 256;
constexpr int FF_ = 8192, LR_ = 64;
constexpr int BT_ = B_ * T_;
constexpr size_t BTH_ = (size_t)BT_ * H_;
constexpr size_t SCSZ_ = (size_t)B_ * NH_ * T_ * T_;
constexpr size_t FFSZ_ = (size_t)BT_ * FF_;
constexpr float EPS_ = 1e-6f;

struct Scratch {
    float pred0[BTH_];
    float cfg[BT_ * 16];
    float xnorm[BTH_];
    float lrpart[8 * BT_ * LR_];
    float lrbuf[BT_ * LR_];
    float laurel[BTH_];
    float qraw[BTH_];
    float kraw[(size_t)BT_ * NKV_ * HD_];
    float vraw[(size_t)BT_ * NKV_ * HD_];
    float q[BTH_];
    float k[(size_t)BT_ * NKV_ * HD_];
    float vT[(size_t)BT_ * NKV_ * HD_];
    float scores[SCSZ_];
    u16 probs[SCSZ_];
    u16 aoH[BTH_];
    float attnproj[BTH_];
    float attnlaurel[BTH_];
    u16 hnH[BTH_];
    u16 gateH[FFSZ_];
    u16 upH[FFSZ_];
    u16 gp[FFSZ_];
    float ffw[BTH_];
};
__device__ Scratch g_scratch;

// ---------- bf16 / fp16 bit helpers ----------
__device__ __forceinline__ uint32_t f2bf(float x) {
    uint32_t u = __float_as_uint(x);
    return (u + 0x7FFFu + ((u >> 16) & 1u)) >> 16;
}
__device__ __forceinline__ float bf2f(uint32_t b) {
    return __uint_as_float(b << 16);
}
__device__ __forceinline__ u16 f2h(float x) {
    u16 h;
    asm("cvt.rn.f16.f32 %0, %1;" : "=h"(h) : "f"(x));
    return h;
}
__device__ __forceinline__ float h2f(u16 h) {
    float f;
    asm("cvt.f32.f16 %0, %1;" : "=f"(f) : "h"(h));
    return f;
}

// ---------- reductions ----------
__device__ __forceinline__ float warpSum(float v) {
#pragma unroll
    for (int o = 16; o > 0; o >>= 1) v += __shfl_xor_sync(0xffffffffu, v, o);
    return v;
}
__device__ __forceinline__ float warpMax(float v) {
#pragma unroll
    for (int o = 16; o > 0; o >>= 1) v = fmaxf(v, __shfl_xor_sync(0xffffffffu, v, o));
    return v;
}
__device__ __forceinline__ float blockSum(float v, float* red) {
    v = warpSum(v);
    int lane = threadIdx.x & 31, w = threadIdx.x >> 5;
    if (lane == 0) red[w] = v;
    __syncthreads();
    int nw = (blockDim.x + 31) >> 5;
    float r = (lane < nw) ? red[lane] : 0.f;
    if (w == 0) {
        r = warpSum(r);
        if (lane == 0) red[0] = r;
    }
    __syncthreads();
    r = red[0];
    __syncthreads();
    return r;
}

// ===== fused per-token kernels =====
__global__ void fused_pre(const float* __restrict__ hs, const float* __restrict__ rnw,
                          const float* __restrict__ rw, const float* __restrict__ pcw,
                          const float* __restrict__ inw,
                          float* __restrict__ pred0, float* __restrict__ cfg,
                          float* __restrict__ xnorm) {
    __shared__ float sx[H_];
    __shared__ float px[H_];
    __shared__ float red[32];
    __shared__ float cf[16];
    size_t off = (size_t)blockIdx.x * H_;
    int tid = threadIdx.x;

    float ls = 0.f;
    for (int i = tid; i < H_; i += blockDim.x) {
        float v = hs[off + i];
        sx[i] = v;
        ls += v;
    }
    float mean = blockSum(ls, red) * (1.f / H_);
    float lv = 0.f;
    for (int i = tid; i < H_; i += blockDim.x) {
        float d = sx[i] - mean;
        lv += d * d;
    }
    float rs = rsqrtf(blockSum(lv, red) * (1.f / H_) + EPS_);

    float a0 = 0.f, a1 = 0.f, a2 = 0.f, a3 = 0.f;
    for (int i = tid; i < H_; i += blockDim.x) {
        float r = (sx[i] - mean) * rs * rnw[i] * (1.f / H_);
        a0 += r * rw[i];
        a1 += r * rw[H_ + i];
        a2 += r * rw[2 * H_ + i];
        a3 += r * rw[3 * H_ + i];
    }
    float t0 = blockSum(a0, red);
    float t1 = blockSum(a1, red);
    float t2 = blockSum(a2, red);
    float t3 = blockSum(a3, red);
    if (tid < 16) {
        float m0 = tanhf(t0), m1 = tanhf(t1), m2 = tanhf(t2), m3 = tanhf(t3);
        float c = m0 * pcw[tid * 4] + m1 * pcw[tid * 4 + 1]
                + m2 * pcw[tid * 4 + 2] + m3 * pcw[tid * 4 + 3];
        cf[tid] = c;
        cfg[(size_t)blockIdx.x * 16 + tid] = c;
    }
    __syncthreads();

    float ps = 0.f;
    for (int i = tid; i < H_; i += blockDim.x) {
        float h0 = sx[i];
        float h1 = hs[BTH_ + off + i];
        float h2 = hs[2 * BTH_ + off + i];
        float h3 = hs[3 * BTH_ + off + i];
        float p0 = h0 + h0 * cf[0] + h1 * cf[1] + h2 * cf[2] + h3 * cf[3];
        pred0[off + i] = p0;
        px[i] = p0;
        ps += p0;
    }
    float mean2 = blockSum(ps, red) * (1.f / H_);
    float lv2 = 0.f;
    for (int i = tid; i < H_; i += blockDim.x) {
        float d = px[i] - mean2;
        lv2 += d * d;
    }
    float rs2 = rsqrtf(blockSum(lv2, red) * (1.f / H_) + EPS_);
    for (int i = tid; i < H_; i += blockDim.x) {
        xnorm[off + i] = (px[i] - mean2) * rs2 * inw[i];
    }
}

__global__ void fused_mid(const float* __restrict__ ap, const float* __restrict__ paw,
                          const float* __restrict__ pred0, const float* __restrict__ laurel,
                          const float* __restrict__ pfw,
                          float* __restrict__ attnlaurel, u16* __restrict__ hnH) {
    __shared__ float sx[H_];
    __shared__ float ax[H_];
    __shared__ float red[32];
    size_t off = (size_t)blockIdx.x * H_;
    int tid = threadIdx.x;

    float ls = 0.f;
    for (int i = tid; i < H_; i += blockDim.x) {
        float v = ap[off + i];
        sx[i] = v;
        ls += v;
    }
    float mean = blockSum(ls, red) * (1.f / H_);
    float lv = 0.f;
    for (int i = tid; i < H_; i += blockDim.x) {
        float d = sx[i] - mean;
        lv += d * d;
    }
    float rs = rsqrtf(blockSum(lv, red) * (1.f / H_) + EPS_);

    float ls2 = 0.f;
    for (int i = tid; i < H_; i += blockDim.x) {
        float v = (sx[i] - mean) * rs * paw[i] + pred0[off + i] + laurel[off + i];
        v *= 0.7071067811865476f;
        ax[i] = v;
        attnlaurel[off + i] = v;
        ls2 += v;
    }
    float mean2 = blockSum(ls2, red) * (1.f / H_);
    float lv2 = 0.f;
    for (int i = tid; i < H_; i += blockDim.x) {
        float d = ax[i] - mean2;
        lv2 += d * d;
    }
    float rs2 = rsqrtf(blockSum(lv2, red) * (1.f / H_) + EPS_);
    for (int i = tid; i < H_; i += blockDim.x) {
        hnH[off + i] = f2h((ax[i] - mean2) * rs2 * pfw[i]);
    }
}

__global__ void fused_post(const float* __restrict__ ffw, const float* __restrict__ pww,
                           const float* __restrict__ attnlaurel,
                           const float* __restrict__ rnw, const float* __restrict__ rw,
                           const float* __restrict__ ccw, const float* __restrict__ cscale,
                           const float* __restrict__ hs, const float* __restrict__ cfg,
                           float* __restrict__ out) {
    __shared__ float sx[H_];
    __shared__ float ax[H_];
    __shared__ float red[32];
    __shared__ float cf[16];
    size_t off = (size_t)blockIdx.x * H_;
    int tid = threadIdx.x;

    if (tid < 16) cf[tid] = cfg[(size_t)blockIdx.x * 16 + tid];

    float ls = 0.f;
    for (int i = tid; i < H_; i += blockDim.x) {
        float v = ffw[off + i];
        sx[i] = v;
        ls += v;
    }
    float mean = blockSum(ls, red) * (1.f / H_);
    float lv = 0.f;
    for (int i = tid; i < H_; i += blockDim.x) {
        float d = sx[i] - mean;
        lv += d * d;
    }
    float rs = rsqrtf(blockSum(lv, red) * (1.f / H_) + EPS_);

    float as = 0.f;
    for (int i = tid; i < H_; i += blockDim.x) {
        float v = (sx[i] - mean) * rs * pww[i] + attnlaurel[off + i];
        ax[i] = v;
        as += v;
    }
    float mean2 = blockSum(as, red) * (1.f / H_);
    float lv2 = 0.f;
    for (int i = tid; i < H_; i += blockDim.x) {
        float d = ax[i] - mean2;
        lv2 += d * d;
    }
    float rs2 = rsqrtf(blockSum(lv2, red) * (1.f / H_) + EPS_);
    float a0 = 0.f, a1 = 0.f, a2 = 0.f, a3 = 0.f;
    for (int i = tid; i < H_; i += blockDim.x) {
        float r = (ax[i] - mean2) * rs2 * rnw[i] * (1.f / H_);
        a0 += r * rw[i];
        a1 += r * rw[H_ + i];
        a2 += r * rw[2 * H_ + i];
        a3 += r * rw[3 * H_ + i];
    }
    float m0 = tanhf(blockSum(a0, red));
    float m1 = tanhf(blockSum(a1, red));
    float m2 = tanhf(blockSum(a2, red));
    float m3 = tanhf(blockSum(a3, red));
    float cc0 = 1.f + m0 * ccw[0]  + m1 * ccw[1]  + m2 * ccw[2]  + m3 * ccw[3];
    float cc1 = 1.f + m0 * ccw[4]  + m1 * ccw[5]  + m2 * ccw[6]  + m3 * ccw[7];
    float cc2 = 1.f + m0 * ccw[8]  + m1 * ccw[9]  + m2 * ccw[10] + m3 * ccw[11];
    float cc3 = 1.f + m0 * ccw[12] + m1 * ccw[13] + m2 * ccw[14] + m3 * ccw[15];

    for (int f = tid; f < H_; f += blockDim.x) {
        float h0 = hs[off + f];
        float h1 = hs[BTH_ + off + f];
        float h2 = hs[2 * BTH_ + off + f];
        float h3 = hs[3 * BTH_ + off + f];
        float p0 = h0 + h0 * cf[0]  + h1 * cf[1]  + h2 * cf[2]  + h3 * cf[3];
        float p1 = h1 + h0 * cf[4]  + h1 * cf[5]  + h2 * cf[6]  + h3 * cf[7];
        float p2 = h2 + h0 * cf[8]  + h1 * cf[9]  + h2 * cf[10] + h3 * cf[11];
        float p3 = h3 + h0 * cf[12] + h1 * cf[13] + h2 * cf[14] + h3 * cf[15];
        float inno = ax[f] - p0;
        out[off + f]            = (inno * cc0 + p0) * cscale[f];
        out[BTH_ + off + f]     = inno * cc1 + p1;
        out[2 * BTH_ + off + f] = inno * cc2 + p2;
        out[3 * BTH_ + off + f] = inno * cc3 + p3;
    }
}

// ---------- remaining elementwise ----------
__global__ void ln_kernel(const float* __restrict__ a, const float* __restrict__ w,
                          const float* __restrict__ add1, const float* __restrict__ add2,
                          float scale, float* __restrict__ dst) {
    __shared__ float sx[H_];
    __shared__ float red[32];
    size_t off = (size_t)blockIdx.x * H_;
    int tid = threadIdx.x;
    float ls = 0.f;
    for (int i = tid; i < H_; i += blockDim.x) {
        float v = a[off + i];
        sx[i] = v;
        ls += v;
    }
    float mean = blockSum(ls, red) * (1.f / H_);
    float lv = 0.f;
    for (int i = tid; i < H_; i += blockDim.x) {
        float d = sx[i] - mean;
        lv += d * d;
    }
    float var = blockSum(lv, red) * (1.f / H_);
    float rs = rsqrtf(var + EPS_);
    for (int i = tid; i < H_; i += blockDim.x) {
        float v = (sx[i] - mean) * rs * w[i];
        if (add1) v += add1[off + i];
        if (add2) v += add2[off + i];
        dst[off + i] = v * scale;
    }
}

__device__ __forceinline__ void qkvpost_body(
    const float* __restrict__ raw, const float* __restrict__ nw,
    const float* __restrict__ cosb, const float* __restrict__ sinb,
    float* __restrict__ out, int nheads, int do_rope, int trans, int idx) {
    __shared__ float sx[HD_];
    __shared__ float red[32];
    int h = idx % nheads;
    int bt = idx / nheads;
    int t = bt % T_, b = bt / T_;
    int d = threadIdx.x;
    float v = raw[(size_t)bt * nheads * HD_ + h * HD_ + d];
    float mean = blockSum(v, red) * (1.f / HD_);
    float c = v - mean;
    float var = blockSum(c * c, red) * (1.f / HD_);
    float ln = c * rsqrtf(var + EPS_) * (nw ? nw[d] : 1.f);
    sx[d] = ln;
    __syncthreads();
    float o = ln;
    if (do_rope) {
        float cs = cosb[(size_t)bt * HD_ + d];
        float sn = sinb[(size_t)bt * HD_ + d];
        float rot = (d < 128) ? -sx[d + 128] : sx[d - 128];
        o = ln * cs + rot * sn;
    }
    if (trans) {
        out[((size_t)(b * nheads + h) * HD_ + d) * T_ + t] = o;
    } else {
        out[((size_t)(b * nheads + h) * T_ + t) * HD_ + d] = o;
    }
}

__global__ void qkvpost_kernel(const float* __restrict__ raw, const float* __restrict__ nw,
                               const float* __restrict__ cosb, const float* __restrict__ sinb,
                               float* __restrict__ out, int nheads, int do_rope, int trans) {
    qkvpost_body(raw, nw, cosb, sinb, out, nheads, do_rope, trans, blockIdx.x);
}

__global__ void qkvpost_qk(const float* __restrict__ qraw, const float* __restrict__ kraw,
                           const float* __restrict__ qnw, const float* __restrict__ knw,
                           const float* __restrict__ cosb, const float* __restrict__ sinb,
                           float* __restrict__ q, float* __restrict__ k) {
    int idx = blockIdx.x;
    if (idx < BT_ * NH_) {
        qkvpost_body(qraw, qnw, cosb, sinb, q, NH_, 1, 0, idx);
    } else {
        qkvpost_body(kraw, knw, cosb, sinb, k, NKV_, 1, 0, idx - BT_ * NH_);
    }
}

// causal softmax, warp-per-row (8 rows/block), fp16 probs out.
// scores/probs pointers are pre-offset to the chunk base (chunk = whole heads,
// so local row % T_ still gives the query position).
__global__ void softmax_kernel(const float* __restrict__ scores, u16* __restrict__ probs) {
    __shared__ float sx[8][T_];
    int wid = threadIdx.x >> 5;
    int lane = threadIdx.x & 31;
    int row = blockIdx.x * 8 + wid;
    int q = row % T_;
    size_t off = (size_t)row * T_;
    int n = q + 1;
    float* srow = sx[wid];
    float lm = -INFINITY;
    for (int i = lane; i < n; i += 32) {
        float v = scores[off + i];
        srow[i] = v;
        lm = fmaxf(lm, v);
    }
    float gm = warpMax(lm);
    float ls = 0.f;
    for (int i = lane; i < n; i += 32) {
        float e = __expf(srow[i] - gm);
        srow[i] = e;
        ls += e;
    }
    float inv = 1.f / warpSum(ls);
    for (int i = lane; i < T_; i += 32) {
        probs[off + i] = (i < n) ? f2h(srow[i] * inv) : (u16)0;
    }
}

__device__ __forceinline__ float gelu_tanh(float x) {
    return 0.5f * x * (1.f + tanhf(0.7978845608028654f * (x + 0.044715f * x * x * x)));
}

// gelu(g)*u on fp16 planes -> fp16 plane
__global__ void gelumul_kernel(const u16* __restrict__ g, const u16* __restrict__ u,
                               u16* __restrict__ o, int n4) {
    int i = blockIdx.x * blockDim.x + threadIdx.x;
    if (i >= n4) return;
    uint2 gp = reinterpret_cast<const uint2*>(g)[i];
    uint2 up = reinterpret_cast<const uint2*>(u)[i];
    float g0 = h2f((u16)(gp.x & 0xFFFF)), g1 = h2f((u16)(gp.x >> 16));
    float g2 = h2f((u16)(gp.y & 0xFFFF)), g3 = h2f((u16)(gp.y >> 16));
    float u0 = h2f((u16)(up.x & 0xFFFF)), u1 = h2f((u16)(up.x >> 16));
    float u2 = h2f((u16)(up.y & 0xFFFF)), u3 = h2f((u16)(up.y >> 16));
    u16 h0 = f2h(gelu_tanh(g0) * u0);
    u16 h1 = f2h(gelu_tanh(g1) * u1);
    u16 h2h = f2h(gelu_tanh(g2) * u2);
    u16 h3 = f2h(gelu_tanh(g3) * u3);
    uint2 pk;
    pk.x = (uint32_t)h0 | ((uint32_t)h1 << 16);
    pk.y = (uint32_t)h2h | ((uint32_t)h3 << 16);
    reinterpret_cast<uint2*>(o)[i] = pk;
}

// ===== shared MMA plumbing =====
__device__ __forceinline__ void ldsm4(uint32_t* r, uint32_t addr) {
    asm volatile("ldmatrix.sync.aligned.m8n8.x4.shared.b16 {%0,%1,%2,%3}, [%4];"
                 : "=r"(r[0]), "=r"(r[1]), "=r"(r[2]), "=r"(r[3]) : "r"(addr));
}
__device__ __forceinline__ void mma_bf(float* d, const uint32_t* a, uint32_t b0, uint32_t b1) {
    asm volatile("mma.sync.aligned.m16n8k16.row.col.f32.bf16.bf16.f32 "
                 "{%0,%1,%2,%3}, {%4,%5,%6,%7}, {%8,%9}, {%0,%1,%2,%3};"
                 : "+f"(d[0]), "+f"(d[1]), "+f"(d[2]), "+f"(d[3])
                 : "r"(a[0]), "r"(a[1]), "r"(a[2]), "r"(a[3]), "r"(b0), "r"(b1));
}
__device__ __forceinline__ void mma_fp(float* d, const uint32_t* a, uint32_t b0, uint32_t b1) {
    asm volatile("mma.sync.aligned.m16n8k16.row.col.f32.f16.f16.f32 "
                 "{%0,%1,%2,%3}, {%4,%5,%6,%7}, {%8,%9}, {%0,%1,%2,%3};"
                 : "+f"(d[0]), "+f"(d[1]), "+f"(d[2]), "+f"(d[3])
                 : "r"(a[0]), "r"(a[1]), "r"(a[2]), "r"(a[3]), "r"(b0), "r"(b1));
}
__device__ __forceinline__ void splitStoreBF(float4 v, uint32_t* hi, uint32_t* lo) {
    uint32_t hx = f2bf(v.x), hy = f2bf(v.y), hz = f2bf(v.z), hw = f2bf(v.w);
    uint32_t lx = f2bf(v.x - bf2f(hx));
    uint32_t ly = f2bf(v.y - bf2f(hy));
    uint32_t lz = f2bf(v.z - bf2f(hz));
    uint32_t lw = f2bf(v.w - bf2f(hw));
    hi[0] = hx | (hy << 16);
    hi[1] = hz | (hw << 16);
    lo[0] = lx | (ly << 16);
    lo[1] = lz | (lw << 16);
}
__device__ __forceinline__ void convStoreH(float4 v, uint32_t* hi) {
    u16 hx = f2h(v.x), hy = f2h(v.y), hz = f2h(v.z), hw = f2h(v.w);
    hi[0] = (uint32_t)hx | ((uint32_t)hy << 16);
    hi[1] = (uint32_t)hz | ((uint32_t)hw << 16);
}

constexpr int MBM = 128, MBN = 128, MBK = 32;
constexpr int MLDW = 20;

// ===== 3-pass bf16 core — q/k projections + scores =====
struct MSmem3 {
    uint32_t Ah[MBM][MLDW];
    uint32_t Al[MBM][MLDW];
    uint32_t Bh[MBN][MLDW];
    uint32_t Bl[MBN][MLDW];
};

__device__ __forceinline__ void mma_core3(
    const float* __restrict__ A, const float* __restrict__ B, float* __restrict__ C,
    int K, int lda, int ldb, int ldc, int bm, int bn, MSmem3& s)
{
    const int tid = threadIdx.x;
    const int lane = tid & 31, wid = tid >> 5;
    const int wm = wid & 3, wn = wid >> 2;

    float acc[2][8][4];
#pragma unroll
    for (int i = 0; i < 2; i++)
#pragma unroll
        for (int j = 0; j < 8; j++)
#pragma unroll
            for (int e = 0; e < 4; e++) acc[i][j][e] = 0.f;

    const int lr = tid >> 3;
    const int lc = (tid & 7) * 4;
    const int wc = (tid & 7) * 2;

    const uint32_t sb = (uint32_t)__cvta_generic_to_shared(&s);
    const uint32_t offAl = MBM * MLDW * 4;
    const uint32_t offBh = 2 * MBM * MLDW * 4;
    const uint32_t offBl = 3 * MBM * MLDW * 4;
    const int arow = wm * 32 + (lane & 15);
    const int acol = (lane >> 4) * 8;
    const int brow = wn * 64 + (lane & 7) + ((lane >> 4) << 3);
    const int bcol = ((lane >> 3) & 1) << 3;

    for (int k0 = 0; k0 < K; k0 += MBK) {
#pragma unroll
        for (int p = 0; p < 4; p++) {
            int r = lr + p * 32;
            float4 av = *reinterpret_cast<const float4*>(&A[(size_t)(bm + r) * lda + k0 + lc]);
            splitStoreBF(av, &s.Ah[r][wc], &s.Al[r][wc]);
            float4 bv = *reinterpret_cast<const float4*>(&B[(size_t)(bn + r) * ldb + k0 + lc]);
            splitStoreBF(bv, &s.Bh[r][wc], &s.Bl[r][wc]);
        }
        __syncthreads();

#pragma unroll
        for (int kk = 0; kk < 2; kk++) {
            uint32_t ah[2][4], al[2][4], bh[4][4], bl[4][4];
#pragma unroll
            for (int mf = 0; mf < 2; mf++) {
                uint32_t ao = (uint32_t)(((arow + mf * 16) * MLDW * 4) + (kk * 16 + acol) * 2);
                ldsm4(ah[mf], sb + ao);
                ldsm4(al[mf], sb + offAl + ao);
            }
#pragma unroll
            for (int np = 0; np < 4; np++) {
                uint32_t bo = (uint32_t)(((brow + np * 16) * MLDW * 4) + (kk * 16 + bcol) * 2);
                ldsm4(bh[np], sb + offBh + bo);
                ldsm4(bl[np], sb + offBl + bo);
            }
#pragma unroll
            for (int mf = 0; mf < 2; mf++) {
#pragma unroll
                for (int nf = 0; nf < 8; nf++) {
                    int np = nf >> 1;
                    int hf = (nf & 1) * 2;
                    mma_bf(acc[mf][nf], ah[mf], bh[np][hf], bh[np][hf + 1]);
                    mma_bf(acc[mf][nf], al[mf], bh[np][hf], bh[np][hf + 1]);
                    mma_bf(acc[mf][nf], ah[mf], bl[np][hf], bl[np][hf + 1]);
                }
            }
        }
        __syncthreads();
    }

#pragma unroll
    for (int mf = 0; mf < 2; mf++) {
        int row = bm + wm * 32 + mf * 16 + (lane >> 2);
#pragma unroll
        for (int nf = 0; nf < 8; nf++) {
            int col = bn + wn * 64 + nf * 8 + (lane & 3) * 2;
            *reinterpret_cast<float2*>(&C[(size_t)row * ldc + col]) =
                make_float2(acc[mf][nf][0], acc[mf][nf][1]);
            *reinterpret_cast<float2*>(&C[(size_t)(row + 8) * ldc + col]) =
                make_float2(acc[mf][nf][2], acc[mf][nf][3]);
        }
    }
}

__global__ void __launch_bounds__(256, 2)
mma_qk(const float* __restrict__ A, const float* __restrict__ wq, const float* __restrict__ wk,
       float* __restrict__ qraw, float* __restrict__ kraw) {
    __shared__ MSmem3 s;
    if (blockIdx.y < 16) {
        mma_core3(A, wq, qraw, H_, H_, H_, NH_ * HD_, blockIdx.x * MBM, blockIdx.y * MBN, s);
    } else {
        mma_core3(A, wk, kraw, H_, H_, H_, NKV_ * HD_, blockIdx.x * MBM,
                  (blockIdx.y - 16) * MBN, s);
    }
}

__global__ void __launch_bounds__(256, 2)
mma_scores(const float* __restrict__ q, const float* __restrict__ k, float* __restrict__ sc,
           int zoff) {
    if (blockIdx.y > blockIdx.x) return;
    int z = blockIdx.z + zoff;
    int b = z >> 3, h = z & 7;
    const float* A = q + (size_t)z * T_ * HD_;
    const float* B = k + (size_t)(b * NKV_ + (h >> 2)) * T_ * HD_;
    float* C = sc + (size_t)z * T_ * T_;
    __shared__ MSmem3 s;
    mma_core3(A, B, C, HD_, HD_, HD_, T_, blockIdx.x * MBM, blockIdx.y * MBN, s);
}

// ===== 1-pass fp16 cores =====
struct MSmem1 {
    uint32_t Ah[MBM][MLDW];
    uint32_t Bh[MBN][MLDW];
};

__device__ __forceinline__ void epi_store(
    float* Cf, u16* Ch, size_t idx, float v0, float v1) {
    if (Ch) {
        *reinterpret_cast<uint32_t*>(&Ch[idx]) =
            (uint32_t)f2h(v0) | ((uint32_t)f2h(v1) << 16);
    } else {
        *reinterpret_cast<float2*>(&Cf[idx]) = make_float2(v0, v1);
    }
}

// pipelined fp32-A core (laurel2, v) — fp32 out
__device__ __forceinline__ void mma_core1(
    const float* __restrict__ A, const float* __restrict__ B, float* __restrict__ C,
    int K, int lda, int ldb, int ldc, int bm, int bn, MSmem1 (&s)[2])
{
    const int tid = threadIdx.x;
    const int lane = tid & 31, wid = tid >> 5;
    const int wm = wid & 3, wn = wid >> 2;

    float acc[2][8][4];
#pragma unroll
    for (int i = 0; i < 2; i++)
#pragma unroll
        for (int j = 0; j < 8; j++)
#pragma unroll
            for (int e = 0; e < 4; e++) acc[i][j][e] = 0.f;

    const int lr = tid >> 3;
    const int lc = (tid & 7) * 4;
    const int wc = (tid & 7) * 2;

    const uint32_t sb0 = (uint32_t)__cvta_generic_to_shared(&s[0]);
    const uint32_t stageBytes = (uint32_t)sizeof(MSmem1);
    const uint32_t offBh = MBM * MLDW * 4;
    const int arow = wm * 32 + (lane & 15);
    const int acol = (lane >> 4) * 8;
    const int brow = wn * 64 + (lane & 7) + ((lane >> 4) << 3);
    const int bcol = ((lane >> 3) & 1) << 3;

    float4 av[4], bv[4];
#pragma unroll
    for (int p = 0; p < 4; p++) {
        int r = lr + p * 32;
        av[p] = *reinterpret_cast<const float4*>(&A[(size_t)(bm + r) * lda + lc]);
        bv[p] = *reinterpret_cast<const float4*>(&B[(size_t)(bn + r) * ldb + lc]);
    }
#pragma unroll
    for (int p = 0; p < 4; p++) {
        int r = lr + p * 32;
        convStoreH(av[p], &s[0].Ah[r][wc]);
        convStoreH(bv[p], &s[0].Bh[r][wc]);
    }
    __syncthreads();

    const int KT = K / MBK;
    for (int kt = 0; kt < KT; kt++) {
        const int cur = kt & 1;
        const uint32_t sb = sb0 + (uint32_t)cur * stageBytes;
        if (kt + 1 < KT) {
            int k0 = (kt + 1) * MBK;
#pragma unroll
            for (int p = 0; p < 4; p++) {
                int r = lr + p * 32;
                av[p] = *reinterpret_cast<const float4*>(&A[(size_t)(bm + r) * lda + k0 + lc]);
                bv[p] = *reinterpret_cast<const float4*>(&B[(size_t)(bn + r) * ldb + k0 + lc]);
            }
        }
#pragma unroll
        for (int kk = 0; kk < 2; kk++) {
            uint32_t ah[2][4], bh[4][4];
#pragma unroll
            for (int mf = 0; mf < 2; mf++) {
                uint32_t ao = (uint32_t)(((arow + mf * 16) * MLDW * 4) + (kk * 16 + acol) * 2);
                ldsm4(ah[mf], sb + ao);
            }
#pragma unroll
            for (int np = 0; np < 4; np++) {
                uint32_t bo = (uint32_t)(((brow + np * 16) * MLDW * 4) + (kk * 16 + bcol) * 2);
                ldsm4(bh[np], sb + offBh + bo);
            }
#pragma unroll
            for (int mf = 0; mf < 2; mf++) {
#pragma unroll
                for (int nf = 0; nf < 8; nf++) {
                    int np = nf >> 1;
                    int hf = (nf & 1) * 2;
                    mma_fp(acc[mf][nf], ah[mf], bh[np][hf], bh[np][hf + 1]);
                }
            }
        }
        if (kt + 1 < KT) {
            MSmem1& sn = s[cur ^ 1];
#pragma unroll
            for (int p = 0; p < 4; p++) {
                int r = lr + p * 32;
                convStoreH(av[p], &sn.Ah[r][wc]);
                convStoreH(bv[p], &sn.Bh[r][wc]);
            }
        }
        __syncthreads();
    }

#pragma unroll
    for (int mf = 0; mf < 2; mf++) {
        int row = bm + wm * 32 + mf * 16 + (lane >> 2);
#pragma unroll
        for (int nf = 0; nf < 8; nf++) {
            int col = bn + wn * 64 + nf * 8 + (lane & 3) * 2;
            *reinterpret_cast<float2*>(&C[(size_t)row * ldc + col]) =
                make_float2(acc[mf][nf][0], acc[mf][nf][1]);
            *reinterpret_cast<float2*>(&C[(size_t)(row + 8) * ldc + col]) =
                make_float2(acc[mf][nf][2], acc[mf][nf][3]);
        }
    }
}

// pipelined u16-A core; dual output (Cf fp32 | Ch fp16)
__device__ __forceinline__ void mma_core1h(
    const u16* __restrict__ A, const float* __restrict__ B,
    float* __restrict__ Cf, u16* __restrict__ Ch,
    int K, int lda, int ldb, int ldc, int bm, int bn, MSmem1 (&s)[2])
{
    const int tid = threadIdx.x;
    const int lane = tid & 31, wid = tid >> 5;
    const int wm = wid & 3, wn = wid >> 2;

    float acc[2][8][4];
#pragma unroll
    for (int i = 0; i < 2; i++)
#pragma unroll
        for (int j = 0; j < 8; j++)
#pragma unroll
            for (int e = 0; e < 4; e++) acc[i][j][e] = 0.f;

    const int lr = tid >> 3;
    const int lc = (tid & 7) * 4;
    const int wc = (tid & 7) * 2;

    const uint32_t sb0 = (uint32_t)__cvta_generic_to_shared(&s[0]);
    const uint32_t stageBytes = (uint32_t)sizeof(MSmem1);
    const uint32_t offBh = MBM * MLDW * 4;
    const int arow = wm * 32 + (lane & 15);
    const int acol = (lane >> 4) * 8;
    const int brow = wn * 64 + (lane & 7) + ((lane >> 4) << 3);
    const int bcol = ((lane >> 3) & 1) << 3;

    uint2 av[4];
    float4 bv[4];
#pragma unroll
    for (int p = 0; p < 4; p++) {
        int r = lr + p * 32;
        av[p] = *reinterpret_cast<const uint2*>(&A[(size_t)(bm + r) * lda + lc]);
        bv[p] = *reinterpret_cast<const float4*>(&B[(size_t)(bn + r) * ldb + lc]);
    }
#pragma unroll
    for (int p = 0; p < 4; p++) {
        int r = lr + p * 32;
        s[0].Ah[r][wc] = av[p].x;
        s[0].Ah[r][wc + 1] = av[p].y;
        convStoreH(bv[p], &s[0].Bh[r][wc]);
    }
    __syncthreads();

    const int KT = K / MBK;
    for (int kt = 0; kt < KT; kt++) {
        const int cur = kt & 1;
        const uint32_t sb = sb0 + (uint32_t)cur * stageBytes;
        if (kt + 1 < KT) {
            int k0 = (kt + 1) * MBK;
#pragma unroll
            for (int p = 0; p < 4; p++) {
                int r = lr + p * 32;
                av[p] = *reinterpret_cast<const uint2*>(&A[(size_t)(bm + r) * lda + k0 + lc]);
                bv[p] = *reinterpret_cast<const float4*>(&B[(size_t)(bn + r) * ldb + k0 + lc]);
            }
        }
#pragma unroll
        for (int kk = 0; kk < 2; kk++) {
            uint32_t ah[2][4], bh[4][4];
#pragma unroll
            for (int mf = 0; mf < 2; mf++) {
                uint32_t ao = (uint32_t)(((arow + mf * 16) * MLDW * 4) + (kk * 16 + acol) * 2);
                ldsm4(ah[mf], sb + ao);
            }
#pragma unroll
            for (int np = 0; np < 4; np++) {
                uint32_t bo = (uint32_t)(((brow + np * 16) * MLDW * 4) + (kk * 16 + bcol) * 2);
                ldsm4(bh[np], sb + offBh + bo);
            }
#pragma unroll
            for (int mf = 0; mf < 2; mf++) {
#pragma unroll
                for (int nf = 0; nf < 8; nf++) {
                    int np = nf >> 1;
                    int hf = (nf & 1) * 2;
                    mma_fp(acc[mf][nf], ah[mf], bh[np][hf], bh[np][hf + 1]);
                }
            }
        }
        if (kt + 1 < KT) {
            MSmem1& sn = s[cur ^ 1];
#pragma unroll
            for (int p = 0; p < 4; p++) {
                int r = lr + p * 32;
                sn.Ah[r][wc] = av[p].x;
                sn.Ah[r][wc + 1] = av[p].y;
                convStoreH(bv[p], &sn.Bh[r][wc]);
            }
        }
        __syncthreads();
    }

#pragma unroll
    for (int mf = 0; mf < 2; mf++) {
        int row = bm + wm * 32 + mf * 16 + (lane >> 2);
#pragma unroll
        for (int nf = 0; nf < 8; nf++) {
            int col = bn + wn * 64 + nf * 8 + (lane & 3) * 2;
            epi_store(Cf, Ch, (size_t)row * ldc + col, acc[mf][nf][0], acc[mf][nf][1]);
            epi_store(Cf, Ch, (size_t)(row + 8) * ldc + col, acc[mf][nf][2], acc[mf][nf][3]);
        }
    }
}

__global__ void __launch_bounds__(256, 2)
mma_nt1(const float* __restrict__ A, const float* __restrict__ B, float* __restrict__ C,
        int K, int lda, int ldb, int ldc) {
    __shared__ MSmem1 s[2];
    mma_core1(A, B, C, K, lda, ldb, ldc, blockIdx.x * MBM, blockIdx.y * MBN, s);
}

__global__ void __launch_bounds__(256, 2)
mma_nt1h(const u16* __restrict__ A, const float* __restrict__ B, float* __restrict__ C,
         int K, int lda, int ldb, int ldc) {
    __shared__ MSmem1 s[2];
    mma_core1h(A, B, C, (u16*)0, K, lda, ldb, ldc, blockIdx.x * MBM, blockIdx.y * MBN, s);
}

__global__ void __launch_bounds__(256, 2)
mma_gateup(const u16* __restrict__ A, const float* __restrict__ gw,
           const float* __restrict__ uw, u16* __restrict__ gateH, u16* __restrict__ upH) {
    __shared__ MSmem1 s[2];
    if (blockIdx.y < 64) {
        mma_core1h(A, gw, (float*)0, gateH, H_, H_, H_, FF_,
                   blockIdx.x * MBM, blockIdx.y * MBN, s);
    } else {
        mma_core1h(A, uw, (float*)0, upH, H_, H_, H_, FF_,
                   blockIdx.x * MBM, (blockIdx.y - 64) * MBN, s);
    }
}

__global__ void __launch_bounds__(256, 2)
mma_attnv(const u16* __restrict__ p, const float* __restrict__ vT, u16* __restrict__ oH) {
    int z = blockIdx.z;
    int b = z >> 3, h = z & 7;
    const u16* A = p + (size_t)z * T_ * T_;
    const float* B = vT + (size_t)(b * NKV_ + (h >> 2)) * HD_ * T_;
    u16* C = oH + (size_t)b * T_ * H_ + (size_t)h * HD_;
    int bm = blockIdx.x * MBM;
    __shared__ MSmem1 s[2];
    mma_core1h(A, B, (float*)0, C, bm + MBM, T_, T_, H_, bm, blockIdx.y * MBN, s);
}

// laurel1: split-K x8
__global__ void __launch_bounds__(256)
laurel1_kernel(const float* __restrict__ A, const float* __restrict__ B, float* __restrict__ P) {
    __shared__ float Bs[64][65];
    __shared__ float As[32][65];
    int tid = threadIdx.x;
    int bm = blockIdx.x * 32;
    int ks = blockIdx.y;
    int kbeg = ks * (H_ / 8), kend = kbeg + H_ / 8;
    float acc0[4] = {0.f, 0.f, 0.f, 0.f};
    float acc1[4] = {0.f, 0.f, 0.f, 0.f};
    int tn = tid & 15;
    int tr = tid >> 4;
    for (int k0 = kbeg; k0 < kend; k0 += 64) {
        for (int i = tid; i < 64 * 64; i += 256) {
            int n = i >> 6, kk = i & 63;
            Bs[n][kk] = B[(size_t)n * H_ + k0 + kk];
        }
        for (int i = tid; i < 32 * 64; i += 256) {
            int r = i >> 6, kk = i & 63;
            As[r][kk] = A[(size_t)(bm + r) * H_ + k0 + kk];
        }
        __syncthreads();
#pragma unroll 8
        for (int kk = 0; kk < 64; kk++) {
            float a0 = As[tr][kk], a1 = As[tr + 16][kk];
#pragma unroll
            for (int j = 0; j < 4; j++) {
                float bv = Bs[tn * 4 + j][kk];
                acc0[j] = fmaf(a0, bv, acc0[j]);
                acc1[j] = fmaf(a1, bv, acc1[j]);
            }
        }
        __syncthreads();
    }
#pragma unroll
    for (int j = 0; j < 4; j++) {
        P[((size_t)ks * BT_ + bm + tr) * LR_ + tn * 4 + j] = acc0[j];
        P[((size_t)ks * BT_ + bm + tr + 16) * LR_ + tn * 4 + j] = acc1[j];
    }
}

__global__ void laurel1_reduce(const float* __restrict__ P, float* __restrict__ out) {
    int i = blockIdx.x * blockDim.x + threadIdx.x;
    if (i >= BT_ * LR_) return;
    float s = 0.f;
#pragma unroll
    for (int k = 0; k < 8; k++) s += P[(size_t)k * BT_ * LR_ + i];
    out[i] = s;
}

// ---------- lazy side stream + events ----------
static cudaStream_t g_s1 = 0;
static cudaEvent_t g_ev0 = 0, g_evL = 0, g_evS0 = 0, g_evP0 = 0;

extern "C" void kernel_launch(void* const* d_in, const int* in_sizes, int n_in,
                              void* d_out, int out_size) {
    const float* hs    = (const float*)d_in[0];
    const float* cosb  = (const float*)d_in[1];
    const float* sinb  = (const float*)d_in[2];
    const float* wq    = (const float*)d_in[3];
    const float* wk    = (const float*)d_in[4];
    const float* wv    = (const float*)d_in[5];
    const float* wo    = (const float*)d_in[6];
    const float* qnw   = (const float*)d_in[7];
    const float* knw   = (const float*)d_in[8];
    const float* in_ln = (const float*)d_in[9];
    const float* pa_ln = (const float*)d_in[10];
    const float* pf_ln = (const float*)d_in[11];
    const float* pw_ln = (const float*)d_in[12];
    const float* gatew = (const float*)d_in[13];
    const float* upw   = (const float*)d_in[14];
    const float* downw = (const float*)d_in[15];
    const float* llw   = (const float*)d_in[16];
    const float* lrw   = (const float*)d_in[17];
    const float* lnw   = (const float*)d_in[18];
    const float* rnw   = (const float*)d_in[19];
    const float* rw    = (const float*)d_in[20];
    const float* pcw   = (const float*)d_in[21];
    const float* ccw   = (const float*)d_in[22];
    const float* cscal = (const float*)d_in[23];
    float* out = (float*)d_out;

    Scratch* S = 0;
    cudaGetSymbolAddress((void**)&S, g_scratch);

    if (!g_s1) {
        cudaStreamCreateWithFlags(&g_s1, cudaStreamNonBlocking);
        cudaEventCreateWithFlags(&g_ev0, cudaEventDisableTiming);
        cudaEventCreateWithFlags(&g_evL, cudaEventDisableTiming);
        cudaEventCreateWithFlags(&g_evS0, cudaEventDisableTiming);
        cudaEventCreateWithFlags(&g_evP0, cudaEventDisableTiming);
    }

    fused_pre<<<BT_, 256>>>(hs, rnw, rw, pcw, in_ln, S->pred0, S->cfg, S->xnorm);

    // fork: laurel chain + v chain on side stream
    cudaEventRecord(g_ev0, 0);
    cudaStreamWaitEvent(g_s1, g_ev0, 0);
    laurel1_kernel<<<dim3(BT_ / 32, 8), 256, 0, g_s1>>>(S->xnorm, llw, S->lrpart);
    laurel1_reduce<<<(BT_ * LR_ + 255) / 256, 256, 0, g_s1>>>(S->lrpart, S->lrbuf);
    mma_nt1<<<dim3(16, 16), 256, 0, g_s1>>>(S->lrbuf, lrw, S->laurel, LR_, LR_, LR_, H_);
    ln_kernel<<<BT_, 256, 0, g_s1>>>(S->laurel, lnw, S->xnorm, (const float*)0, 1.f, S->laurel);
    mma_nt1<<<dim3(16, 4), 256, 0, g_s1>>>(S->xnorm, wv, S->vraw, H_, H_, H_, NKV_ * HD_);
    qkvpost_kernel<<<BT_ * NKV_, 256, 0, g_s1>>>(S->vraw, (const float*)0, cosb, sinb,
                                                 S->vT, NKV_, 0, 1);
    cudaEventRecord(g_evL, g_s1);

    // main: q+k projections (combined), post
    mma_qk<<<dim3(16, 20), 256>>>(S->xnorm, wq, wk, S->qraw, S->kraw);
    qkvpost_qk<<<BT_ * (NH_ + NKV_), 256>>>(S->qraw, S->kraw, qnw, knw, cosb, sinb, S->q, S->k);

    // chunked attention: scores chunk0 -> softmax0 on side stream, overlapped
    // with scores chunk1 + softmax1 on main.
    const size_t chunkElems = (size_t)8 * T_ * T_;   // 8 heads (batch 0)
    mma_scores<<<dim3(8, 8, 8), 256>>>(S->q, S->k, S->scores, 0);
    cudaEventRecord(g_evS0, 0);
    cudaStreamWaitEvent(g_s1, g_evS0, 0);
    softmax_kernel<<<(8 * T_) / 8, 256, 0, g_s1>>>(S->scores, S->probs);
    cudaEventRecord(g_evP0, g_s1);

    mma_scores<<<dim3(8, 8, 8), 256>>>(S->q, S->k, S->scores, 8);
    softmax_kernel<<<(8 * T_) / 8, 256>>>(S->scores + chunkElems, S->probs + chunkElems);

    cudaStreamWaitEvent(0, g_evP0, 0);
    cudaStreamWaitEvent(0, g_evL, 0);
    mma_attnv<<<dim3(8, 2, B_ * NH_), 256>>>(S->probs, S->vT, S->aoH);
    mma_nt1h<<<dim3(16, 16), 256>>>(S->aoH, wo, S->attnproj,
                                    NH_ * HD_, NH_ * HD_, NH_ * HD_, H_);

    fused_mid<<<BT_, 256>>>(S->attnproj, pa_ln, S->pred0, S->laurel, pf_ln,
                            S->attnlaurel, S->hnH);

    mma_gateup<<<dim3(16, 128), 256>>>(S->hnH, gatew, upw, S->gateH, S->upH);

    int n4 = (int)(FFSZ_ / 4);
    gelumul_kernel<<<(n4 + 255) / 256, 256>>>(S->gateH, S->upH, S->gp, n4);
    mma_nt1h<<<dim3(16, 16), 256>>>(S->gp, downw, S->ffw, FF_, FF_, FF_, H_);

    fused_post<<<BT_, 256>>>(S->ffw, pw_ln, S->attnlaurel, rnw, rw, ccw, cscal,
                             hs, S->cfg, out);

    (void)in_sizes; (void)n_in; (void)out_size;
}

// round 17
// speedup vs baseline: 1.2970x; 1.0007x over previous
#include <cuda_runtime.h>
#include <cstdint>
#include <cstddef>
#include <math.h>

typedef unsigned short u16;

constexpr int B_ = 2, T_ = 1024, H_ = 2048, NH_ = 8, NKV_ = 2, HD_ = 256;
constexpr int FF_ = 8192, LR_ = 64;
constexpr int BT_ = B_ * T_;
constexpr size_t BTH_ = (size_t)BT_ * H_;
constexpr size_t SCSZ_ = (size_t)B_ * NH_ * T_ * T_;
constexpr size_t FFSZ_ = (size_t)BT_ * FF_;
constexpr float EPS_ = 1e-6f;

struct Scratch {
    float pred0[BTH_];
    float cfg[BT_ * 16];
    float xnorm[BTH_];
    float lrpart[8 * BT_ * LR_];
    float lrbuf[BT_ * LR_];
    float laurel[BTH_];
    float qraw[BTH_];
    float kraw[(size_t)BT_ * NKV_ * HD_];
    float vraw[(size_t)BT_ * NKV_ * HD_];
    float q[BTH_];
    float k[(size_t)BT_ * NKV_ * HD_];
    float vT[(size_t)BT_ * NKV_ * HD_];
    float scores[SCSZ_];
    u16 probs[SCSZ_];
    u16 aoH[BTH_];
    float attnproj[BTH_];
    float attnlaurel[BTH_];
    u16 hnH[BTH_];
    u16 gateH[FFSZ_];
    u16 upH[FFSZ_];
    u16 gp[FFSZ_];
    float ffw[BTH_];
};
__device__ Scratch g_scratch;

// ---------- bf16 / fp16 bit helpers ----------
__device__ __forceinline__ uint32_t f2bf(float x) {
    uint32_t u = __float_as_uint(x);
    return (u + 0x7FFFu + ((u >> 16) & 1u)) >> 16;
}
__device__ __forceinline__ float bf2f(uint32_t b) {
    return __uint_as_float(b << 16);
}
__device__ __forceinline__ u16 f2h(float x) {
    u16 h;
    asm("cvt.rn.f16.f32 %0, %1;" : "=h"(h) : "f"(x));
    return h;
}
__device__ __forceinline__ float h2f(u16 h) {
    float f;
    asm("cvt.f32.f16 %0, %1;" : "=f"(f) : "h"(h));
    return f;
}

// ---------- reductions ----------
__device__ __forceinline__ float warpSum(float v) {
#pragma unroll
    for (int o = 16; o > 0; o >>= 1) v += __shfl_xor_sync(0xffffffffu, v, o);
    return v;
}
__device__ __forceinline__ float warpMax(float v) {
#pragma unroll
    for (int o = 16; o > 0; o >>= 1) v = fmaxf(v, __shfl_xor_sync(0xffffffffu, v, o));
    return v;
}
__device__ __forceinline__ float blockSum(float v, float* red) {
    v = warpSum(v);
    int lane = threadIdx.x & 31, w = threadIdx.x >> 5;
    if (lane == 0) red[w] = v;
    __syncthreads();
    int nw = (blockDim.x + 31) >> 5;
    float r = (lane < nw) ? red[lane] : 0.f;
    if (w == 0) {
        r = warpSum(r);
        if (lane == 0) red[0] = r;
    }
    __syncthreads();
    r = red[0];
    __syncthreads();
    return r;
}
// 4 simultaneous block sums; per-component arithmetic identical to blockSum.
// red must hold 128 floats.
__device__ __forceinline__ void blockSum4(float& a0, float& a1, float& a2, float& a3,
                                          float* red) {
    a0 = warpSum(a0);
    a1 = warpSum(a1);
    a2 = warpSum(a2);
    a3 = warpSum(a3);
    int lane = threadIdx.x & 31, w = threadIdx.x >> 5;
    if (lane == 0) {
        red[w] = a0;
        red[32 + w] = a1;
        red[64 + w] = a2;
        red[96 + w] = a3;
    }
    __syncthreads();
    int nw = (blockDim.x + 31) >> 5;
    if (w == 0) {
        float r0 = (lane < nw) ? red[lane] : 0.f;
        float r1 = (lane < nw) ? red[32 + lane] : 0.f;
        float r2 = (lane < nw) ? red[64 + lane] : 0.f;
        float r3 = (lane < nw) ? red[96 + lane] : 0.f;
        r0 = warpSum(r0);
        r1 = warpSum(r1);
        r2 = warpSum(r2);
        r3 = warpSum(r3);
        if (lane == 0) {
            red[0] = r0;
            red[32] = r1;
            red[64] = r2;
            red[96] = r3;
        }
    }
    __syncthreads();
    a0 = red[0];
    a1 = red[32];
    a2 = red[64];
    a3 = red[96];
    __syncthreads();
}

// ===== fused per-token kernels =====
__global__ void fused_pre(const float* __restrict__ hs, const float* __restrict__ rnw,
                          const float* __restrict__ rw, const float* __restrict__ pcw,
                          const float* __restrict__ inw,
                          float* __restrict__ pred0, float* __restrict__ cfg,
                          float* __restrict__ xnorm) {
    __shared__ float sx[H_];
    __shared__ float px[H_];
    __shared__ float red[128];
    __shared__ float cf[16];
    size_t off = (size_t)blockIdx.x * H_;
    int tid = threadIdx.x;

    float ls = 0.f;
    for (int i = tid; i < H_; i += blockDim.x) {
        float v = hs[off + i];
        sx[i] = v;
        ls += v;
    }
    float mean = blockSum(ls, red) * (1.f / H_);
    float lv = 0.f;
    for (int i = tid; i < H_; i += blockDim.x) {
        float d = sx[i] - mean;
        lv += d * d;
    }
    float rs = rsqrtf(blockSum(lv, red) * (1.f / H_) + EPS_);

    float a0 = 0.f, a1 = 0.f, a2 = 0.f, a3 = 0.f;
    for (int i = tid; i < H_; i += blockDim.x) {
        float r = (sx[i] - mean) * rs * rnw[i] * (1.f / H_);
        a0 += r * rw[i];
        a1 += r * rw[H_ + i];
        a2 += r * rw[2 * H_ + i];
        a3 += r * rw[3 * H_ + i];
    }
    blockSum4(a0, a1, a2, a3, red);
    if (tid < 16) {
        float m0 = tanhf(a0), m1 = tanhf(a1), m2 = tanhf(a2), m3 = tanhf(a3);
        float c = m0 * pcw[tid * 4] + m1 * pcw[tid * 4 + 1]
                + m2 * pcw[tid * 4 + 2] + m3 * pcw[tid * 4 + 3];
        cf[tid] = c;
        cfg[(size_t)blockIdx.x * 16 + tid] = c;
    }
    __syncthreads();

    float ps = 0.f;
    for (int i = tid; i < H_; i += blockDim.x) {
        float h0 = sx[i];
        float h1 = hs[BTH_ + off + i];
        float h2 = hs[2 * BTH_ + off + i];
        float h3 = hs[3 * BTH_ + off + i];
        float p0 = h0 + h0 * cf[0] + h1 * cf[1] + h2 * cf[2] + h3 * cf[3];
        pred0[off + i] = p0;
        px[i] = p0;
        ps += p0;
    }
    float mean2 = blockSum(ps, red) * (1.f / H_);
    float lv2 = 0.f;
    for (int i = tid; i < H_; i += blockDim.x) {
        float d = px[i] - mean2;
        lv2 += d * d;
    }
    float rs2 = rsqrtf(blockSum(lv2, red) * (1.f / H_) + EPS_);
    for (int i = tid; i < H_; i += blockDim.x) {
        xnorm[off + i] = (px[i] - mean2) * rs2 * inw[i];
    }
}

__global__ void fused_mid(const float* __restrict__ ap, const float* __restrict__ paw,
                          const float* __restrict__ pred0, const float* __restrict__ laurel,
                          const float* __restrict__ pfw,
                          float* __restrict__ attnlaurel, u16* __restrict__ hnH) {
    __shared__ float sx[H_];
    __shared__ float ax[H_];
    __shared__ float red[32];
    size_t off = (size_t)blockIdx.x * H_;
    int tid = threadIdx.x;

    float ls = 0.f;
    for (int i = tid; i < H_; i += blockDim.x) {
        float v = ap[off + i];
        sx[i] = v;
        ls += v;
    }
    float mean = blockSum(ls, red) * (1.f / H_);
    float lv = 0.f;
    for (int i = tid; i < H_; i += blockDim.x) {
        float d = sx[i] - mean;
        lv += d * d;
    }
    float rs = rsqrtf(blockSum(lv, red) * (1.f / H_) + EPS_);

    float ls2 = 0.f;
    for (int i = tid; i < H_; i += blockDim.x) {
        float v = (sx[i] - mean) * rs * paw[i] + pred0[off + i] + laurel[off + i];
        v *= 0.7071067811865476f;
        ax[i] = v;
        attnlaurel[off + i] = v;
        ls2 += v;
    }
    float mean2 = blockSum(ls2, red) * (1.f / H_);
    float lv2 = 0.f;
    for (int i = tid; i < H_; i += blockDim.x) {
        float d = ax[i] - mean2;
        lv2 += d * d;
    }
    float rs2 = rsqrtf(blockSum(lv2, red) * (1.f / H_) + EPS_);
    for (int i = tid; i < H_; i += blockDim.x) {
        hnH[off + i] = f2h((ax[i] - mean2) * rs2 * pfw[i]);
    }
}

__global__ void fused_post(const float* __restrict__ ffw, const float* __restrict__ pww,
                           const float* __restrict__ attnlaurel,
                           const float* __restrict__ rnw, const float* __restrict__ rw,
                           const float* __restrict__ ccw, const float* __restrict__ cscale,
                           const float* __restrict__ hs, const float* __restrict__ cfg,
                           float* __restrict__ out) {
    __shared__ float sx[H_];
    __shared__ float ax[H_];
    __shared__ float red[128];
    __shared__ float cf[16];
    size_t off = (size_t)blockIdx.x * H_;
    int tid = threadIdx.x;

    if (tid < 16) cf[tid] = cfg[(size_t)blockIdx.x * 16 + tid];

    float ls = 0.f;
    for (int i = tid; i < H_; i += blockDim.x) {
        float v = ffw[off + i];
        sx[i] = v;
        ls += v;
    }
    float mean = blockSum(ls, red) * (1.f / H_);
    float lv = 0.f;
    for (int i = tid; i < H_; i += blockDim.x) {
        float d = sx[i] - mean;
        lv += d * d;
    }
    float rs = rsqrtf(blockSum(lv, red) * (1.f / H_) + EPS_);

    float as = 0.f;
    for (int i = tid; i < H_; i += blockDim.x) {
        float v = (sx[i] - mean) * rs * pww[i] + attnlaurel[off + i];
        ax[i] = v;
        as += v;
    }
    float mean2 = blockSum(as, red) * (1.f / H_);
    float lv2 = 0.f;
    for (int i = tid; i < H_; i += blockDim.x) {
        float d = ax[i] - mean2;
        lv2 += d * d;
    }
    float rs2 = rsqrtf(blockSum(lv2, red) * (1.f / H_) + EPS_);
    float a0 = 0.f, a1 = 0.f, a2 = 0.f, a3 = 0.f;
    for (int i = tid; i < H_; i += blockDim.x) {
        float r = (ax[i] - mean2) * rs2 * rnw[i] * (1.f / H_);
        a0 += r * rw[i];
        a1 += r * rw[H_ + i];
        a2 += r * rw[2 * H_ + i];
        a3 += r * rw[3 * H_ + i];
    }
    blockSum4(a0, a1, a2, a3, red);
    float m0 = tanhf(a0);
    float m1 = tanhf(a1);
    float m2 = tanhf(a2);
    float m3 = tanhf(a3);
    float cc0 = 1.f + m0 * ccw[0]  + m1 * ccw[1]  + m2 * ccw[2]  + m3 * ccw[3];
    float cc1 = 1.f + m0 * ccw[4]  + m1 * ccw[5]  + m2 * ccw[6]  + m3 * ccw[7];
    float cc2 = 1.f + m0 * ccw[8]  + m1 * ccw[9]  + m2 * ccw[10] + m3 * ccw[11];
    float cc3 = 1.f + m0 * ccw[12] + m1 * ccw[13] + m2 * ccw[14] + m3 * ccw[15];

    for (int f = tid; f < H_; f += blockDim.x) {
        float h0 = hs[off + f];
        float h1 = hs[BTH_ + off + f];
        float h2 = hs[2 * BTH_ + off + f];
        float h3 = hs[3 * BTH_ + off + f];
        float p0 = h0 + h0 * cf[0]  + h1 * cf[1]  + h2 * cf[2]  + h3 * cf[3];
        float p1 = h1 + h0 * cf[4]  + h1 * cf[5]  + h2 * cf[6]  + h3 * cf[7];
        float p2 = h2 + h0 * cf[8]  + h1 * cf[9]  + h2 * cf[10] + h3 * cf[11];
        float p3 = h3 + h0 * cf[12] + h1 * cf[13] + h2 * cf[14] + h3 * cf[15];
        float inno = ax[f] - p0;
        out[off + f]            = (inno * cc0 + p0) * cscale[f];
        out[BTH_ + off + f]     = inno * cc1 + p1;
        out[2 * BTH_ + off + f] = inno * cc2 + p2;
        out[3 * BTH_ + off + f] = inno * cc3 + p3;
    }
}

// ---------- remaining elementwise ----------
__global__ void ln_kernel(const float* __restrict__ a, const float* __restrict__ w,
                          const float* __restrict__ add1, const float* __restrict__ add2,
                          float scale, float* __restrict__ dst) {
    __shared__ float sx[H_];
    __shared__ float red[32];
    size_t off = (size_t)blockIdx.x * H_;
    int tid = threadIdx.x;
    float ls = 0.f;
    for (int i = tid; i < H_; i += blockDim.x) {
        float v = a[off + i];
        sx[i] = v;
        ls += v;
    }
    float mean = blockSum(ls, red) * (1.f / H_);
    float lv = 0.f;
    for (int i = tid; i < H_; i += blockDim.x) {
        float d = sx[i] - mean;
        lv += d * d;
    }
    float var = blockSum(lv, red) * (1.f / H_);
    float rs = rsqrtf(var + EPS_);
    for (int i = tid; i < H_; i += blockDim.x) {
        float v = (sx[i] - mean) * rs * w[i];
        if (add1) v += add1[off + i];
        if (add2) v += add2[off + i];
        dst[off + i] = v * scale;
    }
}

__device__ __forceinline__ void qkvpost_body(
    const float* __restrict__ raw, const float* __restrict__ nw,
    const float* __restrict__ cosb, const float* __restrict__ sinb,
    float* __restrict__ out, int nheads, int do_rope, int trans, int idx) {
    __shared__ float sx[HD_];
    __shared__ float red[32];
    int h = idx % nheads;
    int bt = idx / nheads;
    int t = bt % T_, b = bt / T_;
    int d = threadIdx.x;
    float v = raw[(size_t)bt * nheads * HD_ + h * HD_ + d];
    float mean = blockSum(v, red) * (1.f / HD_);
    float c = v - mean;
    float var = blockSum(c * c, red) * (1.f / HD_);
    float ln = c * rsqrtf(var + EPS_) * (nw ? nw[d] : 1.f);
    sx[d] = ln;
    __syncthreads();
    float o = ln;
    if (do_rope) {
        float cs = cosb[(size_t)bt * HD_ + d];
        float sn = sinb[(size_t)bt * HD_ + d];
        float rot = (d < 128) ? -sx[d + 128] : sx[d - 128];
        o = ln * cs + rot * sn;
    }
    if (trans) {
        out[((size_t)(b * nheads + h) * HD_ + d) * T_ + t] = o;
    } else {
        out[((size_t)(b * nheads + h) * T_ + t) * HD_ + d] = o;
    }
}

__global__ void qkvpost_kernel(const float* __restrict__ raw, const float* __restrict__ nw,
                               const float* __restrict__ cosb, const float* __restrict__ sinb,
                               float* __restrict__ out, int nheads, int do_rope, int trans) {
    qkvpost_body(raw, nw, cosb, sinb, out, nheads, do_rope, trans, blockIdx.x);
}

__global__ void qkvpost_qk(const float* __restrict__ qraw, const float* __restrict__ kraw,
                           const float* __restrict__ qnw, const float* __restrict__ knw,
                           const float* __restrict__ cosb, const float* __restrict__ sinb,
                           float* __restrict__ q, float* __restrict__ k) {
    int idx = blockIdx.x;
    if (idx < BT_ * NH_) {
        qkvpost_body(qraw, qnw, cosb, sinb, q, NH_, 1, 0, idx);
    } else {
        qkvpost_body(kraw, knw, cosb, sinb, k, NKV_, 1, 0, idx - BT_ * NH_);
    }
}

// causal softmax, warp-per-row (8 rows/block), fp16 probs out.
__global__ void softmax_kernel(const float* __restrict__ scores, u16* __restrict__ probs) {
    __shared__ float sx[8][T_];
    int wid = threadIdx.x >> 5;
    int lane = threadIdx.x & 31;
    int row = blockIdx.x * 8 + wid;
    int q = row % T_;
    size_t off = (size_t)row * T_;
    int n = q + 1;
    float* srow = sx[wid];
    float lm = -INFINITY;
    for (int i = lane; i < n; i += 32) {
        float v = scores[off + i];
        srow[i] = v;
        lm = fmaxf(lm, v);
    }
    float gm = warpMax(lm);
    float ls = 0.f;
    for (int i = lane; i < n; i += 32) {
        float e = __expf(srow[i] - gm);
        srow[i] = e;
        ls += e;
    }
    float inv = 1.f / warpSum(ls);
    for (int i = lane; i < T_; i += 32) {
        probs[off + i] = (i < n) ? f2h(srow[i] * inv) : (u16)0;
    }
}

__device__ __forceinline__ float gelu_tanh(float x) {
    return 0.5f * x * (1.f + tanhf(0.7978845608028654f * (x + 0.044715f * x * x * x)));
}

__global__ void gelumul_kernel(const u16* __restrict__ g, const u16* __restrict__ u,
                               u16* __restrict__ o, int n4) {
    int i = blockIdx.x * blockDim.x + threadIdx.x;
    if (i >= n4) return;
    uint2 gp = reinterpret_cast<const uint2*>(g)[i];
    uint2 up = reinterpret_cast<const uint2*>(u)[i];
    float g0 = h2f((u16)(gp.x & 0xFFFF)), g1 = h2f((u16)(gp.x >> 16));
    float g2 = h2f((u16)(gp.y & 0xFFFF)), g3 = h2f((u16)(gp.y >> 16));
    float u0 = h2f((u16)(up.x & 0xFFFF)), u1 = h2f((u16)(up.x >> 16));
    float u2 = h2f((u16)(up.y & 0xFFFF)), u3 = h2f((u16)(up.y >> 16));
    u16 h0 = f2h(gelu_tanh(g0) * u0);
    u16 h1 = f2h(gelu_tanh(g1) * u1);
    u16 h2h = f2h(gelu_tanh(g2) * u2);
    u16 h3 = f2h(gelu_tanh(g3) * u3);
    uint2 pk;
    pk.x = (uint32_t)h0 | ((uint32_t)h1 << 16);
    pk.y = (uint32_t)h2h | ((uint32_t)h3 << 16);
    reinterpret_cast<uint2*>(o)[i] = pk;
}

// ===== shared MMA plumbing =====
__device__ __forceinline__ void ldsm4(uint32_t* r, uint32_t addr) {
    asm volatile("ldmatrix.sync.aligned.m8n8.x4.shared.b16 {%0,%1,%2,%3}, [%4];"
                 : "=r"(r[0]), "=r"(r[1]), "=r"(r[2]), "=r"(r[3]) : "r"(addr));
}
__device__ __forceinline__ void mma_bf(float* d, const uint32_t* a, uint32_t b0, uint32_t b1) {
    asm volatile("mma.sync.aligned.m16n8k16.row.col.f32.bf16.bf16.f32 "
                 "{%0,%1,%2,%3}, {%4,%5,%6,%7}, {%8,%9}, {%0,%1,%2,%3};"
                 : "+f"(d[0]), "+f"(d[1]), "+f"(d[2]), "+f"(d[3])
                 : "r"(a[0]), "r"(a[1]), "r"(a[2]), "r"(a[3]), "r"(b0), "r"(b1));
}
__device__ __forceinline__ void mma_fp(float* d, const uint32_t* a, uint32_t b0, uint32_t b1) {
    asm volatile("mma.sync.aligned.m16n8k16.row.col.f32.f16.f16.f32 "
                 "{%0,%1,%2,%3}, {%4,%5,%6,%7}, {%8,%9}, {%0,%1,%2,%3};"
                 : "+f"(d[0]), "+f"(d[1]), "+f"(d[2]), "+f"(d[3])
                 : "r"(a[0]), "r"(a[1]), "r"(a[2]), "r"(a[3]), "r"(b0), "r"(b1));
}
__device__ __forceinline__ void splitStoreBF(float4 v, uint32_t* hi, uint32_t* lo) {
    uint32_t hx = f2bf(v.x), hy = f2bf(v.y), hz = f2bf(v.z), hw = f2bf(v.w);
    uint32_t lx = f2bf(v.x - bf2f(hx));
    uint32_t ly = f2bf(v.y - bf2f(hy));
    uint32_t lz = f2bf(v.z - bf2f(hz));
    uint32_t lw = f2bf(v.w - bf2f(hw));
    hi[0] = hx | (hy << 16);
    hi[1] = hz | (hw << 16);
    lo[0] = lx | (ly << 16);
    lo[1] = lz | (lw << 16);
}
__device__ __forceinline__ void convStoreH(float4 v, uint32_t* hi) {
    u16 hx = f2h(v.x), hy = f2h(v.y), hz = f2h(v.z), hw = f2h(v.w);
    hi[0] = (uint32_t)hx | ((uint32_t)hy << 16);
    hi[1] = (uint32_t)hz | ((uint32_t)hw << 16);
}

constexpr int MBM = 128, MBN = 128, MBK = 32;
constexpr int MLDW = 20;

// ===== 3-pass bf16 core — q/k projections + scores =====
struct MSmem3 {
    uint32_t Ah[MBM][MLDW];
    uint32_t Al[MBM][MLDW];
    uint32_t Bh[MBN][MLDW];
    uint32_t Bl[MBN][MLDW];
};

__device__ __forceinline__ void mma_core3(
    const float* __restrict__ A, const float* __restrict__ B, float* __restrict__ C,
    int K, int lda, int ldb, int ldc, int bm, int bn, MSmem3& s)
{
    const int tid = threadIdx.x;
    const int lane = tid & 31, wid = tid >> 5;
    const int wm = wid & 3, wn = wid >> 2;

    float acc[2][8][4];
#pragma unroll
    for (int i = 0; i < 2; i++)
#pragma unroll
        for (int j = 0; j < 8; j++)
#pragma unroll
            for (int e = 0; e < 4; e++) acc[i][j][e] = 0.f;

    const int lr = tid >> 3;
    const int lc = (tid & 7) * 4;
    const int wc = (tid & 7) * 2;

    const uint32_t sb = (uint32_t)__cvta_generic_to_shared(&s);
    const uint32_t offAl = MBM * MLDW * 4;
    const uint32_t offBh = 2 * MBM * MLDW * 4;
    const uint32_t offBl = 3 * MBM * MLDW * 4;
    const int arow = wm * 32 + (lane & 15);
    const int acol = (lane >> 4) * 8;
    const int brow = wn * 64 + (lane & 7) + ((lane >> 4) << 3);
    const int bcol = ((lane >> 3) & 1) << 3;

    for (int k0 = 0; k0 < K; k0 += MBK) {
#pragma unroll
        for (int p = 0; p < 4; p++) {
            int r = lr + p * 32;
            float4 av = *reinterpret_cast<const float4*>(&A[(size_t)(bm + r) * lda + k0 + lc]);
            splitStoreBF(av, &s.Ah[r][wc], &s.Al[r][wc]);
            float4 bv = *reinterpret_cast<const float4*>(&B[(size_t)(bn + r) * ldb + k0 + lc]);
            splitStoreBF(bv, &s.Bh[r][wc], &s.Bl[r][wc]);
        }
        __syncthreads();

#pragma unroll
        for (int kk = 0; kk < 2; kk++) {
            uint32_t ah[2][4], al[2][4], bh[4][4], bl[4][4];
#pragma unroll
            for (int mf = 0; mf < 2; mf++) {
                uint32_t ao = (uint32_t)(((arow + mf * 16) * MLDW * 4) + (kk * 16 + acol) * 2);
                ldsm4(ah[mf], sb + ao);
                ldsm4(al[mf], sb + offAl + ao);
            }
#pragma unroll
            for (int np = 0; np < 4; np++) {
                uint32_t bo = (uint32_t)(((brow + np * 16) * MLDW * 4) + (kk * 16 + bcol) * 2);
                ldsm4(bh[np], sb + offBh + bo);
                ldsm4(bl[np], sb + offBl + bo);
            }
#pragma unroll
            for (int mf = 0; mf < 2; mf++) {
#pragma unroll
                for (int nf = 0; nf < 8; nf++) {
                    int np = nf >> 1;
                    int hf = (nf & 1) * 2;
                    mma_bf(acc[mf][nf], ah[mf], bh[np][hf], bh[np][hf + 1]);
                    mma_bf(acc[mf][nf], al[mf], bh[np][hf], bh[np][hf + 1]);
                    mma_bf(acc[mf][nf], ah[mf], bl[np][hf], bl[np][hf + 1]);
                }
            }
        }
        __syncthreads();
    }

#pragma unroll
    for (int mf = 0; mf < 2; mf++) {
        int row = bm + wm * 32 + mf * 16 + (lane >> 2);
#pragma unroll
        for (int nf = 0; nf < 8; nf++) {
            int col = bn + wn * 64 + nf * 8 + (lane & 3) * 2;
            *reinterpret_cast<float2*>(&C[(size_t)row * ldc + col]) =
                make_float2(acc[mf][nf][0], acc[mf][nf][1]);
            *reinterpret_cast<float2*>(&C[(size_t)(row + 8) * ldc + col]) =
                make_float2(acc[mf][nf][2], acc[mf][nf][3]);
        }
    }
}

__global__ void __launch_bounds__(256, 2)
mma_qk(const float* __restrict__ A, const float* __restrict__ wq, const float* __restrict__ wk,
       float* __restrict__ qraw, float* __restrict__ kraw) {
    __shared__ MSmem3 s;
    if (blockIdx.y < 16) {
        mma_core3(A, wq, qraw, H_, H_, H_, NH_ * HD_, blockIdx.x * MBM, blockIdx.y * MBN, s);
    } else {
        mma_core3(A, wk, kraw, H_, H_, H_, NKV_ * HD_, blockIdx.x * MBM,
                  (blockIdx.y - 16) * MBN, s);
    }
}

__global__ void __launch_bounds__(256, 2)
mma_scores(const float* __restrict__ q, const float* __restrict__ k, float* __restrict__ sc,
           int zoff) {
    if (blockIdx.y > blockIdx.x) return;
    int z = blockIdx.z + zoff;
    int b = z >> 3, h = z & 7;
    const float* A = q + (size_t)z * T_ * HD_;
    const float* B = k + (size_t)(b * NKV_ + (h >> 2)) * T_ * HD_;
    float* C = sc + (size_t)z * T_ * T_;
    __shared__ MSmem3 s;
    mma_core3(A, B, C, HD_, HD_, HD_, T_, blockIdx.x * MBM, blockIdx.y * MBN, s);
}

// ===== 1-pass fp16 cores =====
struct MSmem1 {
    uint32_t Ah[MBM][MLDW];
    uint32_t Bh[MBN][MLDW];
};

__device__ __forceinline__ void epi_store(
    float* Cf, u16* Ch, size_t idx, float v0, float v1) {
    if (Ch) {
        *reinterpret_cast<uint32_t*>(&Ch[idx]) =
            (uint32_t)f2h(v0) | ((uint32_t)f2h(v1) << 16);
    } else {
        *reinterpret_cast<float2*>(&Cf[idx]) = make_float2(v0, v1);
    }
}

// pipelined fp32-A core (laurel2, v) — fp32 out
__device__ __forceinline__ void mma_core1(
    const float* __restrict__ A, const float* __restrict__ B, float* __restrict__ C,
    int K, int lda, int ldb, int ldc, int bm, int bn, MSmem1 (&s)[2])
{
    const int tid = threadIdx.x;
    const int lane = tid & 31, wid = tid >> 5;
    const int wm = wid & 3, wn = wid >> 2;

    float acc[2][8][4];
#pragma unroll
    for (int i = 0; i < 2; i++)
#pragma unroll
        for (int j = 0; j < 8; j++)
#pragma unroll
            for (int e = 0; e < 4; e++) acc[i][j][e] = 0.f;

    const int lr = tid >> 3;
    const int lc = (tid & 7) * 4;
    const int wc = (tid & 7) * 2;

    const uint32_t sb0 = (uint32_t)__cvta_generic_to_shared(&s[0]);
    const uint32_t stageBytes = (uint32_t)sizeof(MSmem1);
    const uint32_t offBh = MBM * MLDW * 4;
    const int arow = wm * 32 + (lane & 15);
    const int acol = (lane >> 4) * 8;
    const int brow = wn * 64 + (lane & 7) + ((lane >> 4) << 3);
    const int bcol = ((lane >> 3) & 1) << 3;

    float4 av[4], bv[4];
#pragma unroll
    for (int p = 0; p < 4; p++) {
        int r = lr + p * 32;
        av[p] = *reinterpret_cast<const float4*>(&A[(size_t)(bm + r) * lda + lc]);
        bv[p] = *reinterpret_cast<const float4*>(&B[(size_t)(bn + r) * ldb + lc]);
    }
#pragma unroll
    for (int p = 0; p < 4; p++) {
        int r = lr + p * 32;
        convStoreH(av[p], &s[0].Ah[r][wc]);
        convStoreH(bv[p], &s[0].Bh[r][wc]);
    }
    __syncthreads();

    const int KT = K / MBK;
    for (int kt = 0; kt < KT; kt++) {
        const int cur = kt & 1;
        const uint32_t sb = sb0 + (uint32_t)cur * stageBytes;
        if (kt + 1 < KT) {
            int k0 = (kt + 1) * MBK;
#pragma unroll
            for (int p = 0; p < 4; p++) {
                int r = lr + p * 32;
                av[p] = *reinterpret_cast<const float4*>(&A[(size_t)(bm + r) * lda + k0 + lc]);
                bv[p] = *reinterpret_cast<const float4*>(&B[(size_t)(bn + r) * ldb + k0 + lc]);
            }
        }
#pragma unroll
        for (int kk = 0; kk < 2; kk++) {
            uint32_t ah[2][4], bh[4][4];
#pragma unroll
            for (int mf = 0; mf < 2; mf++) {
                uint32_t ao = (uint32_t)(((arow + mf * 16) * MLDW * 4) + (kk * 16 + acol) * 2);
                ldsm4(ah[mf], sb + ao);
            }
#pragma unroll
            for (int np = 0; np < 4; np++) {
                uint32_t bo = (uint32_t)(((brow + np * 16) * MLDW * 4) + (kk * 16 + bcol) * 2);
                ldsm4(bh[np], sb + offBh + bo);
            }
#pragma unroll
            for (int mf = 0; mf < 2; mf++) {
#pragma unroll
                for (int nf = 0; nf < 8; nf++) {
                    int np = nf >> 1;
                    int hf = (nf & 1) * 2;
                    mma_fp(acc[mf][nf], ah[mf], bh[np][hf], bh[np][hf + 1]);
                }
            }
        }
        if (kt + 1 < KT) {
            MSmem1& sn = s[cur ^ 1];
#pragma unroll
            for (int p = 0; p < 4; p++) {
                int r = lr + p * 32;
                convStoreH(av[p], &sn.Ah[r][wc]);
                convStoreH(bv[p], &sn.Bh[r][wc]);
            }
        }
        __syncthreads();
    }

#pragma unroll
    for (int mf = 0; mf < 2; mf++) {
        int row = bm + wm * 32 + mf * 16 + (lane >> 2);
#pragma unroll
        for (int nf = 0; nf < 8; nf++) {
            int col = bn + wn * 64 + nf * 8 + (lane & 3) * 2;
            *reinterpret_cast<float2*>(&C[(size_t)row * ldc + col]) =
                make_float2(acc[mf][nf][0], acc[mf][nf][1]);
            *reinterpret_cast<float2*>(&C[(size_t)(row + 8) * ldc + col]) =
                make_float2(acc[mf][nf][2], acc[mf][nf][3]);
        }
    }
}

// pipelined u16-A core; dual output (Cf fp32 | Ch fp16)
__device__ __forceinline__ void mma_core1h(
    const u16* __restrict__ A, const float* __restrict__ B,
    float* __restrict__ Cf, u16* __restrict__ Ch,
    int K, int lda, int ldb, int ldc, int bm, int bn, MSmem1 (&s)[2])
{
    const int tid = threadIdx.x;
    const int lane = tid & 31, wid = tid >> 5;
    const int wm = wid & 3, wn = wid >> 2;

    float acc[2][8][4];
#pragma unroll
    for (int i = 0; i < 2; i++)
#pragma unroll
        for (int j = 0; j < 8; j++)
#pragma unroll
            for (int e = 0; e < 4; e++) acc[i][j][e] = 0.f;

    const int lr = tid >> 3;
    const int lc = (tid & 7) * 4;
    const int wc = (tid & 7) * 2;

    const uint32_t sb0 = (uint32_t)__cvta_generic_to_shared(&s[0]);
    const uint32_t stageBytes = (uint32_t)sizeof(MSmem1);
    const uint32_t offBh = MBM * MLDW * 4;
    const int arow = wm * 32 + (lane & 15);
    const int acol = (lane >> 4) * 8;
    const int brow = wn * 64 + (lane & 7) + ((lane >> 4) << 3);
    const int bcol = ((lane >> 3) & 1) << 3;

    uint2 av[4];
    float4 bv[4];
#pragma unroll
    for (int p = 0; p < 4; p++) {
        int r = lr + p * 32;
        av[p] = *reinterpret_cast<const uint2*>(&A[(size_t)(bm + r) * lda + lc]);
        bv[p] = *reinterpret_cast<const float4*>(&B[(size_t)(bn + r) * ldb + lc]);
    }
#pragma unroll
    for (int p = 0; p < 4; p++) {
        int r = lr + p * 32;
        s[0].Ah[r][wc] = av[p].x;
        s[0].Ah[r][wc + 1] = av[p].y;
        convStoreH(bv[p], &s[0].Bh[r][wc]);
    }
    __syncthreads();

    const int KT = K / MBK;
    for (int kt = 0; kt < KT; kt++) {
        const int cur = kt & 1;
        const uint32_t sb = sb0 + (uint32_t)cur * stageBytes;
        if (kt + 1 < KT) {
            int k0 = (kt + 1) * MBK;
#pragma unroll
            for (int p = 0; p < 4; p++) {
                int r = lr + p * 32;
                av[p] = *reinterpret_cast<const uint2*>(&A[(size_t)(bm + r) * lda + k0 + lc]);
                bv[p] = *reinterpret_cast<const float4*>(&B[(size_t)(bn + r) * ldb + k0 + lc]);
            }
        }
#pragma unroll
        for (int kk = 0; kk < 2; kk++) {
            uint32_t ah[2][4], bh[4][4];
#pragma unroll
            for (int mf = 0; mf < 2; mf++) {
                uint32_t ao = (uint32_t)(((arow + mf * 16) * MLDW * 4) + (kk * 16 + acol) * 2);
                ldsm4(ah[mf], sb + ao);
            }
#pragma unroll
            for (int np = 0; np < 4; np++) {
                uint32_t bo = (uint32_t)(((brow + np * 16) * MLDW * 4) + (kk * 16 + bcol) * 2);
                ldsm4(bh[np], sb + offBh + bo);
            }
#pragma unroll
            for (int mf = 0; mf < 2; mf++) {
#pragma unroll
                for (int nf = 0; nf < 8; nf++) {
                    int np = nf >> 1;
                    int hf = (nf & 1) * 2;
                    mma_fp(acc[mf][nf], ah[mf], bh[np][hf], bh[np][hf + 1]);
                }
            }
        }
        if (kt + 1 < KT) {
            MSmem1& sn = s[cur ^ 1];
#pragma unroll
            for (int p = 0; p < 4; p++) {
                int r = lr + p * 32;
                sn.Ah[r][wc] = av[p].x;
                sn.Ah[r][wc + 1] = av[p].y;
                convStoreH(bv[p], &sn.Bh[r][wc]);
            }
        }
        __syncthreads();
    }

#pragma unroll
    for (int mf = 0; mf < 2; mf++) {
        int row = bm + wm * 32 + mf * 16 + (lane >> 2);
#pragma unroll
        for (int nf = 0; nf < 8; nf++) {
            int col = bn + wn * 64 + nf * 8 + (lane & 3) * 2;
            epi_store(Cf, Ch, (size_t)row * ldc + col, acc[mf][nf][0], acc[mf][nf][1]);
            epi_store(Cf, Ch, (size_t)(row + 8) * ldc + col, acc[mf][nf][2], acc[mf][nf][3]);
        }
    }
}

__global__ void __launch_bounds__(256, 2)
mma_nt1(const float* __restrict__ A, const float* __restrict__ B, float* __restrict__ C,
        int K, int lda, int ldb, int ldc) {
    __shared__ MSmem1 s[2];
    mma_core1(A, B, C, K, lda, ldb, ldc, blockIdx.x * MBM, blockIdx.y * MBN, s);
}

__global__ void __launch_bounds__(256, 2)
mma_nt1h(const u16* __restrict__ A, const float* __restrict__ B, float* __restrict__ C,
         int K, int lda, int ldb, int ldc) {
    __shared__ MSmem1 s[2];
    mma_core1h(A, B, C, (u16*)0, K, lda, ldb, ldc, blockIdx.x * MBM, blockIdx.y * MBN, s);
}

__global__ void __launch_bounds__(256, 2)
mma_gateup(const u16* __restrict__ A, const float* __restrict__ gw,
           const float* __restrict__ uw, u16* __restrict__ gateH, u16* __restrict__ upH) {
    __shared__ MSmem1 s[2];
    if (blockIdx.y < 64) {
        mma_core1h(A, gw, (float*)0, gateH, H_, H_, H_, FF_,
                   blockIdx.x * MBM, blockIdx.y * MBN, s);
    } else {
        mma_core1h(A, uw, (float*)0, upH, H_, H_, H_, FF_,
                   blockIdx.x * MBM, (blockIdx.y - 64) * MBN, s);
    }
}

// attnv: u16 probs A, fp16 output; z chunked via zoff
__global__ void __launch_bounds__(256, 2)
mma_attnv(const u16* __restrict__ p, const float* __restrict__ vT, u16* __restrict__ oH,
          int zoff) {
    int z = blockIdx.z + zoff;
    int b = z >> 3, h = z & 7;
    const u16* A = p + (size_t)z * T_ * T_;
    const float* B = vT + (size_t)(b * NKV_ + (h >> 2)) * HD_ * T_;
    u16* C = oH + (size_t)b * T_ * H_ + (size_t)h * HD_;
    int bm = blockIdx.x * MBM;
    __shared__ MSmem1 s[2];
    mma_core1h(A, B, (float*)0, C, bm + MBM, T_, T_, H_, bm, blockIdx.y * MBN, s);
}

// laurel1: split-K x8
__global__ void __launch_bounds__(256)
laurel1_kernel(const float* __restrict__ A, const float* __restrict__ B, float* __restrict__ P) {
    __shared__ float Bs[64][65];
    __shared__ float As[32][65];
    int tid = threadIdx.x;
    int bm = blockIdx.x * 32;
    int ks = blockIdx.y;
    int kbeg = ks * (H_ / 8), kend = kbeg + H_ / 8;
    float acc0[4] = {0.f, 0.f, 0.f, 0.f};
    float acc1[4] = {0.f, 0.f, 0.f, 0.f};
    int tn = tid & 15;
    int tr = tid >> 4;
    for (int k0 = kbeg; k0 < kend; k0 += 64) {
        for (int i = tid; i < 64 * 64; i += 256) {
            int n = i >> 6, kk = i & 63;
            Bs[n][kk] = B[(size_t)n * H_ + k0 + kk];
        }
        for (int i = tid; i < 32 * 64; i += 256) {
            int r = i >> 6, kk = i & 63;
            As[r][kk] = A[(size_t)(bm + r) * H_ + k0 + kk];
        }
        __syncthreads();
#pragma unroll 8
        for (int kk = 0; kk < 64; kk++) {
            float a0 = As[tr][kk], a1 = As[tr + 16][kk];
#pragma unroll
            for (int j = 0; j < 4; j++) {
                float bv = Bs[tn * 4 + j][kk];
                acc0[j] = fmaf(a0, bv, acc0[j]);
                acc1[j] = fmaf(a1, bv, acc1[j]);
            }
        }
        __syncthreads();
    }
#pragma unroll
    for (int j = 0; j < 4; j++) {
        P[((size_t)ks * BT_ + bm + tr) * LR_ + tn * 4 + j] = acc0[j];
        P[((size_t)ks * BT_ + bm + tr + 16) * LR_ + tn * 4 + j] = acc1[j];
    }
}

__global__ void laurel1_reduce(const float* __restrict__ P, float* __restrict__ out) {
    int i = blockIdx.x * blockDim.x + threadIdx.x;
    if (i >= BT_ * LR_) return;
    float s = 0.f;
#pragma unroll
    for (int k = 0; k < 8; k++) s += P[(size_t)k * BT_ * LR_ + i];
    out[i] = s;
}

// ---------- lazy side stream + events ----------
static cudaStream_t g_s1 = 0;
static cudaEvent_t g_ev0 = 0, g_evL = 0, g_evS0 = 0, g_evA0 = 0;

extern "C" void kernel_launch(void* const* d_in, const int* in_sizes, int n_in,
                              void* d_out, int out_size) {
    const float* hs    = (const float*)d_in[0];
    const float* cosb  = (const float*)d_in[1];
    const float* sinb  = (const float*)d_in[2];
    const float* wq    = (const float*)d_in[3];
    const float* wk    = (const float*)d_in[4];
    const float* wv    = (const float*)d_in[5];
    const float* wo    = (const float*)d_in[6];
    const float* qnw   = (const float*)d_in[7];
    const float* knw   = (const float*)d_in[8];
    const float* in_ln = (const float*)d_in[9];
    const float* pa_ln = (const float*)d_in[10];
    const float* pf_ln = (const float*)d_in[11];
    const float* pw_ln = (const float*)d_in[12];
    const float* gatew = (const float*)d_in[13];
    const float* upw   = (const float*)d_in[14];
    const float* downw = (const float*)d_in[15];
    const float* llw   = (const float*)d_in[16];
    const float* lrw   = (const float*)d_in[17];
    const float* lnw   = (const float*)d_in[18];
    const float* rnw   = (const float*)d_in[19];
    const float* rw    = (const float*)d_in[20];
    const float* pcw   = (const float*)d_in[21];
    const float* ccw   = (const float*)d_in[22];
    const float* cscal = (const float*)d_in[23];
    float* out = (float*)d_out;

    Scratch* S = 0;
    cudaGetSymbolAddress((void**)&S, g_scratch);

    if (!g_s1) {
        cudaStreamCreateWithFlags(&g_s1, cudaStreamNonBlocking);
        cudaEventCreateWithFlags(&g_ev0, cudaEventDisableTiming);
        cudaEventCreateWithFlags(&g_evL, cudaEventDisableTiming);
        cudaEventCreateWithFlags(&g_evS0, cudaEventDisableTiming);
        cudaEventCreateWithFlags(&g_evA0, cudaEventDisableTiming);
    }

    fused_pre<<<BT_, 256>>>(hs, rnw, rw, pcw, in_ln, S->pred0, S->cfg, S->xnorm);

    // fork: laurel chain + v chain on side stream
    cudaEventRecord(g_ev0, 0);
    cudaStreamWaitEvent(g_s1, g_ev0, 0);
    laurel1_kernel<<<dim3(BT_ / 32, 8), 256, 0, g_s1>>>(S->xnorm, llw, S->lrpart);
    laurel1_reduce<<<(BT_ * LR_ + 255) / 256, 256, 0, g_s1>>>(S->lrpart, S->lrbuf);
    mma_nt1<<<dim3(16, 16), 256, 0, g_s1>>>(S->lrbuf, lrw, S->laurel, LR_, LR_, LR_, H_);
    ln_kernel<<<BT_, 256, 0, g_s1>>>(S->laurel, lnw, S->xnorm, (const float*)0, 1.f, S->laurel);
    mma_nt1<<<dim3(16, 4), 256, 0, g_s1>>>(S->xnorm, wv, S->vraw, H_, H_, H_, NKV_ * HD_);
    qkvpost_kernel<<<BT_ * NKV_, 256, 0, g_s1>>>(S->vraw, (const float*)0, cosb, sinb,
                                                 S->vT, NKV_, 0, 1);
    cudaEventRecord(g_evL, g_s1);

    // main: q+k projections (combined), post
    mma_qk<<<dim3(16, 20), 256>>>(S->xnorm, wq, wk, S->qraw, S->kraw);
    qkvpost_qk<<<BT_ * (NH_ + NKV_), 256>>>(S->qraw, S->kraw, qnw, knw, cosb, sinb, S->q, S->k);

    // chunked attention: chunk0 (batch 0) softmax+attnv on side stream,
    // overlapped with chunk1 scores/softmax/attnv on main.
    const size_t chunkElems = (size_t)8 * T_ * T_;
    mma_scores<<<dim3(8, 8, 8), 256>>>(S->q, S->k, S->scores, 0);
    cudaEventRecord(g_evS0, 0);
    cudaStreamWaitEvent(g_s1, g_evS0, 0);
    softmax_kernel<<<(8 * T_) / 8, 256, 0, g_s1>>>(S->scores, S->probs);
    mma_attnv<<<dim3(8, 2, 8), 256, 0, g_s1>>>(S->probs, S->vT, S->aoH, 0);
    cudaEventRecord(g_evA0, g_s1);

    mma_scores<<<dim3(8, 8, 8), 256>>>(S->q, S->k, S->scores, 8);
    softmax_kernel<<<(8 * T_) / 8, 256>>>(S->scores + chunkElems, S->probs + chunkElems);
    cudaStreamWaitEvent(0, g_evL, 0);
    mma_attnv<<<dim3(8, 2, 8), 256>>>(S->probs, S->vT, S->aoH, 8);

    cudaStreamWaitEvent(0, g_evA0, 0);
    mma_nt1h<<<dim3(16, 16), 256>>>(S->aoH, wo, S->attnproj,
                                    NH_ * HD_, NH_ * HD_, NH_ * HD_, H_);

    fused_mid<<<BT_, 256>>>(S->attnproj, pa_ln, S->pred0, S->laurel, pf_ln,
                            S->attnlaurel, S->hnH);

    mma_gateup<<<dim3(16, 128), 256>>>(S->hnH, gatew, upw, S->gateH, S->upH);

    int n4 = (int)(FFSZ_ / 4);
    gelumul_kernel<<<(n4 + 255) / 256, 256>>>(S->gateH, S->upH, S->gp, n4);
    mma_nt1h<<<dim3(16, 16), 256>>>(S->gp, downw, S->ffw, FF_, FF_, FF_, H_);

    fused_post<<<BT_, 256>>>(S->ffw, pw_ln, S->attnlaurel, rnw, rw, ccw, cscal,
                             hs, S->cfg, out);

    (void)in_sizes; (void)n_in; (void)out_size;
}